// round 1
// baseline (speedup 1.0000x reference)
#include <cuda_runtime.h>
#include <math.h>

// Problem constants
#define BATCH   4
#define NSEQ    2048
#define DIM     1024
#define NH      8
#define DH      64
#define INNER   512          // NH*DH
#define ROWS    (BATCH*NSEQ) // 8192
#define QKV_LD  640          // 512 q cols + 64 k + 64 v

// ---------------- scratch (device globals; no allocations allowed) --------
__device__ float g_xn  [ROWS * DIM];     // layernorm(x)
__device__ float g_qkv [ROWS * QKV_LD];  // [q(512) | k(64) | v(64)] per row
__device__ float g_ao  [ROWS * INNER];   // attention output (b,n,h*dh)
__device__ float g_proj[ROWS * DIM];     // out @ Wout

// =============================== LayerNorm ================================
__device__ __forceinline__ void ln_body(const float* __restrict__ x,
                                        const float* __restrict__ g,
                                        float* __restrict__ y) {
    int row = blockIdx.x;
    int t = threadIdx.x;                       // 256 threads, float4 each
    const float4* xr = reinterpret_cast<const float4*>(x + (size_t)row * DIM);
    float4 v = xr[t];
    float s  = v.x + v.y + v.z + v.w;
    float ss = v.x * v.x + v.y * v.y + v.z * v.z + v.w * v.w;
    #pragma unroll
    for (int o = 16; o > 0; o >>= 1) {
        s  += __shfl_xor_sync(0xffffffffu, s,  o);
        ss += __shfl_xor_sync(0xffffffffu, ss, o);
    }
    __shared__ float sh_s[8], sh_ss[8];
    int w = t >> 5, lane = t & 31;
    if (lane == 0) { sh_s[w] = s; sh_ss[w] = ss; }
    __syncthreads();
    if (w == 0) {
        s  = (lane < 8) ? sh_s[lane]  : 0.f;
        ss = (lane < 8) ? sh_ss[lane] : 0.f;
        #pragma unroll
        for (int o = 4; o > 0; o >>= 1) {
            s  += __shfl_xor_sync(0xffffffffu, s,  o);
            ss += __shfl_xor_sync(0xffffffffu, ss, o);
        }
        if (lane == 0) { sh_s[0] = s; sh_ss[0] = ss; }
    }
    __syncthreads();
    float mean = sh_s[0] * (1.0f / DIM);
    float var  = sh_ss[0] * (1.0f / DIM) - mean * mean;
    float inv  = rsqrtf(var + 1e-5f);
    float4 gv = reinterpret_cast<const float4*>(g)[t];
    float4 o4;
    o4.x = (v.x - mean) * inv * gv.x;
    o4.y = (v.y - mean) * inv * gv.y;
    o4.z = (v.z - mean) * inv * gv.z;
    o4.w = (v.w - mean) * inv * gv.w;
    reinterpret_cast<float4*>(y + (size_t)row * DIM)[t] = o4;
}

__global__ void ln1_kernel(const float* __restrict__ x, const float* __restrict__ g) {
    ln_body(x, g, g_xn);
}
__global__ void ln2_kernel(const float* __restrict__ g, float* __restrict__ out) {
    ln_body(g_proj, g, out);
}

// ========================= fp32 tiled GEMM 128x128x16 =====================
// C[m, coff+n] = sum_k A[m,k] * B[k,n],  A: (M,K) ld=K, B: (K,N) ld=N,
// C ld=ldc. 256 threads, 8x8 microtile per thread.
__device__ __forceinline__ void gemm_body(const float* __restrict__ A,
                                          const float* __restrict__ Bm,
                                          float* __restrict__ C,
                                          int Mdim, int Ncols, int Kdim,
                                          int ldc, int coff) {
    __shared__ float As[16][128];   // transposed: As[kk][m]
    __shared__ float Bs[16][128];   // natural:    Bs[kk][n]
    int tid = threadIdx.x;
    int tx = tid & 15, ty = tid >> 4;
    int m0 = blockIdx.x * 128;
    int n0 = blockIdx.y * 128;

    float acc[8][8];
    #pragma unroll
    for (int i = 0; i < 8; i++)
        #pragma unroll
        for (int j = 0; j < 8; j++) acc[i][j] = 0.f;

    int am = tid >> 1;            // 0..127
    int ak = (tid & 1) * 8;       // 0 or 8
    int bn = (tid & 31) * 4;      // 0..124
    int bk = tid >> 5;            // 0..7

    for (int k0 = 0; k0 < Kdim; k0 += 16) {
        const float* ap = A + (size_t)(m0 + am) * Kdim + k0 + ak;
        float4 a0 = *reinterpret_cast<const float4*>(ap);
        float4 a1 = *reinterpret_cast<const float4*>(ap + 4);
        As[ak + 0][am] = a0.x; As[ak + 1][am] = a0.y;
        As[ak + 2][am] = a0.z; As[ak + 3][am] = a0.w;
        As[ak + 4][am] = a1.x; As[ak + 5][am] = a1.y;
        As[ak + 6][am] = a1.z; As[ak + 7][am] = a1.w;

        const float* bp = Bm + (size_t)(k0 + bk) * Ncols + n0 + bn;
        float4 b0 = *reinterpret_cast<const float4*>(bp);
        float4 b1 = *reinterpret_cast<const float4*>(bp + (size_t)8 * Ncols);
        *reinterpret_cast<float4*>(&Bs[bk][bn])     = b0;
        *reinterpret_cast<float4*>(&Bs[bk + 8][bn]) = b1;
        __syncthreads();

        #pragma unroll
        for (int kk = 0; kk < 16; kk++) {
            float4 A0 = *reinterpret_cast<float4*>(&As[kk][ty * 8]);
            float4 A1 = *reinterpret_cast<float4*>(&As[kk][ty * 8 + 4]);
            float4 B0 = *reinterpret_cast<float4*>(&Bs[kk][tx * 8]);
            float4 B1 = *reinterpret_cast<float4*>(&Bs[kk][tx * 8 + 4]);
            float av[8] = {A0.x, A0.y, A0.z, A0.w, A1.x, A1.y, A1.z, A1.w};
            float bv[8] = {B0.x, B0.y, B0.z, B0.w, B1.x, B1.y, B1.z, B1.w};
            #pragma unroll
            for (int i = 0; i < 8; i++)
                #pragma unroll
                for (int j = 0; j < 8; j++)
                    acc[i][j] = fmaf(av[i], bv[j], acc[i][j]);
        }
        __syncthreads();
    }

    #pragma unroll
    for (int i = 0; i < 8; i++) {
        float* cp = C + (size_t)(m0 + ty * 8 + i) * ldc + coff + n0 + tx * 8;
        float4 c0 = make_float4(acc[i][0], acc[i][1], acc[i][2], acc[i][3]);
        float4 c1 = make_float4(acc[i][4], acc[i][5], acc[i][6], acc[i][7]);
        *reinterpret_cast<float4*>(cp)     = c0;
        *reinterpret_cast<float4*>(cp + 4) = c1;
    }
}

__global__ void __launch_bounds__(256) gemm_q_kernel(const float* __restrict__ Wq) {
    gemm_body(g_xn, Wq, g_qkv, ROWS, INNER, DIM, QKV_LD, 0);
}
__global__ void __launch_bounds__(256) gemm_kv_kernel(const float* __restrict__ Wkv) {
    gemm_body(g_xn, Wkv, g_qkv, ROWS, 2 * DH, DIM, QKV_LD, INNER);
}
__global__ void __launch_bounds__(256) gemm_out_kernel(const float* __restrict__ Wout) {
    gemm_body(g_ao, Wout, g_proj, ROWS, DIM, INNER, DIM, 0);
}

// ===================== q/k l2norm * sqrt(SCALE) in place ===================
// One warp per 64-float vector. q vectors: ROWS*NH; k vectors: ROWS.
__global__ void qknorm_kernel() {
    int w = (blockIdx.x * blockDim.x + threadIdx.x) >> 5;
    int lane = threadIdx.x & 31;
    float* vec;
    if (w < ROWS * NH) {
        int row = w >> 3, hh = w & 7;
        vec = g_qkv + (size_t)row * QKV_LD + hh * DH;
    } else {
        int row = w - ROWS * NH;
        if (row >= ROWS) return;
        vec = g_qkv + (size_t)row * QKV_LD + INNER;   // k slot
    }
    float2 v = reinterpret_cast<float2*>(vec)[lane];
    float ss = v.x * v.x + v.y * v.y;
    #pragma unroll
    for (int o = 16; o > 0; o >>= 1) ss += __shfl_xor_sync(0xffffffffu, ss, o);
    float inv = 4.0f / fmaxf(sqrtf(ss), 1e-12f);   // * sqrt(SCALE)=4
    reinterpret_cast<float2*>(vec)[lane] = make_float2(v.x * inv, v.y * inv);
}

// ============================== attention ==================================
// grid: (qtiles=32, bh=32). block 256 threads (16x16), 64q x 64k tiles.
// scores s in [-16,16] -> fixed-shift softmax exp(s-16), no running max.
__global__ void __launch_bounds__(256) attn_kernel() {
    __shared__ float Qt[64][64];   // [d][q]
    __shared__ float KV[64][64];   // K: [d][k]  then V: [k][d]
    __shared__ float Ps[64][64];   // [k][q]

    int bh = blockIdx.y;
    int b = bh >> 3, hd = bh & 7;
    int q0 = blockIdx.x * 64;
    int tid = threadIdx.x;
    int tx = tid & 15, ty = tid >> 4;

    const float* qbase = g_qkv + (size_t)(b * NSEQ + q0) * QKV_LD + hd * DH;
    const float* kbase = g_qkv + (size_t)(b * NSEQ) * QKV_LD + INNER;
    const float* vbase = kbase + DH;

    // load Q tile transposed
    {
        int qr = tid >> 2;
        int d4 = (tid & 3) * 4;
        #pragma unroll
        for (int r = 0; r < 4; r++) {
            float4 v = *reinterpret_cast<const float4*>(qbase + (size_t)qr * QKV_LD + d4 + r * 16);
            int d = d4 + r * 16;
            Qt[d + 0][qr] = v.x; Qt[d + 1][qr] = v.y;
            Qt[d + 2][qr] = v.z; Qt[d + 3][qr] = v.w;
        }
    }

    float o[4][4];
    float rs[4];
    #pragma unroll
    for (int i = 0; i < 4; i++) {
        rs[i] = 0.f;
        #pragma unroll
        for (int j = 0; j < 4; j++) o[i][j] = 0.f;
    }

    for (int kt = 0; kt < NSEQ; kt += 64) {
        __syncthreads();   // Q stored / previous PV done reading KV
        // load K tile transposed: KV[d][k]
        {
            int kr = tid >> 2;
            int d4 = (tid & 3) * 4;
            #pragma unroll
            for (int r = 0; r < 4; r++) {
                float4 v = *reinterpret_cast<const float4*>(kbase + (size_t)(kt + kr) * QKV_LD + d4 + r * 16);
                int d = d4 + r * 16;
                KV[d + 0][kr] = v.x; KV[d + 1][kr] = v.y;
                KV[d + 2][kr] = v.z; KV[d + 3][kr] = v.w;
            }
        }
        __syncthreads();

        float s[4][4];
        #pragma unroll
        for (int i = 0; i < 4; i++)
            #pragma unroll
            for (int j = 0; j < 4; j++) s[i][j] = 0.f;

        #pragma unroll 16
        for (int d = 0; d < 64; d++) {
            float4 a  = *reinterpret_cast<float4*>(&Qt[d][ty * 4]);
            float4 bb = *reinterpret_cast<float4*>(&KV[d][tx * 4]);
            float av[4] = {a.x, a.y, a.z, a.w};
            float bv[4] = {bb.x, bb.y, bb.z, bb.w};
            #pragma unroll
            for (int i = 0; i < 4; i++)
                #pragma unroll
                for (int j = 0; j < 4; j++)
                    s[i][j] = fmaf(av[i], bv[j], s[i][j]);
        }

        float p[4][4];
        #pragma unroll
        for (int i = 0; i < 4; i++)
            #pragma unroll
            for (int j = 0; j < 4; j++) {
                p[i][j] = __expf(s[i][j] - 16.0f);
                rs[i] += p[i][j];
            }

        __syncthreads();   // everyone done reading KV (K)
        // stage P transposed; load V tile natural layout KV[k][d]
        #pragma unroll
        for (int j = 0; j < 4; j++) {
            float4 pv = make_float4(p[0][j], p[1][j], p[2][j], p[3][j]);
            *reinterpret_cast<float4*>(&Ps[tx * 4 + j][ty * 4]) = pv;
        }
        {
            int kr = tid >> 2;
            int d4 = (tid & 3) * 4;
            #pragma unroll
            for (int r = 0; r < 4; r++) {
                float4 v = *reinterpret_cast<const float4*>(vbase + (size_t)(kt + kr) * QKV_LD + d4 + r * 16);
                *reinterpret_cast<float4*>(&KV[kr][d4 + r * 16]) = v;
            }
        }
        __syncthreads();

        #pragma unroll 16
        for (int k = 0; k < 64; k++) {
            float4 a  = *reinterpret_cast<float4*>(&Ps[k][ty * 4]);
            float4 vv = *reinterpret_cast<float4*>(&KV[k][tx * 4]);
            float av[4] = {a.x, a.y, a.z, a.w};
            float bv[4] = {vv.x, vv.y, vv.z, vv.w};
            #pragma unroll
            for (int i = 0; i < 4; i++)
                #pragma unroll
                for (int j = 0; j < 4; j++)
                    o[i][j] = fmaf(av[i], bv[j], o[i][j]);
        }
    }

    // reduce row sums over the 16 tx lanes (width-16 xor shuffles)
    #pragma unroll
    for (int i = 0; i < 4; i++) {
        #pragma unroll
        for (int off = 1; off < 16; off <<= 1)
            rs[i] += __shfl_xor_sync(0xffffffffu, rs[i], off);
    }

    float* obase = g_ao + (size_t)(b * NSEQ + q0) * INNER + hd * DH;
    #pragma unroll
    for (int i = 0; i < 4; i++) {
        float inv = 1.0f / rs[i];
        float4 w = make_float4(o[i][0] * inv, o[i][1] * inv, o[i][2] * inv, o[i][3] * inv);
        *reinterpret_cast<float4*>(obase + (size_t)(ty * 4 + i) * INNER + tx * 4) = w;
    }
}

// ================================ launch ===================================
extern "C" void kernel_launch(void* const* d_in, const int* in_sizes, int n_in,
                              void* d_out, int out_size) {
    const float* x          = (const float*)d_in[0];
    const float* norm_g     = (const float*)d_in[1];
    const float* Wq         = (const float*)d_in[2];
    const float* Wkv        = (const float*)d_in[3];
    const float* Wout       = (const float*)d_in[4];
    const float* out_norm_g = (const float*)d_in[5];
    float* out = (float*)d_out;

    ln1_kernel<<<ROWS, 256>>>(x, norm_g);
    gemm_q_kernel<<<dim3(ROWS / 128, INNER / 128), 256>>>(Wq);
    gemm_kv_kernel<<<dim3(ROWS / 128, 1), 256>>>(Wkv);
    // (ROWS*NH + ROWS) warps, 8 warps per block
    qknorm_kernel<<<(ROWS * NH + ROWS) / 8, 256>>>();
    attn_kernel<<<dim3(NSEQ / 64, BATCH * NH), 256>>>();
    gemm_out_kernel<<<dim3(ROWS / 128, DIM / 128), 256>>>(Wout);
    ln2_kernel<<<ROWS, 256>>>(out_norm_g, out);
}

// round 2
// speedup vs baseline: 1.0010x; 1.0010x over previous
#include <cuda_runtime.h>
#include <math.h>

// Problem constants
#define BATCH   4
#define NSEQ    2048
#define DIM     1024
#define NH      8
#define DH      64
#define INNER   512          // NH*DH
#define ROWS    (BATCH*NSEQ) // 8192
#define QKV_LD  640          // 512 q cols + 64 k + 64 v

// ---------------- scratch (device globals; no allocations allowed) --------
__device__ float g_xn  [ROWS * DIM];     // layernorm(x)
__device__ float g_qkv [ROWS * QKV_LD];  // [q(512) | k(64) | v(64)] per row
__device__ float g_ao  [ROWS * INNER];   // attention output (b,n,h*dh)
__device__ float g_proj[ROWS * DIM];     // out @ Wout

// =============================== LayerNorm ================================
__device__ __forceinline__ void ln_body(const float* __restrict__ x,
                                        const float* __restrict__ g,
                                        float* __restrict__ y) {
    int row = blockIdx.x;
    int t = threadIdx.x;                       // 256 threads, float4 each
    const float4* xr = reinterpret_cast<const float4*>(x + (size_t)row * DIM);
    float4 v = xr[t];
    float s  = v.x + v.y + v.z + v.w;
    float ss = v.x * v.x + v.y * v.y + v.z * v.z + v.w * v.w;
    #pragma unroll
    for (int o = 16; o > 0; o >>= 1) {
        s  += __shfl_xor_sync(0xffffffffu, s,  o);
        ss += __shfl_xor_sync(0xffffffffu, ss, o);
    }
    __shared__ float sh_s[8], sh_ss[8];
    int w = t >> 5, lane = t & 31;
    if (lane == 0) { sh_s[w] = s; sh_ss[w] = ss; }
    __syncthreads();
    if (w == 0) {
        s  = (lane < 8) ? sh_s[lane]  : 0.f;
        ss = (lane < 8) ? sh_ss[lane] : 0.f;
        #pragma unroll
        for (int o = 4; o > 0; o >>= 1) {
            s  += __shfl_xor_sync(0xffffffffu, s,  o);
            ss += __shfl_xor_sync(0xffffffffu, ss, o);
        }
        if (lane == 0) { sh_s[0] = s; sh_ss[0] = ss; }
    }
    __syncthreads();
    float mean = sh_s[0] * (1.0f / DIM);
    float var  = sh_ss[0] * (1.0f / DIM) - mean * mean;
    float inv  = rsqrtf(var + 1e-5f);
    float4 gv = reinterpret_cast<const float4*>(g)[t];
    float4 o4;
    o4.x = (v.x - mean) * inv * gv.x;
    o4.y = (v.y - mean) * inv * gv.y;
    o4.z = (v.z - mean) * inv * gv.z;
    o4.w = (v.w - mean) * inv * gv.w;
    reinterpret_cast<float4*>(y + (size_t)row * DIM)[t] = o4;
}

__global__ void ln1_kernel(const float* __restrict__ x, const float* __restrict__ g) {
    ln_body(x, g, g_xn);
}
__global__ void ln2_kernel(const float* __restrict__ g, float* __restrict__ out) {
    ln_body(g_proj, g, out);
}

// ========================= fp32 tiled GEMM 128x128x16 =====================
// C[m, coff+n] = sum_k A[m,k] * B[k,n],  A: (M,K) ld=K, B: (K,N) ld=N,
// C ld=ldc. 256 threads, 8x8 microtile per thread.
__device__ __forceinline__ void gemm_body(const float* __restrict__ A,
                                          const float* __restrict__ Bm,
                                          float* __restrict__ C,
                                          int Mdim, int Ncols, int Kdim,
                                          int ldc, int coff) {
    __shared__ float As[16][128];   // transposed: As[kk][m]
    __shared__ float Bs[16][128];   // natural:    Bs[kk][n]
    int tid = threadIdx.x;
    int tx = tid & 15, ty = tid >> 4;
    int m0 = blockIdx.x * 128;
    int n0 = blockIdx.y * 128;

    float acc[8][8];
    #pragma unroll
    for (int i = 0; i < 8; i++)
        #pragma unroll
        for (int j = 0; j < 8; j++) acc[i][j] = 0.f;

    int am = tid >> 1;            // 0..127
    int ak = (tid & 1) * 8;       // 0 or 8
    int bn = (tid & 31) * 4;      // 0..124
    int bk = tid >> 5;            // 0..7

    for (int k0 = 0; k0 < Kdim; k0 += 16) {
        const float* ap = A + (size_t)(m0 + am) * Kdim + k0 + ak;
        float4 a0 = *reinterpret_cast<const float4*>(ap);
        float4 a1 = *reinterpret_cast<const float4*>(ap + 4);
        As[ak + 0][am] = a0.x; As[ak + 1][am] = a0.y;
        As[ak + 2][am] = a0.z; As[ak + 3][am] = a0.w;
        As[ak + 4][am] = a1.x; As[ak + 5][am] = a1.y;
        As[ak + 6][am] = a1.z; As[ak + 7][am] = a1.w;

        const float* bp = Bm + (size_t)(k0 + bk) * Ncols + n0 + bn;
        float4 b0 = *reinterpret_cast<const float4*>(bp);
        float4 b1 = *reinterpret_cast<const float4*>(bp + (size_t)8 * Ncols);
        *reinterpret_cast<float4*>(&Bs[bk][bn])     = b0;
        *reinterpret_cast<float4*>(&Bs[bk + 8][bn]) = b1;
        __syncthreads();

        #pragma unroll
        for (int kk = 0; kk < 16; kk++) {
            float4 A0 = *reinterpret_cast<float4*>(&As[kk][ty * 8]);
            float4 A1 = *reinterpret_cast<float4*>(&As[kk][ty * 8 + 4]);
            float4 B0 = *reinterpret_cast<float4*>(&Bs[kk][tx * 8]);
            float4 B1 = *reinterpret_cast<float4*>(&Bs[kk][tx * 8 + 4]);
            float av[8] = {A0.x, A0.y, A0.z, A0.w, A1.x, A1.y, A1.z, A1.w};
            float bv[8] = {B0.x, B0.y, B0.z, B0.w, B1.x, B1.y, B1.z, B1.w};
            #pragma unroll
            for (int i = 0; i < 8; i++)
                #pragma unroll
                for (int j = 0; j < 8; j++)
                    acc[i][j] = fmaf(av[i], bv[j], acc[i][j]);
        }
        __syncthreads();
    }

    #pragma unroll
    for (int i = 0; i < 8; i++) {
        float* cp = C + (size_t)(m0 + ty * 8 + i) * ldc + coff + n0 + tx * 8;
        float4 c0 = make_float4(acc[i][0], acc[i][1], acc[i][2], acc[i][3]);
        float4 c1 = make_float4(acc[i][4], acc[i][5], acc[i][6], acc[i][7]);
        *reinterpret_cast<float4*>(cp)     = c0;
        *reinterpret_cast<float4*>(cp + 4) = c1;
    }
}

__global__ void __launch_bounds__(256) gemm_q_kernel(const float* __restrict__ Wq) {
    gemm_body(g_xn, Wq, g_qkv, ROWS, INNER, DIM, QKV_LD, 0);
}
__global__ void __launch_bounds__(256) gemm_kv_kernel(const float* __restrict__ Wkv) {
    gemm_body(g_xn, Wkv, g_qkv, ROWS, 2 * DH, DIM, QKV_LD, INNER);
}
__global__ void __launch_bounds__(256) gemm_out_kernel(const float* __restrict__ Wout) {
    gemm_body(g_ao, Wout, g_proj, ROWS, DIM, INNER, DIM, 0);
}

// ===================== q/k l2norm * sqrt(SCALE) in place ===================
// One warp per 64-float vector. q vectors: ROWS*NH; k vectors: ROWS.
__global__ void qknorm_kernel() {
    int w = (blockIdx.x * blockDim.x + threadIdx.x) >> 5;
    int lane = threadIdx.x & 31;
    float* vec;
    if (w < ROWS * NH) {
        int row = w >> 3, hh = w & 7;
        vec = g_qkv + (size_t)row * QKV_LD + hh * DH;
    } else {
        int row = w - ROWS * NH;
        if (row >= ROWS) return;
        vec = g_qkv + (size_t)row * QKV_LD + INNER;   // k slot
    }
    float2 v = reinterpret_cast<float2*>(vec)[lane];
    float ss = v.x * v.x + v.y * v.y;
    #pragma unroll
    for (int o = 16; o > 0; o >>= 1) ss += __shfl_xor_sync(0xffffffffu, ss, o);
    float inv = 4.0f / fmaxf(sqrtf(ss), 1e-12f);   // * sqrt(SCALE)=4
    reinterpret_cast<float2*>(vec)[lane] = make_float2(v.x * inv, v.y * inv);
}

// ============================== attention ==================================
// grid: (qtiles=32, bh=32). block 256 threads (16x16), 64q x 64k tiles.
// scores s in [-16,16] -> fixed-shift softmax exp(s-16), no running max.
__global__ void __launch_bounds__(256) attn_kernel() {
    __shared__ float Qt[64][64];   // [d][q]
    __shared__ float KV[64][64];   // K: [d][k]  then V: [k][d]
    __shared__ float Ps[64][64];   // [k][q]

    int bh = blockIdx.y;
    int b = bh >> 3, hd = bh & 7;
    int q0 = blockIdx.x * 64;
    int tid = threadIdx.x;
    int tx = tid & 15, ty = tid >> 4;

    const float* qbase = g_qkv + (size_t)(b * NSEQ + q0) * QKV_LD + hd * DH;
    const float* kbase = g_qkv + (size_t)(b * NSEQ) * QKV_LD + INNER;
    const float* vbase = kbase + DH;

    // load Q tile transposed
    {
        int qr = tid >> 2;
        int d4 = (tid & 3) * 4;
        #pragma unroll
        for (int r = 0; r < 4; r++) {
            float4 v = *reinterpret_cast<const float4*>(qbase + (size_t)qr * QKV_LD + d4 + r * 16);
            int d = d4 + r * 16;
            Qt[d + 0][qr] = v.x; Qt[d + 1][qr] = v.y;
            Qt[d + 2][qr] = v.z; Qt[d + 3][qr] = v.w;
        }
    }

    float o[4][4];
    float rs[4];
    #pragma unroll
    for (int i = 0; i < 4; i++) {
        rs[i] = 0.f;
        #pragma unroll
        for (int j = 0; j < 4; j++) o[i][j] = 0.f;
    }

    for (int kt = 0; kt < NSEQ; kt += 64) {
        __syncthreads();   // Q stored / previous PV done reading KV
        // load K tile transposed: KV[d][k]
        {
            int kr = tid >> 2;
            int d4 = (tid & 3) * 4;
            #pragma unroll
            for (int r = 0; r < 4; r++) {
                float4 v = *reinterpret_cast<const float4*>(kbase + (size_t)(kt + kr) * QKV_LD + d4 + r * 16);
                int d = d4 + r * 16;
                KV[d + 0][kr] = v.x; KV[d + 1][kr] = v.y;
                KV[d + 2][kr] = v.z; KV[d + 3][kr] = v.w;
            }
        }
        __syncthreads();

        float s[4][4];
        #pragma unroll
        for (int i = 0; i < 4; i++)
            #pragma unroll
            for (int j = 0; j < 4; j++) s[i][j] = 0.f;

        #pragma unroll 16
        for (int d = 0; d < 64; d++) {
            float4 a  = *reinterpret_cast<float4*>(&Qt[d][ty * 4]);
            float4 bb = *reinterpret_cast<float4*>(&KV[d][tx * 4]);
            float av[4] = {a.x, a.y, a.z, a.w};
            float bv[4] = {bb.x, bb.y, bb.z, bb.w};
            #pragma unroll
            for (int i = 0; i < 4; i++)
                #pragma unroll
                for (int j = 0; j < 4; j++)
                    s[i][j] = fmaf(av[i], bv[j], s[i][j]);
        }

        float p[4][4];
        #pragma unroll
        for (int i = 0; i < 4; i++)
            #pragma unroll
            for (int j = 0; j < 4; j++) {
                p[i][j] = __expf(s[i][j] - 16.0f);
                rs[i] += p[i][j];
            }

        __syncthreads();   // everyone done reading KV (K)
        // stage P transposed; load V tile natural layout KV[k][d]
        #pragma unroll
        for (int j = 0; j < 4; j++) {
            float4 pv = make_float4(p[0][j], p[1][j], p[2][j], p[3][j]);
            *reinterpret_cast<float4*>(&Ps[tx * 4 + j][ty * 4]) = pv;
        }
        {
            int kr = tid >> 2;
            int d4 = (tid & 3) * 4;
            #pragma unroll
            for (int r = 0; r < 4; r++) {
                float4 v = *reinterpret_cast<const float4*>(vbase + (size_t)(kt + kr) * QKV_LD + d4 + r * 16);
                *reinterpret_cast<float4*>(&KV[kr][d4 + r * 16]) = v;
            }
        }
        __syncthreads();

        #pragma unroll 16
        for (int k = 0; k < 64; k++) {
            float4 a  = *reinterpret_cast<float4*>(&Ps[k][ty * 4]);
            float4 vv = *reinterpret_cast<float4*>(&KV[k][tx * 4]);
            float av[4] = {a.x, a.y, a.z, a.w};
            float bv[4] = {vv.x, vv.y, vv.z, vv.w};
            #pragma unroll
            for (int i = 0; i < 4; i++)
                #pragma unroll
                for (int j = 0; j < 4; j++)
                    o[i][j] = fmaf(av[i], bv[j], o[i][j]);
        }
    }

    // reduce row sums over the 16 tx lanes (width-16 xor shuffles)
    #pragma unroll
    for (int i = 0; i < 4; i++) {
        #pragma unroll
        for (int off = 1; off < 16; off <<= 1)
            rs[i] += __shfl_xor_sync(0xffffffffu, rs[i], off);
    }

    float* obase = g_ao + (size_t)(b * NSEQ + q0) * INNER + hd * DH;
    #pragma unroll
    for (int i = 0; i < 4; i++) {
        float inv = 1.0f / rs[i];
        float4 w = make_float4(o[i][0] * inv, o[i][1] * inv, o[i][2] * inv, o[i][3] * inv);
        *reinterpret_cast<float4*>(obase + (size_t)(ty * 4 + i) * INNER + tx * 4) = w;
    }
}

// ================================ launch ===================================
extern "C" void kernel_launch(void* const* d_in, const int* in_sizes, int n_in,
                              void* d_out, int out_size) {
    const float* x          = (const float*)d_in[0];
    const float* norm_g     = (const float*)d_in[1];
    const float* Wq         = (const float*)d_in[2];
    const float* Wkv        = (const float*)d_in[3];
    const float* Wout       = (const float*)d_in[4];
    const float* out_norm_g = (const float*)d_in[5];
    float* out = (float*)d_out;

    ln1_kernel<<<ROWS, 256>>>(x, norm_g);
    gemm_q_kernel<<<dim3(ROWS / 128, INNER / 128), 256>>>(Wq);
    gemm_kv_kernel<<<dim3(ROWS / 128, 1), 256>>>(Wkv);
    // (ROWS*NH + ROWS) warps, 8 warps per block
    qknorm_kernel<<<(ROWS * NH + ROWS) / 8, 256>>>();
    attn_kernel<<<dim3(NSEQ / 64, BATCH * NH), 256>>>();
    gemm_out_kernel<<<dim3(ROWS / 128, DIM / 128), 256>>>(Wout);
    ln2_kernel<<<ROWS, 256>>>(out_norm_g, out);
}

// round 4
// speedup vs baseline: 2.5085x; 2.5061x over previous
#include <cuda_runtime.h>
#include <cuda_bf16.h>
#include <cstdint>
#include <math.h>

#define BATCH 4
#define NSEQ  2048
#define DIM   1024
#define NH    8
#define DH    64
#define INNER 512
#define ROWS  (BATCH*NSEQ)

// ----------------------------- scratch ------------------------------------
__device__ __nv_bfloat16 g_xn_h[ROWS*DIM], g_xn_l[ROWS*DIM];
__device__ __nv_bfloat16 g_wq_h[INNER*DIM],  g_wq_l[INNER*DIM];   // Wq^T  [512][1024]
__device__ __nv_bfloat16 g_wkv_h[2*DH*DIM],  g_wkv_l[2*DH*DIM];   // Wkv^T [128][1024]
__device__ __nv_bfloat16 g_wo_h[DIM*INNER],  g_wo_l[DIM*INNER];   // Wout^T[1024][512]
__device__ float g_qf[ROWS*INNER];                 // q fp32 head-major [b][h][n][dh]
__device__ float g_kf[ROWS*DH], g_vf[ROWS*DH];
__device__ __nv_bfloat16 g_qh[ROWS*INNER], g_ql[ROWS*INNER];      // head-major
__device__ __nv_bfloat16 g_kh[ROWS*DH],    g_kl[ROWS*DH];
__device__ __nv_bfloat16 g_vth[BATCH*DH*NSEQ], g_vtl[BATCH*DH*NSEQ]; // V^T [b][dh][n]
__device__ __nv_bfloat16 g_aoh[ROWS*INNER], g_aol[ROWS*INNER];
__device__ float g_proj[ROWS*DIM];

// --------------------------- helpers --------------------------------------
__device__ __forceinline__ uint32_t smem_u32(const void* p) {
    uint32_t a;
    asm("{ .reg .u64 t; cvta.to.shared.u64 t, %1; cvt.u32.u64 %0, t; }" : "=r"(a) : "l"(p));
    return a;
}
__device__ __forceinline__ void ldm_x4(uint32_t* r, uint32_t addr) {
    asm volatile("ldmatrix.sync.aligned.m8n8.x4.shared.b16 {%0,%1,%2,%3}, [%4];"
                 : "=r"(r[0]), "=r"(r[1]), "=r"(r[2]), "=r"(r[3]) : "r"(addr));
}
__device__ __forceinline__ void mma16816(float* c, const uint32_t* a, const uint32_t* b) {
    asm volatile("mma.sync.aligned.m16n8k16.row.col.f32.bf16.bf16.f32 "
                 "{%0,%1,%2,%3}, {%4,%5,%6,%7}, {%8,%9}, {%0,%1,%2,%3};"
                 : "+f"(c[0]), "+f"(c[1]), "+f"(c[2]), "+f"(c[3])
                 : "r"(a[0]), "r"(a[1]), "r"(a[2]), "r"(a[3]), "r"(b[0]), "r"(b[1]));
}
__device__ __forceinline__ uint32_t pack_split_hi(float a, float b, uint32_t& lo) {
    __nv_bfloat16 ah = __float2bfloat16_rn(a), bh = __float2bfloat16_rn(b);
    __nv_bfloat16 al = __float2bfloat16_rn(a - __bfloat162float(ah));
    __nv_bfloat16 bl = __float2bfloat16_rn(b - __bfloat162float(bh));
    lo = (uint32_t)__bfloat16_as_ushort(al) | ((uint32_t)__bfloat16_as_ushort(bl) << 16);
    return (uint32_t)__bfloat16_as_ushort(ah) | ((uint32_t)__bfloat16_as_ushort(bh) << 16);
}

// ------------------------------ LayerNorm ---------------------------------
__device__ __forceinline__ float2 ln_block(float4 v, float* shs, float* shss) {
    int t = threadIdx.x, w = t >> 5, lane = t & 31;
    float s = v.x + v.y + v.z + v.w;
    float ss = v.x*v.x + v.y*v.y + v.z*v.z + v.w*v.w;
    #pragma unroll
    for (int o = 16; o > 0; o >>= 1) { s += __shfl_xor_sync(~0u, s, o); ss += __shfl_xor_sync(~0u, ss, o); }
    if (lane == 0) { shs[w] = s; shss[w] = ss; }
    __syncthreads();
    if (w == 0) {
        s = (lane < 8) ? shs[lane] : 0.f; ss = (lane < 8) ? shss[lane] : 0.f;
        #pragma unroll
        for (int o = 4; o > 0; o >>= 1) { s += __shfl_xor_sync(~0u, s, o); ss += __shfl_xor_sync(~0u, ss, o); }
        if (lane == 0) { shs[0] = s; shss[0] = ss; }
    }
    __syncthreads();
    float mean = shs[0] * (1.f / DIM);
    float inv = rsqrtf(shss[0] * (1.f / DIM) - mean * mean + 1e-5f);
    return make_float2(mean, inv);
}
__global__ void ln1_kernel(const float* __restrict__ x, const float* __restrict__ g) {
    __shared__ float shs[8], shss[8];
    int row = blockIdx.x, t = threadIdx.x;
    float4 v = reinterpret_cast<const float4*>(x + (size_t)row * DIM)[t];
    float2 mi = ln_block(v, shs, shss);
    float4 gv = reinterpret_cast<const float4*>(g)[t];
    float y0 = (v.x - mi.x) * mi.y * gv.x, y1 = (v.y - mi.x) * mi.y * gv.y;
    float y2 = (v.z - mi.x) * mi.y * gv.z, y3 = (v.w - mi.x) * mi.y * gv.w;
    uint2 hi, lo;
    hi.x = pack_split_hi(y0, y1, lo.x);
    hi.y = pack_split_hi(y2, y3, lo.y);
    reinterpret_cast<uint2*>(g_xn_h + (size_t)row * DIM)[t] = hi;
    reinterpret_cast<uint2*>(g_xn_l + (size_t)row * DIM)[t] = lo;
}
__global__ void ln2_kernel(const float* __restrict__ g, float* __restrict__ out) {
    __shared__ float shs[8], shss[8];
    int row = blockIdx.x, t = threadIdx.x;
    float4 v = reinterpret_cast<const float4*>(g_proj + (size_t)row * DIM)[t];
    float2 mi = ln_block(v, shs, shss);
    float4 gv = reinterpret_cast<const float4*>(g)[t];
    float4 o4 = make_float4((v.x - mi.x) * mi.y * gv.x, (v.y - mi.x) * mi.y * gv.y,
                            (v.z - mi.x) * mi.y * gv.z, (v.w - mi.x) * mi.y * gv.w);
    reinterpret_cast<float4*>(out + (size_t)row * DIM)[t] = o4;
}

// ------------------ transpose + split: src[R][C] -> dst[C][R] --------------
template<int MODE>
__global__ void tsplit_kernel(const float* __restrict__ srcp) {
    constexpr int R = (MODE == 0 || MODE == 1) ? DIM : (MODE == 2 ? INNER : NSEQ);
    constexpr int C = (MODE == 0) ? INNER : (MODE == 1 ? 2*DH : (MODE == 2 ? DIM : DH));
    __shared__ float t[32][33];
    const float* src; __nv_bfloat16 *dh, *dl;
    if (MODE == 0) { src = srcp; dh = g_wq_h;  dl = g_wq_l;  }
    else if (MODE == 1) { src = srcp; dh = g_wkv_h; dl = g_wkv_l; }
    else if (MODE == 2) { src = srcp; dh = g_wo_h;  dl = g_wo_l;  }
    else { size_t z = (size_t)blockIdx.z * NSEQ * DH; src = g_vf + z; dh = g_vth + z; dl = g_vtl + z; }
    int r0 = blockIdx.x * 32, c0 = blockIdx.y * 32;
    int tx = threadIdx.x, ty = threadIdx.y;
    #pragma unroll
    for (int i = 0; i < 4; i++)
        t[ty + i*8][tx] = src[(size_t)(r0 + ty + i*8) * C + c0 + tx];
    __syncthreads();
    #pragma unroll
    for (int i = 0; i < 4; i++) {
        float v = t[tx][ty + i*8];
        size_t o = (size_t)(c0 + ty + i*8) * R + r0 + tx;
        __nv_bfloat16 h = __float2bfloat16_rn(v);
        dh[o] = h;
        dl[o] = __float2bfloat16_rn(v - __bfloat162float(h));
    }
}

// -------------------- q/k l2norm * 4 + bf16 split --------------------------
__global__ void qknorm_kernel() {
    int w = (blockIdx.x * blockDim.x + threadIdx.x) >> 5;
    int lane = threadIdx.x & 31;
    const float* src; __nv_bfloat16 *oh, *ol;
    if (w < ROWS * NH) { size_t o = (size_t)w * DH; src = g_qf + o; oh = g_qh + o; ol = g_ql + o; }
    else { int r = w - ROWS * NH; if (r >= ROWS) return;
           size_t o = (size_t)r * DH; src = g_kf + o; oh = g_kh + o; ol = g_kl + o; }
    float2 v = reinterpret_cast<const float2*>(src)[lane];
    float ss = v.x * v.x + v.y * v.y;
    #pragma unroll
    for (int o = 16; o > 0; o >>= 1) ss += __shfl_xor_sync(~0u, ss, o);
    float inv = 4.0f / fmaxf(sqrtf(ss), 1e-12f);
    uint32_t lo, hi = pack_split_hi(v.x * inv, v.y * inv, lo);
    reinterpret_cast<uint32_t*>(oh)[lane] = hi;
    reinterpret_cast<uint32_t*>(ol)[lane] = lo;
}

// --------------------- mma.sync projection GEMM ----------------------------
// C[128m x 128n] = A[m][k] * B[n][k]^T ; bf16 split 3-term; fp32 acc regs.
template<int MODE>
__global__ void __launch_bounds__(256, 1) gemm_mma_kernel() {
    constexpr int KD = (MODE == 2) ? INNER : DIM;
    constexpr int LDT = 40;   // 32 + 8 pad
    __shared__ __nv_bfloat16 sAh[128*LDT], sAl[128*LDT], sBh[128*LDT], sBl[128*LDT];
    const __nv_bfloat16 *Ah, *Al, *Bh, *Bl;
    if (MODE == 0) { Ah = g_xn_h; Al = g_xn_l; Bh = g_wq_h;  Bl = g_wq_l;  }
    else if (MODE == 1) { Ah = g_xn_h; Al = g_xn_l; Bh = g_wkv_h; Bl = g_wkv_l; }
    else { Ah = g_aoh; Al = g_aol; Bh = g_wo_h; Bl = g_wo_l; }

    int tid = threadIdx.x, lane = tid & 31, wid = tid >> 5;
    int m0 = blockIdx.x * 128, n0 = blockIdx.y * 128;
    int wm = wid & 3, wn = wid >> 2;
    uint32_t bAh = smem_u32(sAh), bAl = smem_u32(sAl), bBh = smem_u32(sBh), bBl = smem_u32(sBl);

    float c[2][8][4];
    #pragma unroll
    for (int i = 0; i < 2; i++) for (int j = 0; j < 8; j++) for (int q = 0; q < 4; q++) c[i][j][q] = 0.f;

    int lr = tid >> 2, lc = tid & 3;   // 64 rows x 4 col-chunks per 256-thread pass
    uint4 pf[8];
    auto gload = [&](int kc) {
        size_t ko = (size_t)kc * 32 + lc * 8;
        pf[0] = *reinterpret_cast<const uint4*>(Ah + (size_t)(m0 + lr) * KD + ko);
        pf[1] = *reinterpret_cast<const uint4*>(Ah + (size_t)(m0 + lr + 64) * KD + ko);
        pf[2] = *reinterpret_cast<const uint4*>(Al + (size_t)(m0 + lr) * KD + ko);
        pf[3] = *reinterpret_cast<const uint4*>(Al + (size_t)(m0 + lr + 64) * KD + ko);
        pf[4] = *reinterpret_cast<const uint4*>(Bh + (size_t)(n0 + lr) * KD + ko);
        pf[5] = *reinterpret_cast<const uint4*>(Bh + (size_t)(n0 + lr + 64) * KD + ko);
        pf[6] = *reinterpret_cast<const uint4*>(Bl + (size_t)(n0 + lr) * KD + ko);
        pf[7] = *reinterpret_cast<const uint4*>(Bl + (size_t)(n0 + lr + 64) * KD + ko);
    };
    auto stash = [&]() {
        *reinterpret_cast<uint4*>(sAh + lr * LDT + lc * 8)        = pf[0];
        *reinterpret_cast<uint4*>(sAh + (lr + 64) * LDT + lc * 8) = pf[1];
        *reinterpret_cast<uint4*>(sAl + lr * LDT + lc * 8)        = pf[2];
        *reinterpret_cast<uint4*>(sAl + (lr + 64) * LDT + lc * 8) = pf[3];
        *reinterpret_cast<uint4*>(sBh + lr * LDT + lc * 8)        = pf[4];
        *reinterpret_cast<uint4*>(sBh + (lr + 64) * LDT + lc * 8) = pf[5];
        *reinterpret_cast<uint4*>(sBl + lr * LDT + lc * 8)        = pf[6];
        *reinterpret_cast<uint4*>(sBl + (lr + 64) * LDT + lc * 8) = pf[7];
    };

    const int NC = KD / 32;
    gload(0); stash(); __syncthreads();
    for (int kc = 0; kc < NC; kc++) {
        if (kc + 1 < NC) gload(kc + 1);
        #pragma unroll
        for (int ks = 0; ks < 2; ks++) {
            uint32_t a_h[2][4], a_l[2][4];
            #pragma unroll
            for (int mt = 0; mt < 2; mt++) {
                uint32_t ar = wm * 32 + mt * 16 + (lane & 15);
                uint32_t ac = ks * 16 + (lane >> 4) * 8;
                ldm_x4(a_h[mt], bAh + (ar * LDT + ac) * 2);
                ldm_x4(a_l[mt], bAl + (ar * LDT + ac) * 2);
            }
            uint32_t b_h[16], b_l[16];
            #pragma unroll
            for (int j = 0; j < 4; j++) {
                uint32_t br = wn * 64 + j * 16 + (lane & 7) + ((lane >> 4) & 1) * 8;
                uint32_t bc = ks * 16 + ((lane >> 3) & 1) * 8;
                ldm_x4(&b_h[4 * j], bBh + (br * LDT + bc) * 2);
                ldm_x4(&b_l[4 * j], bBl + (br * LDT + bc) * 2);
            }
            #pragma unroll
            for (int mt = 0; mt < 2; mt++)
                #pragma unroll
                for (int nt = 0; nt < 8; nt++) {
                    mma16816(c[mt][nt], a_h[mt], &b_h[2 * nt]);
                    mma16816(c[mt][nt], a_h[mt], &b_l[2 * nt]);
                    mma16816(c[mt][nt], a_l[mt], &b_h[2 * nt]);
                }
        }
        __syncthreads();
        if (kc + 1 < NC) { stash(); __syncthreads(); }
    }

    // epilogue
    #pragma unroll
    for (int mt = 0; mt < 2; mt++) {
        int r = m0 + wm * 32 + mt * 16 + (lane >> 2);
        #pragma unroll
        for (int nt = 0; nt < 8; nt++) {
            int col = n0 + wn * 64 + nt * 8 + (lane & 3) * 2;
            float2 v0 = make_float2(c[mt][nt][0], c[mt][nt][1]);
            float2 v1 = make_float2(c[mt][nt][2], c[mt][nt][3]);
            if (MODE == 0) {
                int b = r >> 11, nn = r & (NSEQ - 1), hd = col >> 6, di = col & 63;
                float* d0 = g_qf + ((size_t)(b * NH + hd) * NSEQ + nn) * DH + di;
                *reinterpret_cast<float2*>(d0) = v0;
                *reinterpret_cast<float2*>(d0 + 8 * DH) = v1;
            } else if (MODE == 1) {
                float* base = (col < 64) ? (g_kf + (size_t)r * DH + col) : (g_vf + (size_t)r * DH + col - 64);
                *reinterpret_cast<float2*>(base) = v0;
                *reinterpret_cast<float2*>(base + 8 * DH) = v1;
            } else {
                float* d0 = g_proj + (size_t)r * DIM + col;
                *reinterpret_cast<float2*>(d0) = v0;
                *reinterpret_cast<float2*>(d0 + 8 * DIM) = v1;
            }
        }
    }
}

// ------------------------------ attention ----------------------------------
// block: (b,h,q-tile of 128). 8 warps, each owns 16 q-rows x all 64 keys/tile.
__global__ void __launch_bounds__(256, 1) attn_kernel() {
    constexpr int LKV = 72;   // 64 + 8 pad
    __shared__ __nv_bfloat16 skh[64*LKV], skl[64*LKV], svh[64*LKV], svl[64*LKV];
    int tid = threadIdx.x, lane = tid & 31, wid = tid >> 5;
    int b = blockIdx.y >> 3, h = blockIdx.y & 7;
    int q0 = blockIdx.x * 128;
    uint32_t bkh = smem_u32(skh), bkl = smem_u32(skl), bvh = smem_u32(svh), bvl = smem_u32(svl);

    const __nv_bfloat16* qhp = g_qh + ((size_t)(b * NH + h) * NSEQ + q0) * DH;
    const __nv_bfloat16* qlp = g_ql + ((size_t)(b * NH + h) * NSEQ + q0) * DH;
    const __nv_bfloat16* khp = g_kh + (size_t)b * NSEQ * DH;
    const __nv_bfloat16* klp = g_kl + (size_t)b * NSEQ * DH;
    const __nv_bfloat16* vhp = g_vth + (size_t)b * DH * NSEQ;
    const __nv_bfloat16* vlp = g_vtl + (size_t)b * DH * NSEQ;

    int lr = tid >> 2, lc = tid & 3;
    uint32_t qfh[4][4], qfl[4][4];

    // stage Q (rows 0-63 then 64-127) through K smem; keep fragments in regs
    #pragma unroll
    for (int stage = 0; stage < 2; stage++) {
        const uint4* sh = reinterpret_cast<const uint4*>(qhp + (size_t)(stage * 64 + lr) * DH);
        const uint4* sl = reinterpret_cast<const uint4*>(qlp + (size_t)(stage * 64 + lr) * DH);
        *reinterpret_cast<uint4*>(skh + lr * LKV + lc * 16)     = sh[lc * 2];
        *reinterpret_cast<uint4*>(skh + lr * LKV + lc * 16 + 8) = sh[lc * 2 + 1];
        *reinterpret_cast<uint4*>(skl + lr * LKV + lc * 16)     = sl[lc * 2];
        *reinterpret_cast<uint4*>(skl + lr * LKV + lc * 16 + 8) = sl[lc * 2 + 1];
        __syncthreads();
        if ((wid >> 2) == stage) {
            int rb = (wid & 3) * 16 + (lane & 15);
            #pragma unroll
            for (int g = 0; g < 4; g++) {
                uint32_t ac = g * 16 + (lane >> 4) * 8;
                ldm_x4(qfh[g], bkh + (rb * LKV + ac) * 2);
                ldm_x4(qfl[g], bkl + (rb * LKV + ac) * 2);
            }
        }
        __syncthreads();
    }

    float o[8][4];
    #pragma unroll
    for (int i = 0; i < 8; i++) for (int j = 0; j < 4; j++) o[i][j] = 0.f;
    float rs0 = 0.f, rs1 = 0.f;

    for (int kt = 0; kt < NSEQ / 64; kt++) {
        {   // load K tile [64key][64d] and V^T tile [64dh][64key]
            const uint4* s0 = reinterpret_cast<const uint4*>(khp + (size_t)(kt * 64 + lr) * DH);
            const uint4* s1 = reinterpret_cast<const uint4*>(klp + (size_t)(kt * 64 + lr) * DH);
            const uint4* s2 = reinterpret_cast<const uint4*>(vhp + (size_t)lr * NSEQ + kt * 64);
            const uint4* s3 = reinterpret_cast<const uint4*>(vlp + (size_t)lr * NSEQ + kt * 64);
            *reinterpret_cast<uint4*>(skh + lr * LKV + lc * 16)     = s0[lc * 2];
            *reinterpret_cast<uint4*>(skh + lr * LKV + lc * 16 + 8) = s0[lc * 2 + 1];
            *reinterpret_cast<uint4*>(skl + lr * LKV + lc * 16)     = s1[lc * 2];
            *reinterpret_cast<uint4*>(skl + lr * LKV + lc * 16 + 8) = s1[lc * 2 + 1];
            *reinterpret_cast<uint4*>(svh + lr * LKV + lc * 16)     = s2[lc * 2];
            *reinterpret_cast<uint4*>(svh + lr * LKV + lc * 16 + 8) = s2[lc * 2 + 1];
            *reinterpret_cast<uint4*>(svl + lr * LKV + lc * 16)     = s3[lc * 2];
            *reinterpret_cast<uint4*>(svl + lr * LKV + lc * 16 + 8) = s3[lc * 2 + 1];
        }
        __syncthreads();

        // S = Q K^T  (16q x 64key per warp)
        float s[8][4];
        #pragma unroll
        for (int i = 0; i < 8; i++) for (int j = 0; j < 4; j++) s[i][j] = 0.f;
        #pragma unroll
        for (int g = 0; g < 4; g++) {
            uint32_t kb_h[16], kb_l[16];
            #pragma unroll
            for (int j = 0; j < 4; j++) {
                uint32_t br = j * 16 + (lane & 7) + ((lane >> 4) & 1) * 8;
                uint32_t bc = g * 16 + ((lane >> 3) & 1) * 8;
                ldm_x4(&kb_h[4 * j], bkh + (br * LKV + bc) * 2);
                ldm_x4(&kb_l[4 * j], bkl + (br * LKV + bc) * 2);
            }
            #pragma unroll
            for (int nt = 0; nt < 8; nt++) {
                mma16816(s[nt], qfh[g], &kb_h[2 * nt]);
                mma16816(s[nt], qfh[g], &kb_l[2 * nt]);
                mma16816(s[nt], qfl[g], &kb_h[2 * nt]);
            }
        }

        // P = exp(s - 16); pack into A-fragments (hi/lo)
        uint32_t pa[4][4], pl_[4][4];
        #pragma unroll
        for (int g = 0; g < 4; g++) {
            float e00 = __expf(s[2*g][0]   - 16.f), e01 = __expf(s[2*g][1]   - 16.f);
            float e02 = __expf(s[2*g][2]   - 16.f), e03 = __expf(s[2*g][3]   - 16.f);
            float e10 = __expf(s[2*g+1][0] - 16.f), e11 = __expf(s[2*g+1][1] - 16.f);
            float e12 = __expf(s[2*g+1][2] - 16.f), e13 = __expf(s[2*g+1][3] - 16.f);
            rs0 += e00 + e01 + e10 + e11;
            rs1 += e02 + e03 + e12 + e13;
            pa[g][0] = pack_split_hi(e00, e01, pl_[g][0]);
            pa[g][1] = pack_split_hi(e02, e03, pl_[g][1]);
            pa[g][2] = pack_split_hi(e10, e11, pl_[g][2]);
            pa[g][3] = pack_split_hi(e12, e13, pl_[g][3]);
        }

        // O += P V  (16q x 64dh per warp)
        #pragma unroll
        for (int g = 0; g < 4; g++) {
            uint32_t vb_h[16], vb_l[16];
            #pragma unroll
            for (int j = 0; j < 4; j++) {
                uint32_t br = j * 16 + (lane & 7) + ((lane >> 4) & 1) * 8;
                uint32_t bc = g * 16 + ((lane >> 3) & 1) * 8;
                ldm_x4(&vb_h[4 * j], bvh + (br * LKV + bc) * 2);
                ldm_x4(&vb_l[4 * j], bvl + (br * LKV + bc) * 2);
            }
            #pragma unroll
            for (int nt = 0; nt < 8; nt++) {
                mma16816(o[nt], pa[g],  &vb_h[2 * nt]);
                mma16816(o[nt], pl_[g], &vb_h[2 * nt]);
                mma16816(o[nt], pa[g],  &vb_l[2 * nt]);
            }
        }
        __syncthreads();
    }

    // row sums across the 4 lanes sharing a row
    rs0 += __shfl_xor_sync(~0u, rs0, 1); rs0 += __shfl_xor_sync(~0u, rs0, 2);
    rs1 += __shfl_xor_sync(~0u, rs1, 1); rs1 += __shfl_xor_sync(~0u, rs1, 2);
    float i0 = 1.f / rs0, i1 = 1.f / rs1;

    int row0 = q0 + wid * 16 + (lane >> 2);
    #pragma unroll
    for (int nt = 0; nt < 8; nt++) {
        int col = h * DH + nt * 8 + (lane & 3) * 2;
        size_t o0 = (size_t)(b * NSEQ + row0) * INNER + col;
        size_t o1 = (size_t)(b * NSEQ + row0 + 8) * INNER + col;
        uint32_t lo, hi;
        hi = pack_split_hi(o[nt][0] * i0, o[nt][1] * i0, lo);
        *reinterpret_cast<uint32_t*>(g_aoh + o0) = hi;
        *reinterpret_cast<uint32_t*>(g_aol + o0) = lo;
        hi = pack_split_hi(o[nt][2] * i1, o[nt][3] * i1, lo);
        *reinterpret_cast<uint32_t*>(g_aoh + o1) = hi;
        *reinterpret_cast<uint32_t*>(g_aol + o1) = lo;
    }
}

// -------------------------------- launch -----------------------------------
extern "C" void kernel_launch(void* const* d_in, const int* in_sizes, int n_in,
                              void* d_out, int out_size) {
    const float* x          = (const float*)d_in[0];
    const float* norm_g     = (const float*)d_in[1];
    const float* Wq         = (const float*)d_in[2];
    const float* Wkv        = (const float*)d_in[3];
    const float* Wout       = (const float*)d_in[4];
    const float* out_norm_g = (const float*)d_in[5];
    float* out = (float*)d_out;

    ln1_kernel<<<ROWS, 256>>>(x, norm_g);
    tsplit_kernel<0><<<dim3(DIM/32, INNER/32, 1), dim3(32, 8)>>>(Wq);
    tsplit_kernel<1><<<dim3(DIM/32, (2*DH)/32, 1), dim3(32, 8)>>>(Wkv);
    tsplit_kernel<2><<<dim3(INNER/32, DIM/32, 1), dim3(32, 8)>>>(Wout);
    gemm_mma_kernel<0><<<dim3(ROWS/128, INNER/128), 256>>>();
    gemm_mma_kernel<1><<<dim3(ROWS/128, 1), 256>>>();
    qknorm_kernel<<<(ROWS*NH + ROWS)/8, 256>>>();
    tsplit_kernel<3><<<dim3(NSEQ/32, DH/32, BATCH), dim3(32, 8)>>>(nullptr);
    attn_kernel<<<dim3(NSEQ/128, BATCH*NH), 256>>>();
    gemm_mma_kernel<2><<<dim3(ROWS/128, DIM/128), 256>>>();
    ln2_kernel<<<ROWS, 256>>>(out_norm_g, out);
}

// round 5
// speedup vs baseline: 2.6619x; 1.0611x over previous
#include <cuda_runtime.h>
#include <cuda_bf16.h>
#include <cstdint>
#include <math.h>

#define BATCH 4
#define NSEQ  2048
#define DIM   1024
#define NH    8
#define DH    64
#define INNER 512
#define ROWS  (BATCH*NSEQ)

// ----------------------------- scratch ------------------------------------
__device__ __nv_bfloat16 g_xn_h[ROWS*DIM], g_xn_l[ROWS*DIM];
__device__ __nv_bfloat16 g_wq_h[INNER*DIM],  g_wq_l[INNER*DIM];   // Wq^T  [512][1024]
__device__ __nv_bfloat16 g_wkv_h[2*DH*DIM],  g_wkv_l[2*DH*DIM];   // Wkv^T [128][1024]
__device__ __nv_bfloat16 g_wo_h[DIM*INNER],  g_wo_l[DIM*INNER];   // Wout^T[1024][512]
__device__ float g_vf[ROWS*DH];
__device__ __nv_bfloat16 g_qh[ROWS*INNER], g_ql[ROWS*INNER];      // head-major [b][h][n][dh]
__device__ __nv_bfloat16 g_kh[ROWS*DH],    g_kl[ROWS*DH];
__device__ __nv_bfloat16 g_vth[BATCH*DH*NSEQ], g_vtl[BATCH*DH*NSEQ]; // V^T [b][dh][n]
__device__ __nv_bfloat16 g_aoh[ROWS*INNER], g_aol[ROWS*INNER];
__device__ float g_proj[ROWS*DIM];

// --------------------------- helpers --------------------------------------
__device__ __forceinline__ uint32_t smem_u32(const void* p) {
    uint32_t a;
    asm("{ .reg .u64 t; cvta.to.shared.u64 t, %1; cvt.u32.u64 %0, t; }" : "=r"(a) : "l"(p));
    return a;
}
__device__ __forceinline__ void ldm_x4(uint32_t* r, uint32_t addr) {
    asm volatile("ldmatrix.sync.aligned.m8n8.x4.shared.b16 {%0,%1,%2,%3}, [%4];"
                 : "=r"(r[0]), "=r"(r[1]), "=r"(r[2]), "=r"(r[3]) : "r"(addr));
}
__device__ __forceinline__ void mma16816(float* c, const uint32_t* a, const uint32_t* b) {
    asm volatile("mma.sync.aligned.m16n8k16.row.col.f32.bf16.bf16.f32 "
                 "{%0,%1,%2,%3}, {%4,%5,%6,%7}, {%8,%9}, {%0,%1,%2,%3};"
                 : "+f"(c[0]), "+f"(c[1]), "+f"(c[2]), "+f"(c[3])
                 : "r"(a[0]), "r"(a[1]), "r"(a[2]), "r"(a[3]), "r"(b[0]), "r"(b[1]));
}
__device__ __forceinline__ void cp16(uint32_t d, const void* s) {
    asm volatile("cp.async.cg.shared.global [%0], [%1], 16;"
                 :: "r"(d), "l"(__cvta_generic_to_global(s)) : "memory");
}
#define CP_COMMIT() asm volatile("cp.async.commit_group;" ::: "memory")

// fast bf16 2-term split: 2 cvt + 2 bitops + 2 subs
__device__ __forceinline__ uint32_t pack_split_hi(float a, float b, uint32_t& lo) {
    uint32_t hi;
    asm("cvt.rn.bf16x2.f32 %0, %1, %2;" : "=r"(hi) : "f"(b), "f"(a));
    float ra = a - __uint_as_float(hi << 16);
    float rb = b - __uint_as_float(hi & 0xFFFF0000u);
    asm("cvt.rn.bf16x2.f32 %0, %1, %2;" : "=r"(lo) : "f"(rb), "f"(ra));
    return hi;
}

// ------------------------------ LayerNorm ---------------------------------
__device__ __forceinline__ float2 ln_block(float4 v, float* shs, float* shss) {
    int t = threadIdx.x, w = t >> 5, lane = t & 31;
    float s = v.x + v.y + v.z + v.w;
    float ss = v.x*v.x + v.y*v.y + v.z*v.z + v.w*v.w;
    #pragma unroll
    for (int o = 16; o > 0; o >>= 1) { s += __shfl_xor_sync(~0u, s, o); ss += __shfl_xor_sync(~0u, ss, o); }
    if (lane == 0) { shs[w] = s; shss[w] = ss; }
    __syncthreads();
    if (w == 0) {
        s = (lane < 8) ? shs[lane] : 0.f; ss = (lane < 8) ? shss[lane] : 0.f;
        #pragma unroll
        for (int o = 4; o > 0; o >>= 1) { s += __shfl_xor_sync(~0u, s, o); ss += __shfl_xor_sync(~0u, ss, o); }
        if (lane == 0) { shs[0] = s; shss[0] = ss; }
    }
    __syncthreads();
    float mean = shs[0] * (1.f / DIM);
    float inv = rsqrtf(shss[0] * (1.f / DIM) - mean * mean + 1e-5f);
    return make_float2(mean, inv);
}
__global__ void ln1_kernel(const float* __restrict__ x, const float* __restrict__ g) {
    __shared__ float shs[8], shss[8];
    int row = blockIdx.x, t = threadIdx.x;
    float4 v = reinterpret_cast<const float4*>(x + (size_t)row * DIM)[t];
    float2 mi = ln_block(v, shs, shss);
    float4 gv = reinterpret_cast<const float4*>(g)[t];
    float y0 = (v.x - mi.x) * mi.y * gv.x, y1 = (v.y - mi.x) * mi.y * gv.y;
    float y2 = (v.z - mi.x) * mi.y * gv.z, y3 = (v.w - mi.x) * mi.y * gv.w;
    uint2 hi, lo;
    hi.x = pack_split_hi(y0, y1, lo.x);
    hi.y = pack_split_hi(y2, y3, lo.y);
    reinterpret_cast<uint2*>(g_xn_h + (size_t)row * DIM)[t] = hi;
    reinterpret_cast<uint2*>(g_xn_l + (size_t)row * DIM)[t] = lo;
}
__global__ void ln2_kernel(const float* __restrict__ g, float* __restrict__ out) {
    __shared__ float shs[8], shss[8];
    int row = blockIdx.x, t = threadIdx.x;
    float4 v = reinterpret_cast<const float4*>(g_proj + (size_t)row * DIM)[t];
    float2 mi = ln_block(v, shs, shss);
    float4 gv = reinterpret_cast<const float4*>(g)[t];
    float4 o4 = make_float4((v.x - mi.x) * mi.y * gv.x, (v.y - mi.x) * mi.y * gv.y,
                            (v.z - mi.x) * mi.y * gv.z, (v.w - mi.x) * mi.y * gv.w);
    reinterpret_cast<float4*>(out + (size_t)row * DIM)[t] = o4;
}

// ------------------ transpose + split: src[R][C] -> dst[C][R] --------------
template<int MODE>
__global__ void tsplit_kernel(const float* __restrict__ srcp) {
    constexpr int R = (MODE == 0 || MODE == 1) ? DIM : (MODE == 2 ? INNER : NSEQ);
    constexpr int C = (MODE == 0) ? INNER : (MODE == 1 ? 2*DH : (MODE == 2 ? DIM : DH));
    __shared__ float t[32][33];
    const float* src; __nv_bfloat16 *dh, *dl;
    if (MODE == 0) { src = srcp; dh = g_wq_h;  dl = g_wq_l;  }
    else if (MODE == 1) { src = srcp; dh = g_wkv_h; dl = g_wkv_l; }
    else if (MODE == 2) { src = srcp; dh = g_wo_h;  dl = g_wo_l;  }
    else { size_t z = (size_t)blockIdx.z * NSEQ * DH; src = g_vf + z; dh = g_vth + z; dl = g_vtl + z; }
    int r0 = blockIdx.x * 32, c0 = blockIdx.y * 32;
    int tx = threadIdx.x, ty = threadIdx.y;
    #pragma unroll
    for (int i = 0; i < 4; i++)
        t[ty + i*8][tx] = src[(size_t)(r0 + ty + i*8) * C + c0 + tx];
    __syncthreads();
    #pragma unroll
    for (int i = 0; i < 4; i++) {
        float v = t[tx][ty + i*8];
        size_t o = (size_t)(c0 + ty + i*8) * R + r0 + tx;
        __nv_bfloat16 h = __float2bfloat16_rn(v);
        dh[o] = h;
        dl[o] = __float2bfloat16_rn(v - __bfloat162float(h));
    }
}

// --------------------- mma.sync projection GEMM ----------------------------
// C[128m x 128n] = A[m][k] * B[n][k]^T ; bf16 split 3-term; cp.async 2-stage.
// MODE 0: fused q l2norm*4 + split -> g_qh/g_ql (head-major)
// MODE 1: fused k l2norm*4 + split -> g_kh/g_kl ; v fp32 -> g_vf
// MODE 2: fp32 -> g_proj
template<int MODE>
__global__ void __launch_bounds__(256, 1) gemm_mma_kernel() {
    constexpr int KD  = (MODE == 2) ? INNER : DIM;
    constexpr int LDT = 40;               // 32 + 8 pad (bf16 elems)
    constexpr int AS  = 128 * LDT * 2;    // 10240 B per array
    constexpr int STG = 4 * AS;           // 40960 B per stage
    extern __shared__ __align__(16) char dsm[];
    const __nv_bfloat16 *Ah, *Al, *Bh, *Bl;
    if (MODE == 0) { Ah = g_xn_h; Al = g_xn_l; Bh = g_wq_h;  Bl = g_wq_l;  }
    else if (MODE == 1) { Ah = g_xn_h; Al = g_xn_l; Bh = g_wkv_h; Bl = g_wkv_l; }
    else { Ah = g_aoh; Al = g_aol; Bh = g_wo_h; Bl = g_wo_l; }

    int tid = threadIdx.x, lane = tid & 31, wid = tid >> 5;
    int m0 = blockIdx.x * 128, n0 = blockIdx.y * 128;
    int wm = wid & 3, wn = wid >> 2;
    uint32_t sb = smem_u32(dsm);

    float c[2][8][4];
    #pragma unroll
    for (int i = 0; i < 2; i++) for (int j = 0; j < 8; j++) for (int q = 0; q < 4; q++) c[i][j][q] = 0.f;

    int lr = tid >> 2, lc = tid & 3;
    auto pf = [&](int kc, int st) {
        size_t ko = (size_t)kc * 32 + lc * 8;
        uint32_t base = sb + st * STG;
        uint32_t d0 = (lr * LDT + lc * 8) * 2, d1 = ((lr + 64) * LDT + lc * 8) * 2;
        cp16(base + d0,          Ah + (size_t)(m0 + lr) * KD + ko);
        cp16(base + d1,          Ah + (size_t)(m0 + lr + 64) * KD + ko);
        cp16(base + AS + d0,     Al + (size_t)(m0 + lr) * KD + ko);
        cp16(base + AS + d1,     Al + (size_t)(m0 + lr + 64) * KD + ko);
        cp16(base + 2*AS + d0,   Bh + (size_t)(n0 + lr) * KD + ko);
        cp16(base + 2*AS + d1,   Bh + (size_t)(n0 + lr + 64) * KD + ko);
        cp16(base + 3*AS + d0,   Bl + (size_t)(n0 + lr) * KD + ko);
        cp16(base + 3*AS + d1,   Bl + (size_t)(n0 + lr + 64) * KD + ko);
        CP_COMMIT();
    };

    const int NC = KD / 32;
    pf(0, 0);
    for (int kc = 0; kc < NC; kc++) {
        int st = kc & 1;
        if (kc + 1 < NC) { pf(kc + 1, st ^ 1); asm volatile("cp.async.wait_group 1;" ::: "memory"); }
        else             { asm volatile("cp.async.wait_group 0;" ::: "memory"); }
        __syncthreads();
        uint32_t bAh = sb + st * STG, bAl = bAh + AS, bBh = bAh + 2*AS, bBl = bAh + 3*AS;
        #pragma unroll
        for (int ks = 0; ks < 2; ks++) {
            uint32_t a_h[2][4], a_l[2][4];
            #pragma unroll
            for (int mt = 0; mt < 2; mt++) {
                uint32_t ar = wm * 32 + mt * 16 + (lane & 15);
                uint32_t ac = ks * 16 + (lane >> 4) * 8;
                ldm_x4(a_h[mt], bAh + (ar * LDT + ac) * 2);
                ldm_x4(a_l[mt], bAl + (ar * LDT + ac) * 2);
            }
            uint32_t b_h[16], b_l[16];
            #pragma unroll
            for (int j = 0; j < 4; j++) {
                uint32_t br = wn * 64 + j * 16 + (lane & 7) + ((lane >> 4) & 1) * 8;
                uint32_t bc = ks * 16 + ((lane >> 3) & 1) * 8;
                ldm_x4(&b_h[4 * j], bBh + (br * LDT + bc) * 2);
                ldm_x4(&b_l[4 * j], bBl + (br * LDT + bc) * 2);
            }
            #pragma unroll
            for (int mt = 0; mt < 2; mt++)
                #pragma unroll
                for (int nt = 0; nt < 8; nt++) {
                    mma16816(c[mt][nt], a_h[mt], &b_h[2 * nt]);
                    mma16816(c[mt][nt], a_h[mt], &b_l[2 * nt]);
                    mma16816(c[mt][nt], a_l[mt], &b_h[2 * nt]);
                }
        }
        __syncthreads();
    }

    // ------------------------------ epilogue -------------------------------
    #pragma unroll
    for (int mt = 0; mt < 2; mt++) {
        int r = m0 + wm * 32 + mt * 16 + (lane >> 2);
        if (MODE == 0 || (MODE == 1 && wn == 0)) {
            // fused l2norm * 4 over the 64-col head owned by this warp
            float ss0 = 0.f, ss1 = 0.f;
            #pragma unroll
            for (int nt = 0; nt < 8; nt++) {
                ss0 += c[mt][nt][0]*c[mt][nt][0] + c[mt][nt][1]*c[mt][nt][1];
                ss1 += c[mt][nt][2]*c[mt][nt][2] + c[mt][nt][3]*c[mt][nt][3];
            }
            ss0 += __shfl_xor_sync(~0u, ss0, 1); ss0 += __shfl_xor_sync(~0u, ss0, 2);
            ss1 += __shfl_xor_sync(~0u, ss1, 1); ss1 += __shfl_xor_sync(~0u, ss1, 2);
            float i0 = 4.f / fmaxf(sqrtf(ss0), 1e-12f);
            float i1 = 4.f / fmaxf(sqrtf(ss1), 1e-12f);
            __nv_bfloat16 *dhp, *dlp; size_t off0;
            if (MODE == 0) {
                int b = r >> 11, nn = r & (NSEQ - 1), hd = (n0 + wn * 64) >> 6;
                off0 = ((size_t)(b * NH + hd) * NSEQ + nn) * DH;
                dhp = g_qh; dlp = g_ql;
            } else {
                off0 = (size_t)r * DH;
                dhp = g_kh; dlp = g_kl;
            }
            #pragma unroll
            for (int nt = 0; nt < 8; nt++) {
                int di = nt * 8 + (lane & 3) * 2;
                uint32_t lo, hi;
                hi = pack_split_hi(c[mt][nt][0] * i0, c[mt][nt][1] * i0, lo);
                *reinterpret_cast<uint32_t*>(dhp + off0 + di) = hi;
                *reinterpret_cast<uint32_t*>(dlp + off0 + di) = lo;
                hi = pack_split_hi(c[mt][nt][2] * i1, c[mt][nt][3] * i1, lo);
                *reinterpret_cast<uint32_t*>(dhp + off0 + (size_t)8 * DH + di) = hi;
                *reinterpret_cast<uint32_t*>(dlp + off0 + (size_t)8 * DH + di) = lo;
            }
        } else if (MODE == 1) {          // wn == 1: v fp32
            #pragma unroll
            for (int nt = 0; nt < 8; nt++) {
                int di = nt * 8 + (lane & 3) * 2;
                float* d0 = g_vf + (size_t)r * DH + di;
                *reinterpret_cast<float2*>(d0) = make_float2(c[mt][nt][0], c[mt][nt][1]);
                *reinterpret_cast<float2*>(d0 + (size_t)8 * DH) = make_float2(c[mt][nt][2], c[mt][nt][3]);
            }
        } else {                          // MODE 2
            #pragma unroll
            for (int nt = 0; nt < 8; nt++) {
                int col = n0 + wn * 64 + nt * 8 + (lane & 3) * 2;
                float* d0 = g_proj + (size_t)r * DIM + col;
                *reinterpret_cast<float2*>(d0) = make_float2(c[mt][nt][0], c[mt][nt][1]);
                *reinterpret_cast<float2*>(d0 + (size_t)8 * DIM) = make_float2(c[mt][nt][2], c[mt][nt][3]);
            }
        }
    }
}

// ------------------------------ attention ----------------------------------
// block: (b,h,q-tile of 128). 8 warps x 16 q-rows; cp.async 2-stage K/V.
__global__ void __launch_bounds__(256, 1) attn_kernel() {
    constexpr int LKV = 72;              // 64 + 8 pad
    constexpr int AS  = 64 * LKV * 2;    // 9216 B
    constexpr int STG = 4 * AS;          // 36864 B
    extern __shared__ __align__(16) char dsm[];
    int tid = threadIdx.x, lane = tid & 31, wid = tid >> 5;
    int b = blockIdx.y >> 3, h = blockIdx.y & 7;
    int q0 = blockIdx.x * 128;
    uint32_t sb = smem_u32(dsm);

    const __nv_bfloat16* qhp = g_qh + ((size_t)(b * NH + h) * NSEQ + q0) * DH;
    const __nv_bfloat16* qlp = g_ql + ((size_t)(b * NH + h) * NSEQ + q0) * DH;
    const __nv_bfloat16* khp = g_kh + (size_t)b * NSEQ * DH;
    const __nv_bfloat16* klp = g_kl + (size_t)b * NSEQ * DH;
    const __nv_bfloat16* vhp = g_vth + (size_t)b * DH * NSEQ;
    const __nv_bfloat16* vlp = g_vtl + (size_t)b * DH * NSEQ;

    int lr = tid >> 2, lc = tid & 3;
    uint32_t qfh[4][4], qfl[4][4];

    // stage Q (rows 0-63 then 64-127) through stage0 K buffers; frags in regs
    {
        __nv_bfloat16* skh = reinterpret_cast<__nv_bfloat16*>(dsm);
        __nv_bfloat16* skl = reinterpret_cast<__nv_bfloat16*>(dsm + AS);
        #pragma unroll
        for (int stage = 0; stage < 2; stage++) {
            const uint4* sh = reinterpret_cast<const uint4*>(qhp + (size_t)(stage * 64 + lr) * DH);
            const uint4* sl = reinterpret_cast<const uint4*>(qlp + (size_t)(stage * 64 + lr) * DH);
            *reinterpret_cast<uint4*>(skh + lr * LKV + lc * 16)     = sh[lc * 2];
            *reinterpret_cast<uint4*>(skh + lr * LKV + lc * 16 + 8) = sh[lc * 2 + 1];
            *reinterpret_cast<uint4*>(skl + lr * LKV + lc * 16)     = sl[lc * 2];
            *reinterpret_cast<uint4*>(skl + lr * LKV + lc * 16 + 8) = sl[lc * 2 + 1];
            __syncthreads();
            if ((wid >> 2) == stage) {
                int rb = (wid & 3) * 16 + (lane & 15);
                #pragma unroll
                for (int g = 0; g < 4; g++) {
                    uint32_t ac = g * 16 + (lane >> 4) * 8;
                    ldm_x4(qfh[g], sb + (rb * LKV + ac) * 2);
                    ldm_x4(qfl[g], sb + AS + (rb * LKV + ac) * 2);
                }
            }
            __syncthreads();
        }
    }

    auto pf = [&](int kt, int st) {
        uint32_t base = sb + st * STG;
        uint32_t d = (lr * LKV + lc * 16) * 2;
        const __nv_bfloat16* k0 = khp + (size_t)(kt * 64 + lr) * DH + lc * 16;
        const __nv_bfloat16* k1 = klp + (size_t)(kt * 64 + lr) * DH + lc * 16;
        const __nv_bfloat16* v0 = vhp + (size_t)lr * NSEQ + kt * 64 + lc * 16;
        const __nv_bfloat16* v1 = vlp + (size_t)lr * NSEQ + kt * 64 + lc * 16;
        cp16(base + d,              k0);  cp16(base + d + 16,          k0 + 8);
        cp16(base + AS + d,         k1);  cp16(base + AS + d + 16,     k1 + 8);
        cp16(base + 2*AS + d,       v0);  cp16(base + 2*AS + d + 16,   v0 + 8);
        cp16(base + 3*AS + d,       v1);  cp16(base + 3*AS + d + 16,   v1 + 8);
        CP_COMMIT();
    };

    float o[8][4];
    #pragma unroll
    for (int i = 0; i < 8; i++) for (int j = 0; j < 4; j++) o[i][j] = 0.f;
    float rs0 = 0.f, rs1 = 0.f;
    const float L2E = 1.44269504f, SH = -23.0831216f;   // -16*log2(e)

    const int NT = NSEQ / 64;
    pf(0, 0);
    for (int kt = 0; kt < NT; kt++) {
        int st = kt & 1;
        if (kt + 1 < NT) { pf(kt + 1, st ^ 1); asm volatile("cp.async.wait_group 1;" ::: "memory"); }
        else             { asm volatile("cp.async.wait_group 0;" ::: "memory"); }
        __syncthreads();
        uint32_t bkh = sb + st * STG, bkl = bkh + AS, bvh = bkh + 2*AS, bvl = bkh + 3*AS;

        // S = Q K^T
        float s[8][4];
        #pragma unroll
        for (int i = 0; i < 8; i++) for (int j = 0; j < 4; j++) s[i][j] = 0.f;
        #pragma unroll
        for (int g = 0; g < 4; g++) {
            uint32_t kb_h[16], kb_l[16];
            #pragma unroll
            for (int j = 0; j < 4; j++) {
                uint32_t br = j * 16 + (lane & 7) + ((lane >> 4) & 1) * 8;
                uint32_t bc = g * 16 + ((lane >> 3) & 1) * 8;
                ldm_x4(&kb_h[4 * j], bkh + (br * LKV + bc) * 2);
                ldm_x4(&kb_l[4 * j], bkl + (br * LKV + bc) * 2);
            }
            #pragma unroll
            for (int nt = 0; nt < 8; nt++) {
                mma16816(s[nt], qfh[g], &kb_h[2 * nt]);
                mma16816(s[nt], qfh[g], &kb_l[2 * nt]);
                mma16816(s[nt], qfl[g], &kb_h[2 * nt]);
            }
        }

        // P = exp(s - 16), packed into A-fragments (hi/lo)
        uint32_t pa[4][4], pl_[4][4];
        #pragma unroll
        for (int g = 0; g < 4; g++) {
            float e00 = exp2f(fmaf(s[2*g][0],   L2E, SH)), e01 = exp2f(fmaf(s[2*g][1],   L2E, SH));
            float e02 = exp2f(fmaf(s[2*g][2],   L2E, SH)), e03 = exp2f(fmaf(s[2*g][3],   L2E, SH));
            float e10 = exp2f(fmaf(s[2*g+1][0], L2E, SH)), e11 = exp2f(fmaf(s[2*g+1][1], L2E, SH));
            float e12 = exp2f(fmaf(s[2*g+1][2], L2E, SH)), e13 = exp2f(fmaf(s[2*g+1][3], L2E, SH));
            rs0 += e00 + e01 + e10 + e11;
            rs1 += e02 + e03 + e12 + e13;
            pa[g][0] = pack_split_hi(e00, e01, pl_[g][0]);
            pa[g][1] = pack_split_hi(e02, e03, pl_[g][1]);
            pa[g][2] = pack_split_hi(e10, e11, pl_[g][2]);
            pa[g][3] = pack_split_hi(e12, e13, pl_[g][3]);
        }

        // O += P V
        #pragma unroll
        for (int g = 0; g < 4; g++) {
            uint32_t vb_h[16], vb_l[16];
            #pragma unroll
            for (int j = 0; j < 4; j++) {
                uint32_t br = j * 16 + (lane & 7) + ((lane >> 4) & 1) * 8;
                uint32_t bc = g * 16 + ((lane >> 3) & 1) * 8;
                ldm_x4(&vb_h[4 * j], bvh + (br * LKV + bc) * 2);
                ldm_x4(&vb_l[4 * j], bvl + (br * LKV + bc) * 2);
            }
            #pragma unroll
            for (int nt = 0; nt < 8; nt++) {
                mma16816(o[nt], pa[g],  &vb_h[2 * nt]);
                mma16816(o[nt], pl_[g], &vb_h[2 * nt]);
                mma16816(o[nt], pa[g],  &vb_l[2 * nt]);
            }
        }
        __syncthreads();
    }

    rs0 += __shfl_xor_sync(~0u, rs0, 1); rs0 += __shfl_xor_sync(~0u, rs0, 2);
    rs1 += __shfl_xor_sync(~0u, rs1, 1); rs1 += __shfl_xor_sync(~0u, rs1, 2);
    float i0 = 1.f / rs0, i1 = 1.f / rs1;

    int row0 = q0 + wid * 16 + (lane >> 2);
    #pragma unroll
    for (int nt = 0; nt < 8; nt++) {
        int col = h * DH + nt * 8 + (lane & 3) * 2;
        size_t o0 = (size_t)(b * NSEQ + row0) * INNER + col;
        size_t o1 = (size_t)(b * NSEQ + row0 + 8) * INNER + col;
        uint32_t lo, hi;
        hi = pack_split_hi(o[nt][0] * i0, o[nt][1] * i0, lo);
        *reinterpret_cast<uint32_t*>(g_aoh + o0) = hi;
        *reinterpret_cast<uint32_t*>(g_aol + o0) = lo;
        hi = pack_split_hi(o[nt][2] * i1, o[nt][3] * i1, lo);
        *reinterpret_cast<uint32_t*>(g_aoh + o1) = hi;
        *reinterpret_cast<uint32_t*>(g_aol + o1) = lo;
    }
}

// -------------------------------- launch -----------------------------------
extern "C" void kernel_launch(void* const* d_in, const int* in_sizes, int n_in,
                              void* d_out, int out_size) {
    const float* x          = (const float*)d_in[0];
    const float* norm_g     = (const float*)d_in[1];
    const float* Wq         = (const float*)d_in[2];
    const float* Wkv        = (const float*)d_in[3];
    const float* Wout       = (const float*)d_in[4];
    const float* out_norm_g = (const float*)d_in[5];
    float* out = (float*)d_out;

    cudaFuncSetAttribute(gemm_mma_kernel<0>, cudaFuncAttributeMaxDynamicSharedMemorySize, 81920);
    cudaFuncSetAttribute(gemm_mma_kernel<1>, cudaFuncAttributeMaxDynamicSharedMemorySize, 81920);
    cudaFuncSetAttribute(gemm_mma_kernel<2>, cudaFuncAttributeMaxDynamicSharedMemorySize, 81920);
    cudaFuncSetAttribute(attn_kernel,        cudaFuncAttributeMaxDynamicSharedMemorySize, 73728);
    cudaGetLastError();

    ln1_kernel<<<ROWS, 256>>>(x, norm_g);
    tsplit_kernel<0><<<dim3(DIM/32, INNER/32, 1), dim3(32, 8)>>>(Wq);
    tsplit_kernel<1><<<dim3(DIM/32, (2*DH)/32, 1), dim3(32, 8)>>>(Wkv);
    tsplit_kernel<2><<<dim3(INNER/32, DIM/32, 1), dim3(32, 8)>>>(Wout);
    gemm_mma_kernel<0><<<dim3(ROWS/128, INNER/128), 256, 81920>>>();
    gemm_mma_kernel<1><<<dim3(ROWS/128, 1), 256, 81920>>>();
    tsplit_kernel<3><<<dim3(NSEQ/32, DH/32, BATCH), dim3(32, 8)>>>(nullptr);
    attn_kernel<<<dim3(NSEQ/128, BATCH*NH), 256, 73728>>>();
    gemm_mma_kernel<2><<<dim3(ROWS/128, DIM/128), 256, 81920>>>();
    ln2_kernel<<<ROWS, 256>>>(out_norm_g, out);
}

// round 6
// speedup vs baseline: 2.7194x; 1.0216x over previous
#include <cuda_runtime.h>
#include <cuda_bf16.h>
#include <cstdint>
#include <math.h>

#define BATCH 4
#define NSEQ  2048
#define DIM   1024
#define NH    8
#define DH    64
#define INNER 512
#define ROWS  (BATCH*NSEQ)

// ----------------------------- scratch ------------------------------------
__device__ __nv_bfloat16 g_xn_h[ROWS*DIM], g_xn_l[ROWS*DIM];
__device__ __nv_bfloat16 g_wq_h[INNER*DIM],  g_wq_l[INNER*DIM];   // Wq^T  [512][1024]
__device__ __nv_bfloat16 g_wkv_h[2*DH*DIM],  g_wkv_l[2*DH*DIM];   // Wkv^T [128][1024]
__device__ __nv_bfloat16 g_wo_h[DIM*INNER],  g_wo_l[DIM*INNER];   // Wout^T[1024][512]
__device__ float g_vf[ROWS*DH];
__device__ __nv_bfloat16 g_qh[ROWS*INNER], g_ql[ROWS*INNER];      // head-major [b][h][n][dh]
__device__ __nv_bfloat16 g_kh[ROWS*DH],    g_kl[ROWS*DH];
__device__ __nv_bfloat16 g_vth[BATCH*DH*NSEQ], g_vtl[BATCH*DH*NSEQ]; // V^T [b][dh][n]
__device__ __nv_bfloat16 g_aoh[ROWS*INNER], g_aol[ROWS*INNER];
__device__ float g_proj[ROWS*DIM];

// --------------------------- helpers --------------------------------------
__device__ __forceinline__ uint32_t smem_u32(const void* p) {
    uint32_t a;
    asm("{ .reg .u64 t; cvta.to.shared.u64 t, %1; cvt.u32.u64 %0, t; }" : "=r"(a) : "l"(p));
    return a;
}
__device__ __forceinline__ void ldm_x4(uint32_t* r, uint32_t addr) {
    asm volatile("ldmatrix.sync.aligned.m8n8.x4.shared.b16 {%0,%1,%2,%3}, [%4];"
                 : "=r"(r[0]), "=r"(r[1]), "=r"(r[2]), "=r"(r[3]) : "r"(addr));
}
__device__ __forceinline__ void mma16816(float* c, const uint32_t* a, const uint32_t* b) {
    asm volatile("mma.sync.aligned.m16n8k16.row.col.f32.bf16.bf16.f32 "
                 "{%0,%1,%2,%3}, {%4,%5,%6,%7}, {%8,%9}, {%0,%1,%2,%3};"
                 : "+f"(c[0]), "+f"(c[1]), "+f"(c[2]), "+f"(c[3])
                 : "r"(a[0]), "r"(a[1]), "r"(a[2]), "r"(a[3]), "r"(b[0]), "r"(b[1]));
}
__device__ __forceinline__ void cp16(uint32_t d, const void* s) {
    asm volatile("cp.async.cg.shared.global [%0], [%1], 16;"
                 :: "r"(d), "l"(__cvta_generic_to_global(s)) : "memory");
}
#define CP_COMMIT() asm volatile("cp.async.commit_group;" ::: "memory")
__device__ __forceinline__ float ex2f(float x) {
    float y;
    asm("ex2.approx.ftz.f32 %0, %1;" : "=f"(y) : "f"(x));
    return y;
}
// fast bf16 2-term split
__device__ __forceinline__ uint32_t pack_split_hi(float a, float b, uint32_t& lo) {
    uint32_t hi;
    asm("cvt.rn.bf16x2.f32 %0, %1, %2;" : "=r"(hi) : "f"(b), "f"(a));
    float ra = a - __uint_as_float(hi << 16);
    float rb = b - __uint_as_float(hi & 0xFFFF0000u);
    asm("cvt.rn.bf16x2.f32 %0, %1, %2;" : "=r"(lo) : "f"(rb), "f"(ra));
    return hi;
}

// ------------------------------ LayerNorm ---------------------------------
__device__ __forceinline__ float2 ln_block(float4 v, float* shs, float* shss) {
    int t = threadIdx.x, w = t >> 5, lane = t & 31;
    float s = v.x + v.y + v.z + v.w;
    float ss = v.x*v.x + v.y*v.y + v.z*v.z + v.w*v.w;
    #pragma unroll
    for (int o = 16; o > 0; o >>= 1) { s += __shfl_xor_sync(~0u, s, o); ss += __shfl_xor_sync(~0u, ss, o); }
    if (lane == 0) { shs[w] = s; shss[w] = ss; }
    __syncthreads();
    if (w == 0) {
        s = (lane < 8) ? shs[lane] : 0.f; ss = (lane < 8) ? shss[lane] : 0.f;
        #pragma unroll
        for (int o = 4; o > 0; o >>= 1) { s += __shfl_xor_sync(~0u, s, o); ss += __shfl_xor_sync(~0u, ss, o); }
        if (lane == 0) { shs[0] = s; shss[0] = ss; }
    }
    __syncthreads();
    float mean = shs[0] * (1.f / DIM);
    float inv = rsqrtf(shss[0] * (1.f / DIM) - mean * mean + 1e-5f);
    return make_float2(mean, inv);
}
__global__ void ln1_kernel(const float* __restrict__ x, const float* __restrict__ g) {
    __shared__ float shs[8], shss[8];
    int row = blockIdx.x, t = threadIdx.x;
    float4 v = reinterpret_cast<const float4*>(x + (size_t)row * DIM)[t];
    float2 mi = ln_block(v, shs, shss);
    float4 gv = reinterpret_cast<const float4*>(g)[t];
    float y0 = (v.x - mi.x) * mi.y * gv.x, y1 = (v.y - mi.x) * mi.y * gv.y;
    float y2 = (v.z - mi.x) * mi.y * gv.z, y3 = (v.w - mi.x) * mi.y * gv.w;
    uint2 hi, lo;
    hi.x = pack_split_hi(y0, y1, lo.x);
    hi.y = pack_split_hi(y2, y3, lo.y);
    reinterpret_cast<uint2*>(g_xn_h + (size_t)row * DIM)[t] = hi;
    reinterpret_cast<uint2*>(g_xn_l + (size_t)row * DIM)[t] = lo;
}
__global__ void ln2_kernel(const float* __restrict__ g, float* __restrict__ out) {
    __shared__ float shs[8], shss[8];
    int row = blockIdx.x, t = threadIdx.x;
    float4 v = reinterpret_cast<const float4*>(g_proj + (size_t)row * DIM)[t];
    float2 mi = ln_block(v, shs, shss);
    float4 gv = reinterpret_cast<const float4*>(g)[t];
    float4 o4 = make_float4((v.x - mi.x) * mi.y * gv.x, (v.y - mi.x) * mi.y * gv.y,
                            (v.z - mi.x) * mi.y * gv.z, (v.w - mi.x) * mi.y * gv.w);
    reinterpret_cast<float4*>(out + (size_t)row * DIM)[t] = o4;
}

// ------------------ transpose + split: src[R][C] -> dst[C][R] --------------
template<int MODE>
__global__ void tsplit_kernel(const float* __restrict__ srcp) {
    constexpr int R = (MODE == 0 || MODE == 1) ? DIM : (MODE == 2 ? INNER : NSEQ);
    constexpr int C = (MODE == 0) ? INNER : (MODE == 1 ? 2*DH : (MODE == 2 ? DIM : DH));
    __shared__ float t[32][33];
    const float* src; __nv_bfloat16 *dh, *dl;
    if (MODE == 0) { src = srcp; dh = g_wq_h;  dl = g_wq_l;  }
    else if (MODE == 1) { src = srcp; dh = g_wkv_h; dl = g_wkv_l; }
    else if (MODE == 2) { src = srcp; dh = g_wo_h;  dl = g_wo_l;  }
    else { size_t z = (size_t)blockIdx.z * NSEQ * DH; src = g_vf + z; dh = g_vth + z; dl = g_vtl + z; }
    int r0 = blockIdx.x * 32, c0 = blockIdx.y * 32;
    int tx = threadIdx.x, ty = threadIdx.y;
    #pragma unroll
    for (int i = 0; i < 4; i++)
        t[ty + i*8][tx] = src[(size_t)(r0 + ty + i*8) * C + c0 + tx];
    __syncthreads();
    #pragma unroll
    for (int i = 0; i < 4; i++) {
        float v = t[tx][ty + i*8];
        size_t o = (size_t)(c0 + ty + i*8) * R + r0 + tx;
        __nv_bfloat16 h = __float2bfloat16_rn(v);
        dh[o] = h;
        dl[o] = __float2bfloat16_rn(v - __bfloat162float(h));
    }
}

// --------------------- mma.sync projection GEMM ----------------------------
// 3-stage cp.async pipeline, 1 sync/iter.
// QKV == 1: grid (64,5); y<4 q-proj (fused l2norm split), y==4 kv.
// QKV == 0: out-proj -> g_proj fp32.
template<int QKV>
__global__ void __launch_bounds__(256, 1) gemm_mma_kernel() {
    constexpr int KD  = QKV ? DIM : INNER;
    constexpr int LDT = 40;               // bf16 elems per row (32+8 pad)
    constexpr int AS  = 128 * LDT * 2;    // 10240 B
    constexpr int STG = 4 * AS;           // 40960 B
    extern __shared__ __align__(16) char dsm[];

    int tid = threadIdx.x, lane = tid & 31, wid = tid >> 5;
    int by = blockIdx.y;
    int m0 = blockIdx.x * 128, n0;
    const __nv_bfloat16 *Ah, *Al, *Bh, *Bl;
    if (QKV) {
        Ah = g_xn_h; Al = g_xn_l;
        if (by < 4) { Bh = g_wq_h;  Bl = g_wq_l;  n0 = by * 128; }
        else        { Bh = g_wkv_h; Bl = g_wkv_l; n0 = 0; }
    } else {
        Ah = g_aoh; Al = g_aol; Bh = g_wo_h; Bl = g_wo_l; n0 = by * 128;
    }
    int wm = wid & 3, wn = wid >> 2;
    uint32_t sb = smem_u32(dsm);

    float c[2][8][4];
    #pragma unroll
    for (int i = 0; i < 2; i++) for (int j = 0; j < 8; j++) for (int q = 0; q < 4; q++) c[i][j][q] = 0.f;

    int lr = tid >> 2, lc = tid & 3;
    auto pf = [&](int kc, int st) {
        size_t ko = (size_t)kc * 32 + lc * 8;
        uint32_t base = sb + st * STG;
        uint32_t d0 = (lr * LDT + lc * 8) * 2, d1 = ((lr + 64) * LDT + lc * 8) * 2;
        cp16(base + d0,          Ah + (size_t)(m0 + lr) * KD + ko);
        cp16(base + d1,          Ah + (size_t)(m0 + lr + 64) * KD + ko);
        cp16(base + AS + d0,     Al + (size_t)(m0 + lr) * KD + ko);
        cp16(base + AS + d1,     Al + (size_t)(m0 + lr + 64) * KD + ko);
        cp16(base + 2*AS + d0,   Bh + (size_t)(n0 + lr) * KD + ko);
        cp16(base + 2*AS + d1,   Bh + (size_t)(n0 + lr + 64) * KD + ko);
        cp16(base + 3*AS + d0,   Bl + (size_t)(n0 + lr) * KD + ko);
        cp16(base + 3*AS + d1,   Bl + (size_t)(n0 + lr + 64) * KD + ko);
        CP_COMMIT();
    };

    const int NC = KD / 32;
    pf(0, 0); pf(1, 1);
    for (int kc = 0; kc < NC; kc++) {
        int st = kc % 3;
        if (kc < NC - 1) asm volatile("cp.async.wait_group 1;" ::: "memory");
        else             asm volatile("cp.async.wait_group 0;" ::: "memory");
        __syncthreads();
        if (kc + 2 < NC) pf(kc + 2, (kc + 2) % 3);
        uint32_t bAh = sb + st * STG, bAl = bAh + AS, bBh = bAh + 2*AS, bBl = bAh + 3*AS;
        #pragma unroll
        for (int ks = 0; ks < 2; ks++) {
            uint32_t a_h[2][4], a_l[2][4];
            #pragma unroll
            for (int mt = 0; mt < 2; mt++) {
                uint32_t ar = wm * 32 + mt * 16 + (lane & 15);
                uint32_t ac = ks * 16 + (lane >> 4) * 8;
                ldm_x4(a_h[mt], bAh + (ar * LDT + ac) * 2);
                ldm_x4(a_l[mt], bAl + (ar * LDT + ac) * 2);
            }
            uint32_t b_h[16], b_l[16];
            #pragma unroll
            for (int j = 0; j < 4; j++) {
                uint32_t br = wn * 64 + j * 16 + (lane & 7) + ((lane >> 4) & 1) * 8;
                uint32_t bc = ks * 16 + ((lane >> 3) & 1) * 8;
                ldm_x4(&b_h[4 * j], bBh + (br * LDT + bc) * 2);
                ldm_x4(&b_l[4 * j], bBl + (br * LDT + bc) * 2);
            }
            #pragma unroll
            for (int mt = 0; mt < 2; mt++)
                #pragma unroll
                for (int nt = 0; nt < 8; nt++) {
                    mma16816(c[mt][nt], a_h[mt], &b_h[2 * nt]);
                    mma16816(c[mt][nt], a_h[mt], &b_l[2 * nt]);
                    mma16816(c[mt][nt], a_l[mt], &b_h[2 * nt]);
                }
        }
    }

    // ------------------------------ epilogue -------------------------------
    bool qpath = QKV && (by < 4);
    bool kpath = QKV && (by == 4) && (wn == 0);
    bool vpath = QKV && (by == 4) && (wn == 1);
    #pragma unroll
    for (int mt = 0; mt < 2; mt++) {
        int r = m0 + wm * 32 + mt * 16 + (lane >> 2);
        if (qpath || kpath) {
            float ss0 = 0.f, ss1 = 0.f;
            #pragma unroll
            for (int nt = 0; nt < 8; nt++) {
                ss0 += c[mt][nt][0]*c[mt][nt][0] + c[mt][nt][1]*c[mt][nt][1];
                ss1 += c[mt][nt][2]*c[mt][nt][2] + c[mt][nt][3]*c[mt][nt][3];
            }
            ss0 += __shfl_xor_sync(~0u, ss0, 1); ss0 += __shfl_xor_sync(~0u, ss0, 2);
            ss1 += __shfl_xor_sync(~0u, ss1, 1); ss1 += __shfl_xor_sync(~0u, ss1, 2);
            float i0 = 4.f / fmaxf(sqrtf(ss0), 1e-12f);
            float i1 = 4.f / fmaxf(sqrtf(ss1), 1e-12f);
            __nv_bfloat16 *dhp, *dlp; size_t off0;
            if (qpath) {
                int b = r >> 11, nn = r & (NSEQ - 1), hd = by * 2 + wn;
                off0 = ((size_t)(b * NH + hd) * NSEQ + nn) * DH;
                dhp = g_qh; dlp = g_ql;
            } else {
                off0 = (size_t)r * DH;
                dhp = g_kh; dlp = g_kl;
            }
            #pragma unroll
            for (int nt = 0; nt < 8; nt++) {
                int di = nt * 8 + (lane & 3) * 2;
                uint32_t lo, hi;
                hi = pack_split_hi(c[mt][nt][0] * i0, c[mt][nt][1] * i0, lo);
                *reinterpret_cast<uint32_t*>(dhp + off0 + di) = hi;
                *reinterpret_cast<uint32_t*>(dlp + off0 + di) = lo;
                hi = pack_split_hi(c[mt][nt][2] * i1, c[mt][nt][3] * i1, lo);
                *reinterpret_cast<uint32_t*>(dhp + off0 + (size_t)8 * DH + di) = hi;
                *reinterpret_cast<uint32_t*>(dlp + off0 + (size_t)8 * DH + di) = lo;
            }
        } else if (vpath) {
            #pragma unroll
            for (int nt = 0; nt < 8; nt++) {
                int di = nt * 8 + (lane & 3) * 2;
                float* d0 = g_vf + (size_t)r * DH + di;
                *reinterpret_cast<float2*>(d0) = make_float2(c[mt][nt][0], c[mt][nt][1]);
                *reinterpret_cast<float2*>(d0 + (size_t)8 * DH) = make_float2(c[mt][nt][2], c[mt][nt][3]);
            }
        } else {
            #pragma unroll
            for (int nt = 0; nt < 8; nt++) {
                int col = n0 + wn * 64 + nt * 8 + (lane & 3) * 2;
                float* d0 = g_proj + (size_t)r * DIM + col;
                *reinterpret_cast<float2*>(d0) = make_float2(c[mt][nt][0], c[mt][nt][1]);
                *reinterpret_cast<float2*>(d0 + (size_t)8 * DIM) = make_float2(c[mt][nt][2], c[mt][nt][3]);
            }
        }
    }
}

// ------------------------------ attention ----------------------------------
// block: (b,h,q-tile of 128). 8 warps x 16 q-rows; 3-stage cp.async, 1 sync/iter.
__global__ void __launch_bounds__(256, 1) attn_kernel() {
    constexpr int LKV = 72;              // 64 + 8 pad
    constexpr int AS  = 64 * LKV * 2;    // 9216 B
    constexpr int STG = 4 * AS;          // 36864 B
    extern __shared__ __align__(16) char dsm[];
    int tid = threadIdx.x, lane = tid & 31, wid = tid >> 5;
    int b = blockIdx.y >> 3, h = blockIdx.y & 7;
    int q0 = blockIdx.x * 128;
    uint32_t sb = smem_u32(dsm);

    const __nv_bfloat16* qhp = g_qh + ((size_t)(b * NH + h) * NSEQ + q0) * DH;
    const __nv_bfloat16* qlp = g_ql + ((size_t)(b * NH + h) * NSEQ + q0) * DH;
    const __nv_bfloat16* khp = g_kh + (size_t)b * NSEQ * DH;
    const __nv_bfloat16* klp = g_kl + (size_t)b * NSEQ * DH;
    const __nv_bfloat16* vhp = g_vth + (size_t)b * DH * NSEQ;
    const __nv_bfloat16* vlp = g_vtl + (size_t)b * DH * NSEQ;

    int lr = tid >> 2, lc = tid & 3;

    auto pf = [&](int kt, int st) {
        uint32_t base = sb + st * STG;
        uint32_t d = (lr * LKV + lc * 16) * 2;
        const __nv_bfloat16* k0 = khp + (size_t)(kt * 64 + lr) * DH + lc * 16;
        const __nv_bfloat16* k1 = klp + (size_t)(kt * 64 + lr) * DH + lc * 16;
        const __nv_bfloat16* v0 = vhp + (size_t)lr * NSEQ + kt * 64 + lc * 16;
        const __nv_bfloat16* v1 = vlp + (size_t)lr * NSEQ + kt * 64 + lc * 16;
        cp16(base + d,            k0);  cp16(base + d + 16,        k0 + 8);
        cp16(base + AS + d,       k1);  cp16(base + AS + d + 16,   k1 + 8);
        cp16(base + 2*AS + d,     v0);  cp16(base + 2*AS + d + 16, v0 + 8);
        cp16(base + 3*AS + d,     v1);  cp16(base + 3*AS + d + 16, v1 + 8);
        CP_COMMIT();
    };

    pf(0, 0); pf(1, 1);   // prefetch first two K/V tiles into stages 0,1

    // stage Q through stage-2 smem; fragments in regs
    uint32_t qfh[4][4], qfl[4][4];
    {
        __nv_bfloat16* skh = reinterpret_cast<__nv_bfloat16*>(dsm + 2 * STG);
        __nv_bfloat16* skl = reinterpret_cast<__nv_bfloat16*>(dsm + 2 * STG + AS);
        uint32_t bq = sb + 2 * STG;
        #pragma unroll
        for (int stage = 0; stage < 2; stage++) {
            const uint4* sh = reinterpret_cast<const uint4*>(qhp + (size_t)(stage * 64 + lr) * DH);
            const uint4* sl = reinterpret_cast<const uint4*>(qlp + (size_t)(stage * 64 + lr) * DH);
            *reinterpret_cast<uint4*>(skh + lr * LKV + lc * 16)     = sh[lc * 2];
            *reinterpret_cast<uint4*>(skh + lr * LKV + lc * 16 + 8) = sh[lc * 2 + 1];
            *reinterpret_cast<uint4*>(skl + lr * LKV + lc * 16)     = sl[lc * 2];
            *reinterpret_cast<uint4*>(skl + lr * LKV + lc * 16 + 8) = sl[lc * 2 + 1];
            __syncthreads();
            if ((wid >> 2) == stage) {
                int rb = (wid & 3) * 16 + (lane & 15);
                #pragma unroll
                for (int g = 0; g < 4; g++) {
                    uint32_t ac = g * 16 + (lane >> 4) * 8;
                    ldm_x4(qfh[g], bq + (rb * LKV + ac) * 2);
                    ldm_x4(qfl[g], bq + AS + (rb * LKV + ac) * 2);
                }
            }
            __syncthreads();
        }
    }

    float o[8][4];
    #pragma unroll
    for (int i = 0; i < 8; i++) for (int j = 0; j < 4; j++) o[i][j] = 0.f;
    float rs0 = 0.f, rs1 = 0.f;
    const float L2E = 1.44269504f, SH = -23.0831216f;   // -16*log2(e)

    const int NT = NSEQ / 64;
    for (int kt = 0; kt < NT; kt++) {
        int st = kt % 3;
        if (kt < NT - 1) asm volatile("cp.async.wait_group 1;" ::: "memory");
        else             asm volatile("cp.async.wait_group 0;" ::: "memory");
        __syncthreads();
        if (kt + 2 < NT) pf(kt + 2, (kt + 2) % 3);
        uint32_t bkh = sb + st * STG, bkl = bkh + AS, bvh = bkh + 2*AS, bvl = bkh + 3*AS;

        // S = Q K^T
        float s[8][4];
        #pragma unroll
        for (int i = 0; i < 8; i++) for (int j = 0; j < 4; j++) s[i][j] = 0.f;
        #pragma unroll
        for (int g = 0; g < 4; g++) {
            uint32_t kb_h[16], kb_l[16];
            #pragma unroll
            for (int j = 0; j < 4; j++) {
                uint32_t br = j * 16 + (lane & 7) + ((lane >> 4) & 1) * 8;
                uint32_t bc = g * 16 + ((lane >> 3) & 1) * 8;
                ldm_x4(&kb_h[4 * j], bkh + (br * LKV + bc) * 2);
                ldm_x4(&kb_l[4 * j], bkl + (br * LKV + bc) * 2);
            }
            #pragma unroll
            for (int nt = 0; nt < 8; nt++) {
                mma16816(s[nt], qfh[g], &kb_h[2 * nt]);
                mma16816(s[nt], qfh[g], &kb_l[2 * nt]);
                mma16816(s[nt], qfl[g], &kb_h[2 * nt]);
            }
        }

        // P = exp(s - 16), packed into A-fragments (hi/lo)
        uint32_t pa[4][4], pl_[4][4];
        #pragma unroll
        for (int g = 0; g < 4; g++) {
            float e00 = ex2f(fmaf(s[2*g][0],   L2E, SH)), e01 = ex2f(fmaf(s[2*g][1],   L2E, SH));
            float e02 = ex2f(fmaf(s[2*g][2],   L2E, SH)), e03 = ex2f(fmaf(s[2*g][3],   L2E, SH));
            float e10 = ex2f(fmaf(s[2*g+1][0], L2E, SH)), e11 = ex2f(fmaf(s[2*g+1][1], L2E, SH));
            float e12 = ex2f(fmaf(s[2*g+1][2], L2E, SH)), e13 = ex2f(fmaf(s[2*g+1][3], L2E, SH));
            rs0 += e00 + e01 + e10 + e11;
            rs1 += e02 + e03 + e12 + e13;
            pa[g][0] = pack_split_hi(e00, e01, pl_[g][0]);
            pa[g][1] = pack_split_hi(e02, e03, pl_[g][1]);
            pa[g][2] = pack_split_hi(e10, e11, pl_[g][2]);
            pa[g][3] = pack_split_hi(e12, e13, pl_[g][3]);
        }

        // O += P V
        #pragma unroll
        for (int g = 0; g < 4; g++) {
            uint32_t vb_h[16], vb_l[16];
            #pragma unroll
            for (int j = 0; j < 4; j++) {
                uint32_t br = j * 16 + (lane & 7) + ((lane >> 4) & 1) * 8;
                uint32_t bc = g * 16 + ((lane >> 3) & 1) * 8;
                ldm_x4(&vb_h[4 * j], bvh + (br * LKV + bc) * 2);
                ldm_x4(&vb_l[4 * j], bvl + (br * LKV + bc) * 2);
            }
            #pragma unroll
            for (int nt = 0; nt < 8; nt++) {
                mma16816(o[nt], pa[g],  &vb_h[2 * nt]);
                mma16816(o[nt], pl_[g], &vb_h[2 * nt]);
                mma16816(o[nt], pa[g],  &vb_l[2 * nt]);
            }
        }
    }

    rs0 += __shfl_xor_sync(~0u, rs0, 1); rs0 += __shfl_xor_sync(~0u, rs0, 2);
    rs1 += __shfl_xor_sync(~0u, rs1, 1); rs1 += __shfl_xor_sync(~0u, rs1, 2);
    float i0 = 1.f / rs0, i1 = 1.f / rs1;

    int row0 = q0 + wid * 16 + (lane >> 2);
    #pragma unroll
    for (int nt = 0; nt < 8; nt++) {
        int col = h * DH + nt * 8 + (lane & 3) * 2;
        size_t o0 = (size_t)(b * NSEQ + row0) * INNER + col;
        size_t o1 = (size_t)(b * NSEQ + row0 + 8) * INNER + col;
        uint32_t lo, hi;
        hi = pack_split_hi(o[nt][0] * i0, o[nt][1] * i0, lo);
        *reinterpret_cast<uint32_t*>(g_aoh + o0) = hi;
        *reinterpret_cast<uint32_t*>(g_aol + o0) = lo;
        hi = pack_split_hi(o[nt][2] * i1, o[nt][3] * i1, lo);
        *reinterpret_cast<uint32_t*>(g_aoh + o1) = hi;
        *reinterpret_cast<uint32_t*>(g_aol + o1) = lo;
    }
}

// -------------------------------- launch -----------------------------------
extern "C" void kernel_launch(void* const* d_in, const int* in_sizes, int n_in,
                              void* d_out, int out_size) {
    const float* x          = (const float*)d_in[0];
    const float* norm_g     = (const float*)d_in[1];
    const float* Wq         = (const float*)d_in[2];
    const float* Wkv        = (const float*)d_in[3];
    const float* Wout       = (const float*)d_in[4];
    const float* out_norm_g = (const float*)d_in[5];
    float* out = (float*)d_out;

    cudaFuncSetAttribute(gemm_mma_kernel<1>, cudaFuncAttributeMaxDynamicSharedMemorySize, 122880);
    cudaFuncSetAttribute(gemm_mma_kernel<0>, cudaFuncAttributeMaxDynamicSharedMemorySize, 122880);
    cudaFuncSetAttribute(attn_kernel,        cudaFuncAttributeMaxDynamicSharedMemorySize, 110592);
    cudaGetLastError();

    ln1_kernel<<<ROWS, 256>>>(x, norm_g);
    tsplit_kernel<0><<<dim3(DIM/32, INNER/32, 1), dim3(32, 8)>>>(Wq);
    tsplit_kernel<1><<<dim3(DIM/32, (2*DH)/32, 1), dim3(32, 8)>>>(Wkv);
    tsplit_kernel<2><<<dim3(INNER/32, DIM/32, 1), dim3(32, 8)>>>(Wout);
    gemm_mma_kernel<1><<<dim3(ROWS/128, 5), 256, 122880>>>();     // q + kv fused
    tsplit_kernel<3><<<dim3(NSEQ/32, DH/32, BATCH), dim3(32, 8)>>>(nullptr);
    attn_kernel<<<dim3(NSEQ/128, BATCH*NH), 256, 110592>>>();
    gemm_mma_kernel<0><<<dim3(ROWS/128, DIM/128), 256, 122880>>>();  // out-proj
    ln2_kernel<<<ROWS, 256>>>(out_norm_g, out);
}

// round 7
// speedup vs baseline: 3.3133x; 1.2184x over previous
#include <cuda_runtime.h>
#include <cuda_fp16.h>
#include <cstdint>
#include <math.h>

#define BATCH 4
#define NSEQ  2048
#define DIM   1024
#define NH    8
#define DH    64
#define INNER 512
#define ROWS  (BATCH*NSEQ)

// ----------------------------- scratch ------------------------------------
__device__ __half g_xn_h[ROWS*DIM];                       // LN(x), single fp16
__device__ __half g_wq_h[INNER*DIM],  g_wq_l[INNER*DIM];  // Wq^T  [512][1024]
__device__ __half g_wkv_h[2*DH*DIM],  g_wkv_l[2*DH*DIM];  // Wkv^T [128][1024]
__device__ __half g_wo_h[DIM*INNER],  g_wo_l[DIM*INNER];  // Wout^T[1024][512]
__device__ float  g_vf[ROWS*DH];
__device__ __half g_qh[ROWS*INNER];                       // q single fp16, head-major
__device__ __half g_kh[ROWS*DH], g_kl[ROWS*DH];           // k 2-term
__device__ __half g_vth[BATCH*DH*NSEQ], g_vtl[BATCH*DH*NSEQ]; // V^T [b][dh][n] 2-term
__device__ __half g_aoh[ROWS*INNER], g_aol[ROWS*INNER];   // attn out 2-term
__device__ float  g_proj[ROWS*DIM];

// --------------------------- helpers --------------------------------------
__device__ __forceinline__ uint32_t smem_u32(const void* p) {
    uint32_t a;
    asm("{ .reg .u64 t; cvta.to.shared.u64 t, %1; cvt.u32.u64 %0, t; }" : "=r"(a) : "l"(p));
    return a;
}
__device__ __forceinline__ void ldm_x4(uint32_t* r, uint32_t addr) {
    asm volatile("ldmatrix.sync.aligned.m8n8.x4.shared.b16 {%0,%1,%2,%3}, [%4];"
                 : "=r"(r[0]), "=r"(r[1]), "=r"(r[2]), "=r"(r[3]) : "r"(addr));
}
__device__ __forceinline__ void mma16816(float* c, const uint32_t* a, const uint32_t* b) {
    asm volatile("mma.sync.aligned.m16n8k16.row.col.f32.f16.f16.f32 "
                 "{%0,%1,%2,%3}, {%4,%5,%6,%7}, {%8,%9}, {%0,%1,%2,%3};"
                 : "+f"(c[0]), "+f"(c[1]), "+f"(c[2]), "+f"(c[3])
                 : "r"(a[0]), "r"(a[1]), "r"(a[2]), "r"(a[3]), "r"(b[0]), "r"(b[1]));
}
__device__ __forceinline__ void cp16(uint32_t d, const void* s) {
    asm volatile("cp.async.cg.shared.global [%0], [%1], 16;"
                 :: "r"(d), "l"(__cvta_generic_to_global(s)) : "memory");
}
#define CP_COMMIT() asm volatile("cp.async.commit_group;" ::: "memory")
__device__ __forceinline__ float ex2f(float x) {
    float y;
    asm("ex2.approx.ftz.f32 %0, %1;" : "=f"(y) : "f"(x));
    return y;
}
__device__ __forceinline__ uint32_t pack2h(float a, float b) {
    __half2 h = __floats2half2_rn(a, b);
    return *reinterpret_cast<uint32_t*>(&h);
}
__device__ __forceinline__ uint32_t pack_split_hi(float a, float b, uint32_t& lo) {
    __half2 h = __floats2half2_rn(a, b);
    float2 f = __half22float2(h);
    lo = pack2h(a - f.x, b - f.y);
    return *reinterpret_cast<uint32_t*>(&h);
}

// ------------------------------ LayerNorm ---------------------------------
__device__ __forceinline__ float2 ln_block(float4 v, float* shs, float* shss) {
    int t = threadIdx.x, w = t >> 5, lane = t & 31;
    float s = v.x + v.y + v.z + v.w;
    float ss = v.x*v.x + v.y*v.y + v.z*v.z + v.w*v.w;
    #pragma unroll
    for (int o = 16; o > 0; o >>= 1) { s += __shfl_xor_sync(~0u, s, o); ss += __shfl_xor_sync(~0u, ss, o); }
    if (lane == 0) { shs[w] = s; shss[w] = ss; }
    __syncthreads();
    if (w == 0) {
        s = (lane < 8) ? shs[lane] : 0.f; ss = (lane < 8) ? shss[lane] : 0.f;
        #pragma unroll
        for (int o = 4; o > 0; o >>= 1) { s += __shfl_xor_sync(~0u, s, o); ss += __shfl_xor_sync(~0u, ss, o); }
        if (lane == 0) { shs[0] = s; shss[0] = ss; }
    }
    __syncthreads();
    float mean = shs[0] * (1.f / DIM);
    float inv = rsqrtf(shss[0] * (1.f / DIM) - mean * mean + 1e-5f);
    return make_float2(mean, inv);
}
__global__ void ln1_kernel(const float* __restrict__ x, const float* __restrict__ g) {
    __shared__ float shs[8], shss[8];
    int row = blockIdx.x, t = threadIdx.x;
    float4 v = reinterpret_cast<const float4*>(x + (size_t)row * DIM)[t];
    float2 mi = ln_block(v, shs, shss);
    float4 gv = reinterpret_cast<const float4*>(g)[t];
    uint2 hi;
    hi.x = pack2h((v.x - mi.x) * mi.y * gv.x, (v.y - mi.x) * mi.y * gv.y);
    hi.y = pack2h((v.z - mi.x) * mi.y * gv.z, (v.w - mi.x) * mi.y * gv.w);
    reinterpret_cast<uint2*>(g_xn_h + (size_t)row * DIM)[t] = hi;
}
__global__ void ln2_kernel(const float* __restrict__ g, float* __restrict__ out) {
    __shared__ float shs[8], shss[8];
    int row = blockIdx.x, t = threadIdx.x;
    float4 v = reinterpret_cast<const float4*>(g_proj + (size_t)row * DIM)[t];
    float2 mi = ln_block(v, shs, shss);
    float4 gv = reinterpret_cast<const float4*>(g)[t];
    float4 o4 = make_float4((v.x - mi.x) * mi.y * gv.x, (v.y - mi.x) * mi.y * gv.y,
                            (v.z - mi.x) * mi.y * gv.z, (v.w - mi.x) * mi.y * gv.w);
    reinterpret_cast<float4*>(out + (size_t)row * DIM)[t] = o4;
}

// ------------------ transpose + split: src[R][C] -> dst[C][R] --------------
template<int MODE>
__global__ void tsplit_kernel(const float* __restrict__ srcp) {
    constexpr int R = (MODE == 0 || MODE == 1) ? DIM : (MODE == 2 ? INNER : NSEQ);
    constexpr int C = (MODE == 0) ? INNER : (MODE == 1 ? 2*DH : (MODE == 2 ? DIM : DH));
    __shared__ float t[32][33];
    const float* src; __half *dh, *dl;
    if (MODE == 0) { src = srcp; dh = g_wq_h;  dl = g_wq_l;  }
    else if (MODE == 1) { src = srcp; dh = g_wkv_h; dl = g_wkv_l; }
    else if (MODE == 2) { src = srcp; dh = g_wo_h;  dl = g_wo_l;  }
    else { size_t z = (size_t)blockIdx.z * NSEQ * DH; src = g_vf + z; dh = g_vth + z; dl = g_vtl + z; }
    int r0 = blockIdx.x * 32, c0 = blockIdx.y * 32;
    int tx = threadIdx.x, ty = threadIdx.y;
    #pragma unroll
    for (int i = 0; i < 4; i++)
        t[ty + i*8][tx] = src[(size_t)(r0 + ty + i*8) * C + c0 + tx];
    __syncthreads();
    #pragma unroll
    for (int i = 0; i < 4; i++) {
        float v = t[tx][ty + i*8];
        size_t o = (size_t)(c0 + ty + i*8) * R + r0 + tx;
        __half h = __float2half_rn(v);
        dh[o] = h;
        dl[o] = __float2half_rn(v - __half2float(h));
    }
}

// --------------------- mma.sync projection GEMM ----------------------------
// QKV==1: A=xn (single fp16), B 2-term -> 2 mmas. grid (64,5): y<4 q, y==4 kv.
// QKV==0: out-proj, A 2-term, B 2-term -> 3 mmas -> g_proj fp32.
template<int QKV>
__global__ void __launch_bounds__(256, 1) gemm_mma_kernel() {
    constexpr int KD  = QKV ? DIM : INNER;
    constexpr int LDT = 40;               // fp16 elems per row (32+8 pad)
    constexpr int AS  = 128 * LDT * 2;    // 10240 B per array
    constexpr int NAR = QKV ? 3 : 4;      // QKV: [Ah,Bh,Bl]; out: [Ah,Al,Bh,Bl]
    constexpr int STG = NAR * AS;
    extern __shared__ __align__(16) char dsm[];

    int tid = threadIdx.x, lane = tid & 31, wid = tid >> 5;
    int by = blockIdx.y;
    int m0 = blockIdx.x * 128, n0;
    const __half *Ah, *Al, *Bh, *Bl;
    if (QKV) {
        Ah = g_xn_h; Al = nullptr;
        if (by < 4) { Bh = g_wq_h;  Bl = g_wq_l;  n0 = by * 128; }
        else        { Bh = g_wkv_h; Bl = g_wkv_l; n0 = 0; }
    } else {
        Ah = g_aoh; Al = g_aol; Bh = g_wo_h; Bl = g_wo_l; n0 = by * 128;
    }
    int wm = wid & 3, wn = wid >> 2;
    uint32_t sb = smem_u32(dsm);

    float c[2][8][4];
    #pragma unroll
    for (int i = 0; i < 2; i++) for (int j = 0; j < 8; j++) for (int q = 0; q < 4; q++) c[i][j][q] = 0.f;

    int lr = tid >> 2, lc = tid & 3;
    auto pf = [&](int kc, int st) {
        size_t ko = (size_t)kc * 32 + lc * 8;
        uint32_t base = sb + st * STG;
        uint32_t d0 = (lr * LDT + lc * 8) * 2, d1 = ((lr + 64) * LDT + lc * 8) * 2;
        cp16(base + d0,  Ah + (size_t)(m0 + lr) * KD + ko);
        cp16(base + d1,  Ah + (size_t)(m0 + lr + 64) * KD + ko);
        if (!QKV) {
            cp16(base + AS + d0, Al + (size_t)(m0 + lr) * KD + ko);
            cp16(base + AS + d1, Al + (size_t)(m0 + lr + 64) * KD + ko);
        }
        uint32_t bo = QKV ? AS : 2*AS;
        cp16(base + bo + d0,      Bh + (size_t)(n0 + lr) * KD + ko);
        cp16(base + bo + d1,      Bh + (size_t)(n0 + lr + 64) * KD + ko);
        cp16(base + bo + AS + d0, Bl + (size_t)(n0 + lr) * KD + ko);
        cp16(base + bo + AS + d1, Bl + (size_t)(n0 + lr + 64) * KD + ko);
        CP_COMMIT();
    };

    const int NC = KD / 32;
    pf(0, 0); pf(1, 1);
    for (int kc = 0; kc < NC; kc++) {
        int st = kc % 3;
        if (kc < NC - 1) asm volatile("cp.async.wait_group 1;" ::: "memory");
        else             asm volatile("cp.async.wait_group 0;" ::: "memory");
        __syncthreads();
        if (kc + 2 < NC) pf(kc + 2, (kc + 2) % 3);
        uint32_t bAh = sb + st * STG;
        uint32_t bAl = bAh + AS;                       // valid only for !QKV
        uint32_t bBh = bAh + (QKV ? AS : 2*AS), bBl = bBh + AS;
        #pragma unroll
        for (int ks = 0; ks < 2; ks++) {
            uint32_t a_h[2][4], a_l[2][4];
            #pragma unroll
            for (int mt = 0; mt < 2; mt++) {
                uint32_t ar = wm * 32 + mt * 16 + (lane & 15);
                uint32_t ac = ks * 16 + (lane >> 4) * 8;
                ldm_x4(a_h[mt], bAh + (ar * LDT + ac) * 2);
                if (!QKV) ldm_x4(a_l[mt], bAl + (ar * LDT + ac) * 2);
            }
            uint32_t b_h[16], b_l[16];
            #pragma unroll
            for (int j = 0; j < 4; j++) {
                uint32_t br = wn * 64 + j * 16 + (lane & 7) + ((lane >> 4) & 1) * 8;
                uint32_t bc = ks * 16 + ((lane >> 3) & 1) * 8;
                ldm_x4(&b_h[4 * j], bBh + (br * LDT + bc) * 2);
                ldm_x4(&b_l[4 * j], bBl + (br * LDT + bc) * 2);
            }
            #pragma unroll
            for (int mt = 0; mt < 2; mt++)
                #pragma unroll
                for (int nt = 0; nt < 8; nt++) {
                    mma16816(c[mt][nt], a_h[mt], &b_h[2 * nt]);
                    mma16816(c[mt][nt], a_h[mt], &b_l[2 * nt]);
                    if (!QKV) mma16816(c[mt][nt], a_l[mt], &b_h[2 * nt]);
                }
        }
    }

    // ------------------------------ epilogue -------------------------------
    bool qpath = QKV && (by < 4);
    bool kpath = QKV && (by == 4) && (wn == 0);
    bool vpath = QKV && (by == 4) && (wn == 1);
    #pragma unroll
    for (int mt = 0; mt < 2; mt++) {
        int r = m0 + wm * 32 + mt * 16 + (lane >> 2);
        if (qpath || kpath) {
            float ss0 = 0.f, ss1 = 0.f;
            #pragma unroll
            for (int nt = 0; nt < 8; nt++) {
                ss0 += c[mt][nt][0]*c[mt][nt][0] + c[mt][nt][1]*c[mt][nt][1];
                ss1 += c[mt][nt][2]*c[mt][nt][2] + c[mt][nt][3]*c[mt][nt][3];
            }
            ss0 += __shfl_xor_sync(~0u, ss0, 1); ss0 += __shfl_xor_sync(~0u, ss0, 2);
            ss1 += __shfl_xor_sync(~0u, ss1, 1); ss1 += __shfl_xor_sync(~0u, ss1, 2);
            float i0 = 4.f / fmaxf(sqrtf(ss0), 1e-12f);
            float i1 = 4.f / fmaxf(sqrtf(ss1), 1e-12f);
            if (qpath) {
                int b = r >> 11, nn = r & (NSEQ - 1), hd = by * 2 + wn;
                size_t off0 = ((size_t)(b * NH + hd) * NSEQ + nn) * DH;
                #pragma unroll
                for (int nt = 0; nt < 8; nt++) {
                    int di = nt * 8 + (lane & 3) * 2;
                    *reinterpret_cast<uint32_t*>(g_qh + off0 + di) =
                        pack2h(c[mt][nt][0] * i0, c[mt][nt][1] * i0);
                    *reinterpret_cast<uint32_t*>(g_qh + off0 + (size_t)8 * DH + di) =
                        pack2h(c[mt][nt][2] * i1, c[mt][nt][3] * i1);
                }
            } else {
                size_t off0 = (size_t)r * DH;
                #pragma unroll
                for (int nt = 0; nt < 8; nt++) {
                    int di = nt * 8 + (lane & 3) * 2;
                    uint32_t lo, hi;
                    hi = pack_split_hi(c[mt][nt][0] * i0, c[mt][nt][1] * i0, lo);
                    *reinterpret_cast<uint32_t*>(g_kh + off0 + di) = hi;
                    *reinterpret_cast<uint32_t*>(g_kl + off0 + di) = lo;
                    hi = pack_split_hi(c[mt][nt][2] * i1, c[mt][nt][3] * i1, lo);
                    *reinterpret_cast<uint32_t*>(g_kh + off0 + (size_t)8 * DH + di) = hi;
                    *reinterpret_cast<uint32_t*>(g_kl + off0 + (size_t)8 * DH + di) = lo;
                }
            }
        } else if (vpath) {
            #pragma unroll
            for (int nt = 0; nt < 8; nt++) {
                int di = nt * 8 + (lane & 3) * 2;
                float* d0 = g_vf + (size_t)r * DH + di;
                *reinterpret_cast<float2*>(d0) = make_float2(c[mt][nt][0], c[mt][nt][1]);
                *reinterpret_cast<float2*>(d0 + (size_t)8 * DH) = make_float2(c[mt][nt][2], c[mt][nt][3]);
            }
        } else {
            #pragma unroll
            for (int nt = 0; nt < 8; nt++) {
                int col = n0 + wn * 64 + nt * 8 + (lane & 3) * 2;
                float* d0 = g_proj + (size_t)r * DIM + col;
                *reinterpret_cast<float2*>(d0) = make_float2(c[mt][nt][0], c[mt][nt][1]);
                *reinterpret_cast<float2*>(d0 + (size_t)8 * DIM) = make_float2(c[mt][nt][2], c[mt][nt][3]);
            }
        }
    }
}

// ------------------------------ attention ----------------------------------
// block: (b,h,q-tile 128). 8 warps x 16 q-rows; 3-stage cp.async.
// Q single fp16 -> S = Qh*(Kh+Kl): 2 mmas. P single fp16 -> PV = P*(Vh+Vl): 2 mmas.
// softmax: p = exp(s - 5.5) (shift cancels in normalization; p <= e^10.5 < fp16 max)
__global__ void __launch_bounds__(256, 1) attn_kernel() {
    constexpr int LKV = 72;              // 64 + 8 pad
    constexpr int AS  = 64 * LKV * 2;    // 9216 B
    constexpr int STG = 4 * AS;          // 36864 B (kh,kl,vh,vl)
    extern __shared__ __align__(16) char dsm[];
    int tid = threadIdx.x, lane = tid & 31, wid = tid >> 5;
    int b = blockIdx.y >> 3, h = blockIdx.y & 7;
    int q0 = blockIdx.x * 128;
    uint32_t sb = smem_u32(dsm);

    const __half* qhp = g_qh + ((size_t)(b * NH + h) * NSEQ + q0) * DH;
    const __half* khp = g_kh + (size_t)b * NSEQ * DH;
    const __half* klp = g_kl + (size_t)b * NSEQ * DH;
    const __half* vhp = g_vth + (size_t)b * DH * NSEQ;
    const __half* vlp = g_vtl + (size_t)b * DH * NSEQ;

    int lr = tid >> 2, lc = tid & 3;

    auto pf = [&](int kt, int st) {
        uint32_t base = sb + st * STG;
        uint32_t d = (lr * LKV + lc * 16) * 2;
        const __half* k0 = khp + (size_t)(kt * 64 + lr) * DH + lc * 16;
        const __half* k1 = klp + (size_t)(kt * 64 + lr) * DH + lc * 16;
        const __half* v0 = vhp + (size_t)lr * NSEQ + kt * 64 + lc * 16;
        const __half* v1 = vlp + (size_t)lr * NSEQ + kt * 64 + lc * 16;
        cp16(base + d,            k0);  cp16(base + d + 16,        k0 + 8);
        cp16(base + AS + d,       k1);  cp16(base + AS + d + 16,   k1 + 8);
        cp16(base + 2*AS + d,     v0);  cp16(base + 2*AS + d + 16, v0 + 8);
        cp16(base + 3*AS + d,     v1);  cp16(base + 3*AS + d + 16, v1 + 8);
        CP_COMMIT();
    };

    pf(0, 0); pf(1, 1);

    // stage Q through stage-2 smem area; fragments in regs
    uint32_t qfh[4][4];
    {
        __half* skh = reinterpret_cast<__half*>(dsm + 2 * STG);
        uint32_t bq = sb + 2 * STG;
        #pragma unroll
        for (int stage = 0; stage < 2; stage++) {
            const uint4* sh = reinterpret_cast<const uint4*>(qhp + (size_t)(stage * 64 + lr) * DH);
            *reinterpret_cast<uint4*>(skh + lr * LKV + lc * 16)     = sh[lc * 2];
            *reinterpret_cast<uint4*>(skh + lr * LKV + lc * 16 + 8) = sh[lc * 2 + 1];
            __syncthreads();
            if ((wid >> 2) == stage) {
                int rb = (wid & 3) * 16 + (lane & 15);
                #pragma unroll
                for (int g = 0; g < 4; g++) {
                    uint32_t ac = g * 16 + (lane >> 4) * 8;
                    ldm_x4(qfh[g], bq + (rb * LKV + ac) * 2);
                }
            }
            __syncthreads();
        }
    }

    float o[8][4];
    #pragma unroll
    for (int i = 0; i < 8; i++) for (int j = 0; j < 4; j++) o[i][j] = 0.f;
    float rs0 = 0.f, rs1 = 0.f;
    const float L2E = 1.44269504f, SH = -7.93482272f;   // -5.5*log2(e)

    const int NT = NSEQ / 64;
    for (int kt = 0; kt < NT; kt++) {
        int st = kt % 3;
        if (kt < NT - 1) asm volatile("cp.async.wait_group 1;" ::: "memory");
        else             asm volatile("cp.async.wait_group 0;" ::: "memory");
        __syncthreads();
        if (kt + 2 < NT) pf(kt + 2, (kt + 2) % 3);
        uint32_t bkh = sb + st * STG, bkl = bkh + AS, bvh = bkh + 2*AS, bvl = bkh + 3*AS;

        // S = Q K^T  (Q single term, K 2-term)
        float s[8][4];
        #pragma unroll
        for (int i = 0; i < 8; i++) for (int j = 0; j < 4; j++) s[i][j] = 0.f;
        #pragma unroll
        for (int g = 0; g < 4; g++) {
            uint32_t kb_h[16], kb_l[16];
            #pragma unroll
            for (int j = 0; j < 4; j++) {
                uint32_t br = j * 16 + (lane & 7) + ((lane >> 4) & 1) * 8;
                uint32_t bc = g * 16 + ((lane >> 3) & 1) * 8;
                ldm_x4(&kb_h[4 * j], bkh + (br * LKV + bc) * 2);
                ldm_x4(&kb_l[4 * j], bkl + (br * LKV + bc) * 2);
            }
            #pragma unroll
            for (int nt = 0; nt < 8; nt++) {
                mma16816(s[nt], qfh[g], &kb_h[2 * nt]);
                mma16816(s[nt], qfh[g], &kb_l[2 * nt]);
            }
        }

        // P = exp(s - 5.5), packed single fp16 into A-fragments
        uint32_t pa[4][4];
        #pragma unroll
        for (int g = 0; g < 4; g++) {
            float e00 = ex2f(fmaf(s[2*g][0],   L2E, SH)), e01 = ex2f(fmaf(s[2*g][1],   L2E, SH));
            float e02 = ex2f(fmaf(s[2*g][2],   L2E, SH)), e03 = ex2f(fmaf(s[2*g][3],   L2E, SH));
            float e10 = ex2f(fmaf(s[2*g+1][0], L2E, SH)), e11 = ex2f(fmaf(s[2*g+1][1], L2E, SH));
            float e12 = ex2f(fmaf(s[2*g+1][2], L2E, SH)), e13 = ex2f(fmaf(s[2*g+1][3], L2E, SH));
            rs0 += e00 + e01 + e10 + e11;
            rs1 += e02 + e03 + e12 + e13;
            pa[g][0] = pack2h(e00, e01);
            pa[g][1] = pack2h(e02, e03);
            pa[g][2] = pack2h(e10, e11);
            pa[g][3] = pack2h(e12, e13);
        }

        // O += P V  (P single term, V 2-term)
        #pragma unroll
        for (int g = 0; g < 4; g++) {
            uint32_t vb_h[16], vb_l[16];
            #pragma unroll
            for (int j = 0; j < 4; j++) {
                uint32_t br = j * 16 + (lane & 7) + ((lane >> 4) & 1) * 8;
                uint32_t bc = g * 16 + ((lane >> 3) & 1) * 8;
                ldm_x4(&vb_h[4 * j], bvh + (br * LKV + bc) * 2);
                ldm_x4(&vb_l[4 * j], bvl + (br * LKV + bc) * 2);
            }
            #pragma unroll
            for (int nt = 0; nt < 8; nt++) {
                mma16816(o[nt], pa[g], &vb_h[2 * nt]);
                mma16816(o[nt], pa[g], &vb_l[2 * nt]);
            }
        }
    }

    rs0 += __shfl_xor_sync(~0u, rs0, 1); rs0 += __shfl_xor_sync(~0u, rs0, 2);
    rs1 += __shfl_xor_sync(~0u, rs1, 1); rs1 += __shfl_xor_sync(~0u, rs1, 2);
    float i0 = 1.f / rs0, i1 = 1.f / rs1;

    int row0 = q0 + wid * 16 + (lane >> 2);
    #pragma unroll
    for (int nt = 0; nt < 8; nt++) {
        int col = h * DH + nt * 8 + (lane & 3) * 2;
        size_t o0 = (size_t)(b * NSEQ + row0) * INNER + col;
        size_t o1 = (size_t)(b * NSEQ + row0 + 8) * INNER + col;
        uint32_t lo, hi;
        hi = pack_split_hi(o[nt][0] * i0, o[nt][1] * i0, lo);
        *reinterpret_cast<uint32_t*>(g_aoh + o0) = hi;
        *reinterpret_cast<uint32_t*>(g_aol + o0) = lo;
        hi = pack_split_hi(o[nt][2] * i1, o[nt][3] * i1, lo);
        *reinterpret_cast<uint32_t*>(g_aoh + o1) = hi;
        *reinterpret_cast<uint32_t*>(g_aol + o1) = lo;
    }
}

// -------------------------------- launch -----------------------------------
extern "C" void kernel_launch(void* const* d_in, const int* in_sizes, int n_in,
                              void* d_out, int out_size) {
    const float* x          = (const float*)d_in[0];
    const float* norm_g     = (const float*)d_in[1];
    const float* Wq         = (const float*)d_in[2];
    const float* Wkv        = (const float*)d_in[3];
    const float* Wout       = (const float*)d_in[4];
    const float* out_norm_g = (const float*)d_in[5];
    float* out = (float*)d_out;

    cudaFuncSetAttribute(gemm_mma_kernel<1>, cudaFuncAttributeMaxDynamicSharedMemorySize, 92160);
    cudaFuncSetAttribute(gemm_mma_kernel<0>, cudaFuncAttributeMaxDynamicSharedMemorySize, 122880);
    cudaFuncSetAttribute(attn_kernel,        cudaFuncAttributeMaxDynamicSharedMemorySize, 110592);
    cudaGetLastError();

    ln1_kernel<<<ROWS, 256>>>(x, norm_g);
    tsplit_kernel<0><<<dim3(DIM/32, INNER/32, 1), dim3(32, 8)>>>(Wq);
    tsplit_kernel<1><<<dim3(DIM/32, (2*DH)/32, 1), dim3(32, 8)>>>(Wkv);
    tsplit_kernel<2><<<dim3(INNER/32, DIM/32, 1), dim3(32, 8)>>>(Wout);
    gemm_mma_kernel<1><<<dim3(ROWS/128, 5), 256, 92160>>>();      // q + kv fused
    tsplit_kernel<3><<<dim3(NSEQ/32, DH/32, BATCH), dim3(32, 8)>>>(nullptr);
    attn_kernel<<<dim3(NSEQ/128, BATCH*NH), 256, 110592>>>();
    gemm_mma_kernel<0><<<dim3(ROWS/128, DIM/128), 256, 122880>>>();  // out-proj
    ln2_kernel<<<ROWS, 256>>>(out_norm_g, out);
}

// round 8
// speedup vs baseline: 3.7345x; 1.1271x over previous
#include <cuda_runtime.h>
#include <cuda_fp16.h>
#include <cstdint>
#include <math.h>

#define BATCH 4
#define NSEQ  2048
#define DIM   1024
#define NH    8
#define DH    64
#define INNER 512
#define ROWS  (BATCH*NSEQ)

// ----------------------------- scratch ------------------------------------
__device__ __half g_xn_h[ROWS*DIM];                       // LN(x), single fp16
__device__ __half g_wq_h[INNER*DIM],  g_wq_l[INNER*DIM];  // Wq^T  [512][1024]
__device__ __half g_wkv_h[2*DH*DIM],  g_wkv_l[2*DH*DIM];  // Wkv^T [128][1024]
__device__ __half g_wo_h[DIM*INNER],  g_wo_l[DIM*INNER];  // Wout^T[1024][512]
__device__ float  g_vf[ROWS*DH];
__device__ __half g_qh[ROWS*INNER];                       // q single fp16, head-major
__device__ __half g_kh[ROWS*DH], g_kl[ROWS*DH];           // k 2-term
__device__ __half g_vth[BATCH*DH*NSEQ], g_vtl[BATCH*DH*NSEQ]; // V^T [b][dh][n] 2-term
__device__ __half g_aoh[ROWS*INNER], g_aol[ROWS*INNER];   // attn out 2-term
__device__ float  g_proj[ROWS*DIM];

// --------------------------- helpers --------------------------------------
__device__ __forceinline__ uint32_t smem_u32(const void* p) {
    uint32_t a;
    asm("{ .reg .u64 t; cvta.to.shared.u64 t, %1; cvt.u32.u64 %0, t; }" : "=r"(a) : "l"(p));
    return a;
}
__device__ __forceinline__ void ldm_x4(uint32_t* r, uint32_t addr) {
    asm volatile("ldmatrix.sync.aligned.m8n8.x4.shared.b16 {%0,%1,%2,%3}, [%4];"
                 : "=r"(r[0]), "=r"(r[1]), "=r"(r[2]), "=r"(r[3]) : "r"(addr));
}
__device__ __forceinline__ void mma16816(float* c, const uint32_t* a, const uint32_t* b) {
    asm volatile("mma.sync.aligned.m16n8k16.row.col.f32.f16.f16.f32 "
                 "{%0,%1,%2,%3}, {%4,%5,%6,%7}, {%8,%9}, {%0,%1,%2,%3};"
                 : "+f"(c[0]), "+f"(c[1]), "+f"(c[2]), "+f"(c[3])
                 : "r"(a[0]), "r"(a[1]), "r"(a[2]), "r"(a[3]), "r"(b[0]), "r"(b[1]));
}
__device__ __forceinline__ void cp16(uint32_t d, const void* s) {
    asm volatile("cp.async.cg.shared.global [%0], [%1], 16;"
                 :: "r"(d), "l"(__cvta_generic_to_global(s)) : "memory");
}
#define CP_COMMIT() asm volatile("cp.async.commit_group;" ::: "memory")
__device__ __forceinline__ float ex2f(float x) {
    float y;
    asm("ex2.approx.ftz.f32 %0, %1;" : "=f"(y) : "f"(x));
    return y;
}
__device__ __forceinline__ uint32_t pack2h(float a, float b) {
    __half2 h = __floats2half2_rn(a, b);
    return *reinterpret_cast<uint32_t*>(&h);
}
__device__ __forceinline__ uint32_t pack_split_hi(float a, float b, uint32_t& lo) {
    __half2 h = __floats2half2_rn(a, b);
    float2 f = __half22float2(h);
    lo = pack2h(a - f.x, b - f.y);
    return *reinterpret_cast<uint32_t*>(&h);
}

// ------------------------------ LayerNorm ---------------------------------
__device__ __forceinline__ float2 ln_block(float4 v, float* shs, float* shss) {
    int t = threadIdx.x, w = t >> 5, lane = t & 31;
    float s = v.x + v.y + v.z + v.w;
    float ss = v.x*v.x + v.y*v.y + v.z*v.z + v.w*v.w;
    #pragma unroll
    for (int o = 16; o > 0; o >>= 1) { s += __shfl_xor_sync(~0u, s, o); ss += __shfl_xor_sync(~0u, ss, o); }
    if (lane == 0) { shs[w] = s; shss[w] = ss; }
    __syncthreads();
    if (w == 0) {
        s = (lane < 8) ? shs[lane] : 0.f; ss = (lane < 8) ? shss[lane] : 0.f;
        #pragma unroll
        for (int o = 4; o > 0; o >>= 1) { s += __shfl_xor_sync(~0u, s, o); ss += __shfl_xor_sync(~0u, ss, o); }
        if (lane == 0) { shs[0] = s; shss[0] = ss; }
    }
    __syncthreads();
    float mean = shs[0] * (1.f / DIM);
    float inv = rsqrtf(shss[0] * (1.f / DIM) - mean * mean + 1e-5f);
    return make_float2(mean, inv);
}
__global__ void ln1_kernel(const float* __restrict__ x, const float* __restrict__ g) {
    __shared__ float shs[8], shss[8];
    int row = blockIdx.x, t = threadIdx.x;
    float4 v = reinterpret_cast<const float4*>(x + (size_t)row * DIM)[t];
    float2 mi = ln_block(v, shs, shss);
    float4 gv = reinterpret_cast<const float4*>(g)[t];
    uint2 hi;
    hi.x = pack2h((v.x - mi.x) * mi.y * gv.x, (v.y - mi.x) * mi.y * gv.y);
    hi.y = pack2h((v.z - mi.x) * mi.y * gv.z, (v.w - mi.x) * mi.y * gv.w);
    reinterpret_cast<uint2*>(g_xn_h + (size_t)row * DIM)[t] = hi;
}
__global__ void ln2_kernel(const float* __restrict__ g, float* __restrict__ out) {
    __shared__ float shs[8], shss[8];
    int row = blockIdx.x, t = threadIdx.x;
    float4 v = reinterpret_cast<const float4*>(g_proj + (size_t)row * DIM)[t];
    float2 mi = ln_block(v, shs, shss);
    float4 gv = reinterpret_cast<const float4*>(g)[t];
    float4 o4 = make_float4((v.x - mi.x) * mi.y * gv.x, (v.y - mi.x) * mi.y * gv.y,
                            (v.z - mi.x) * mi.y * gv.z, (v.w - mi.x) * mi.y * gv.w);
    reinterpret_cast<float4*>(out + (size_t)row * DIM)[t] = o4;
}

// ------------------ transpose + split: src[R][C] -> dst[C][R] --------------
template<int MODE>
__global__ void tsplit_kernel(const float* __restrict__ srcp) {
    constexpr int R = (MODE == 0 || MODE == 1) ? DIM : (MODE == 2 ? INNER : NSEQ);
    constexpr int C = (MODE == 0) ? INNER : (MODE == 1 ? 2*DH : (MODE == 2 ? DIM : DH));
    __shared__ float t[32][33];
    const float* src; __half *dh, *dl;
    if (MODE == 0) { src = srcp; dh = g_wq_h;  dl = g_wq_l;  }
    else if (MODE == 1) { src = srcp; dh = g_wkv_h; dl = g_wkv_l; }
    else if (MODE == 2) { src = srcp; dh = g_wo_h;  dl = g_wo_l;  }
    else { size_t z = (size_t)blockIdx.z * NSEQ * DH; src = g_vf + z; dh = g_vth + z; dl = g_vtl + z; }
    int r0 = blockIdx.x * 32, c0 = blockIdx.y * 32;
    int tx = threadIdx.x, ty = threadIdx.y;
    #pragma unroll
    for (int i = 0; i < 4; i++)
        t[ty + i*8][tx] = src[(size_t)(r0 + ty + i*8) * C + c0 + tx];
    __syncthreads();
    #pragma unroll
    for (int i = 0; i < 4; i++) {
        float v = t[tx][ty + i*8];
        size_t o = (size_t)(c0 + ty + i*8) * R + r0 + tx;
        __half h = __float2half_rn(v);
        dh[o] = h;
        dl[o] = __float2half_rn(v - __half2float(h));
    }
}

// --------------------- mma.sync projection GEMM ----------------------------
// QKV==1: A=xn single fp16, B 2-term -> 2 mmas; 3-stage pipe; grid (64,5).
// QKV==0: out-proj, A/B 2-term -> 3 mmas; 2-stage pipe (fits 2 CTAs/SM).
template<int QKV>
__global__ void __launch_bounds__(256, 2) gemm_mma_kernel() {
    constexpr int KD  = QKV ? DIM : INNER;
    constexpr int LDT = 40;               // fp16 elems per row (32+8 pad)
    constexpr int AS  = 128 * LDT * 2;    // 10240 B per array
    constexpr int NAR = QKV ? 3 : 4;      // QKV: [Ah,Bh,Bl]; out: [Ah,Al,Bh,Bl]
    constexpr int STG = NAR * AS;
    extern __shared__ __align__(16) char dsm[];

    int tid = threadIdx.x, lane = tid & 31, wid = tid >> 5;
    int by = blockIdx.y;
    int m0 = blockIdx.x * 128, n0;
    const __half *Ah, *Al, *Bh, *Bl;
    if (QKV) {
        Ah = g_xn_h; Al = nullptr;
        if (by < 4) { Bh = g_wq_h;  Bl = g_wq_l;  n0 = by * 128; }
        else        { Bh = g_wkv_h; Bl = g_wkv_l; n0 = 0; }
    } else {
        Ah = g_aoh; Al = g_aol; Bh = g_wo_h; Bl = g_wo_l; n0 = by * 128;
    }
    int wm = wid & 3, wn = wid >> 2;
    uint32_t sb = smem_u32(dsm);

    float c[2][8][4];
    #pragma unroll
    for (int i = 0; i < 2; i++) for (int j = 0; j < 8; j++) for (int q = 0; q < 4; q++) c[i][j][q] = 0.f;

    int lr = tid >> 2, lc = tid & 3;
    auto pf = [&](int kc, int st) {
        size_t ko = (size_t)kc * 32 + lc * 8;
        uint32_t base = sb + st * STG;
        uint32_t d0 = (lr * LDT + lc * 8) * 2, d1 = ((lr + 64) * LDT + lc * 8) * 2;
        cp16(base + d0,  Ah + (size_t)(m0 + lr) * KD + ko);
        cp16(base + d1,  Ah + (size_t)(m0 + lr + 64) * KD + ko);
        if (!QKV) {
            cp16(base + AS + d0, Al + (size_t)(m0 + lr) * KD + ko);
            cp16(base + AS + d1, Al + (size_t)(m0 + lr + 64) * KD + ko);
        }
        uint32_t bo = QKV ? AS : 2*AS;
        cp16(base + bo + d0,      Bh + (size_t)(n0 + lr) * KD + ko);
        cp16(base + bo + d1,      Bh + (size_t)(n0 + lr + 64) * KD + ko);
        cp16(base + bo + AS + d0, Bl + (size_t)(n0 + lr) * KD + ko);
        cp16(base + bo + AS + d1, Bl + (size_t)(n0 + lr + 64) * KD + ko);
        CP_COMMIT();
    };

    const int NC = KD / 32;
    pf(0, 0);
    if (QKV) pf(1, 1);
    for (int kc = 0; kc < NC; kc++) {
        int st;
        if (QKV) {
            st = kc % 3;
            if (kc < NC - 1) asm volatile("cp.async.wait_group 1;" ::: "memory");
            else             asm volatile("cp.async.wait_group 0;" ::: "memory");
            __syncthreads();
            if (kc + 2 < NC) pf(kc + 2, (kc + 2) % 3);
        } else {
            st = kc & 1;
            if (kc + 1 < NC) { pf(kc + 1, (kc + 1) & 1);
                               asm volatile("cp.async.wait_group 1;" ::: "memory"); }
            else             { asm volatile("cp.async.wait_group 0;" ::: "memory"); }
            __syncthreads();
        }
        uint32_t bAh = sb + st * STG;
        uint32_t bAl = bAh + AS;                       // valid only for !QKV
        uint32_t bBh = bAh + (QKV ? AS : 2*AS), bBl = bBh + AS;
        #pragma unroll
        for (int ks = 0; ks < 2; ks++) {
            uint32_t a_h[2][4], a_l[2][4];
            #pragma unroll
            for (int mt = 0; mt < 2; mt++) {
                uint32_t ar = wm * 32 + mt * 16 + (lane & 15);
                uint32_t ac = ks * 16 + (lane >> 4) * 8;
                ldm_x4(a_h[mt], bAh + (ar * LDT + ac) * 2);
                if (!QKV) ldm_x4(a_l[mt], bAl + (ar * LDT + ac) * 2);
            }
            #pragma unroll
            for (int j = 0; j < 4; j++) {
                uint32_t bh[4], bl[4];
                uint32_t br = wn * 64 + j * 16 + (lane & 7) + ((lane >> 4) & 1) * 8;
                uint32_t bc = ks * 16 + ((lane >> 3) & 1) * 8;
                ldm_x4(bh, bBh + (br * LDT + bc) * 2);
                ldm_x4(bl, bBl + (br * LDT + bc) * 2);
                #pragma unroll
                for (int mt = 0; mt < 2; mt++)
                    #pragma unroll
                    for (int t2 = 0; t2 < 2; t2++) {
                        mma16816(c[mt][2*j + t2], a_h[mt], &bh[2 * t2]);
                        mma16816(c[mt][2*j + t2], a_h[mt], &bl[2 * t2]);
                        if (!QKV) mma16816(c[mt][2*j + t2], a_l[mt], &bh[2 * t2]);
                    }
            }
        }
        if (!QKV) __syncthreads();     // WAR barrier for 2-stage pipe
    }

    // ------------------------------ epilogue -------------------------------
    bool qpath = QKV && (by < 4);
    bool kpath = QKV && (by == 4) && (wn == 0);
    bool vpath = QKV && (by == 4) && (wn == 1);
    #pragma unroll
    for (int mt = 0; mt < 2; mt++) {
        int r = m0 + wm * 32 + mt * 16 + (lane >> 2);
        if (qpath || kpath) {
            float ss0 = 0.f, ss1 = 0.f;
            #pragma unroll
            for (int nt = 0; nt < 8; nt++) {
                ss0 += c[mt][nt][0]*c[mt][nt][0] + c[mt][nt][1]*c[mt][nt][1];
                ss1 += c[mt][nt][2]*c[mt][nt][2] + c[mt][nt][3]*c[mt][nt][3];
            }
            ss0 += __shfl_xor_sync(~0u, ss0, 1); ss0 += __shfl_xor_sync(~0u, ss0, 2);
            ss1 += __shfl_xor_sync(~0u, ss1, 1); ss1 += __shfl_xor_sync(~0u, ss1, 2);
            float i0 = 4.f / fmaxf(sqrtf(ss0), 1e-12f);
            float i1 = 4.f / fmaxf(sqrtf(ss1), 1e-12f);
            if (qpath) {
                int b = r >> 11, nn = r & (NSEQ - 1), hd = by * 2 + wn;
                size_t off0 = ((size_t)(b * NH + hd) * NSEQ + nn) * DH;
                #pragma unroll
                for (int nt = 0; nt < 8; nt++) {
                    int di = nt * 8 + (lane & 3) * 2;
                    *reinterpret_cast<uint32_t*>(g_qh + off0 + di) =
                        pack2h(c[mt][nt][0] * i0, c[mt][nt][1] * i0);
                    *reinterpret_cast<uint32_t*>(g_qh + off0 + (size_t)8 * DH + di) =
                        pack2h(c[mt][nt][2] * i1, c[mt][nt][3] * i1);
                }
            } else {
                size_t off0 = (size_t)r * DH;
                #pragma unroll
                for (int nt = 0; nt < 8; nt++) {
                    int di = nt * 8 + (lane & 3) * 2;
                    uint32_t lo, hi;
                    hi = pack_split_hi(c[mt][nt][0] * i0, c[mt][nt][1] * i0, lo);
                    *reinterpret_cast<uint32_t*>(g_kh + off0 + di) = hi;
                    *reinterpret_cast<uint32_t*>(g_kl + off0 + di) = lo;
                    hi = pack_split_hi(c[mt][nt][2] * i1, c[mt][nt][3] * i1, lo);
                    *reinterpret_cast<uint32_t*>(g_kh + off0 + (size_t)8 * DH + di) = hi;
                    *reinterpret_cast<uint32_t*>(g_kl + off0 + (size_t)8 * DH + di) = lo;
                }
            }
        } else if (vpath) {
            #pragma unroll
            for (int nt = 0; nt < 8; nt++) {
                int di = nt * 8 + (lane & 3) * 2;
                float* d0 = g_vf + (size_t)r * DH + di;
                *reinterpret_cast<float2*>(d0) = make_float2(c[mt][nt][0], c[mt][nt][1]);
                *reinterpret_cast<float2*>(d0 + (size_t)8 * DH) = make_float2(c[mt][nt][2], c[mt][nt][3]);
            }
        } else {
            #pragma unroll
            for (int nt = 0; nt < 8; nt++) {
                int col = n0 + wn * 64 + nt * 8 + (lane & 3) * 2;
                float* d0 = g_proj + (size_t)r * DIM + col;
                *reinterpret_cast<float2*>(d0) = make_float2(c[mt][nt][0], c[mt][nt][1]);
                *reinterpret_cast<float2*>(d0 + (size_t)8 * DIM) = make_float2(c[mt][nt][2], c[mt][nt][3]);
            }
        }
    }
}

// ------------------------------ attention ----------------------------------
// block: (b,h,q-tile 128). 8 warps x 16 q-rows; 3-stage cp.async; 2 CTAs/SM.
__global__ void __launch_bounds__(256, 2) attn_kernel() {
    constexpr int LKV = 72;              // 64 + 8 pad
    constexpr int AS  = 64 * LKV * 2;    // 9216 B
    constexpr int STG = 4 * AS;          // 36864 B (kh,kl,vh,vl)
    extern __shared__ __align__(16) char dsm[];
    int tid = threadIdx.x, lane = tid & 31, wid = tid >> 5;
    int b = blockIdx.y >> 3, h = blockIdx.y & 7;
    int q0 = blockIdx.x * 128;
    uint32_t sb = smem_u32(dsm);

    const __half* qhp = g_qh + ((size_t)(b * NH + h) * NSEQ + q0) * DH;
    const __half* khp = g_kh + (size_t)b * NSEQ * DH;
    const __half* klp = g_kl + (size_t)b * NSEQ * DH;
    const __half* vhp = g_vth + (size_t)b * DH * NSEQ;
    const __half* vlp = g_vtl + (size_t)b * DH * NSEQ;

    int lr = tid >> 2, lc = tid & 3;

    auto pf = [&](int kt, int st) {
        uint32_t base = sb + st * STG;
        uint32_t d = (lr * LKV + lc * 16) * 2;
        const __half* k0 = khp + (size_t)(kt * 64 + lr) * DH + lc * 16;
        const __half* k1 = klp + (size_t)(kt * 64 + lr) * DH + lc * 16;
        const __half* v0 = vhp + (size_t)lr * NSEQ + kt * 64 + lc * 16;
        const __half* v1 = vlp + (size_t)lr * NSEQ + kt * 64 + lc * 16;
        cp16(base + d,            k0);  cp16(base + d + 16,        k0 + 8);
        cp16(base + AS + d,       k1);  cp16(base + AS + d + 16,   k1 + 8);
        cp16(base + 2*AS + d,     v0);  cp16(base + 2*AS + d + 16, v0 + 8);
        cp16(base + 3*AS + d,     v1);  cp16(base + 3*AS + d + 16, v1 + 8);
        CP_COMMIT();
    };

    pf(0, 0); pf(1, 1);

    // stage Q through stage-2 smem area; fragments in regs
    uint32_t qfh[4][4];
    {
        __half* skh = reinterpret_cast<__half*>(dsm + 2 * STG);
        uint32_t bq = sb + 2 * STG;
        #pragma unroll
        for (int stage = 0; stage < 2; stage++) {
            const uint4* sh = reinterpret_cast<const uint4*>(qhp + (size_t)(stage * 64 + lr) * DH);
            *reinterpret_cast<uint4*>(skh + lr * LKV + lc * 16)     = sh[lc * 2];
            *reinterpret_cast<uint4*>(skh + lr * LKV + lc * 16 + 8) = sh[lc * 2 + 1];
            __syncthreads();
            if ((wid >> 2) == stage) {
                int rb = (wid & 3) * 16 + (lane & 15);
                #pragma unroll
                for (int g = 0; g < 4; g++) {
                    uint32_t ac = g * 16 + (lane >> 4) * 8;
                    ldm_x4(qfh[g], bq + (rb * LKV + ac) * 2);
                }
            }
            __syncthreads();
        }
    }

    float o[8][4];
    #pragma unroll
    for (int i = 0; i < 8; i++) for (int j = 0; j < 4; j++) o[i][j] = 0.f;
    float rs0 = 0.f, rs1 = 0.f;
    const float L2E = 1.44269504f, SH = -7.93482272f;   // -5.5*log2(e)

    const int NT = NSEQ / 64;
    for (int kt = 0; kt < NT; kt++) {
        int st = kt % 3;
        if (kt < NT - 1) asm volatile("cp.async.wait_group 1;" ::: "memory");
        else             asm volatile("cp.async.wait_group 0;" ::: "memory");
        __syncthreads();
        if (kt + 2 < NT) pf(kt + 2, (kt + 2) % 3);
        uint32_t bkh = sb + st * STG, bkl = bkh + AS, bvh = bkh + 2*AS, bvl = bkh + 3*AS;

        // S = Q K^T  (Q single term, K 2-term); b-frags loaded per (j,g)
        float s[8][4];
        #pragma unroll
        for (int i = 0; i < 8; i++) for (int j = 0; j < 4; j++) s[i][j] = 0.f;
        #pragma unroll
        for (int j = 0; j < 4; j++) {
            uint32_t br = j * 16 + (lane & 7) + ((lane >> 4) & 1) * 8;
            #pragma unroll
            for (int g = 0; g < 4; g++) {
                uint32_t bh[4], bl[4];
                uint32_t bc = g * 16 + ((lane >> 3) & 1) * 8;
                ldm_x4(bh, bkh + (br * LKV + bc) * 2);
                ldm_x4(bl, bkl + (br * LKV + bc) * 2);
                #pragma unroll
                for (int t2 = 0; t2 < 2; t2++) {
                    mma16816(s[2*j + t2], qfh[g], &bh[2 * t2]);
                    mma16816(s[2*j + t2], qfh[g], &bl[2 * t2]);
                }
            }
        }

        // P = exp(s - 5.5), packed single fp16 into A-fragments
        uint32_t pa[4][4];
        #pragma unroll
        for (int g = 0; g < 4; g++) {
            float e00 = ex2f(fmaf(s[2*g][0],   L2E, SH)), e01 = ex2f(fmaf(s[2*g][1],   L2E, SH));
            float e02 = ex2f(fmaf(s[2*g][2],   L2E, SH)), e03 = ex2f(fmaf(s[2*g][3],   L2E, SH));
            float e10 = ex2f(fmaf(s[2*g+1][0], L2E, SH)), e11 = ex2f(fmaf(s[2*g+1][1], L2E, SH));
            float e12 = ex2f(fmaf(s[2*g+1][2], L2E, SH)), e13 = ex2f(fmaf(s[2*g+1][3], L2E, SH));
            rs0 += e00 + e01 + e10 + e11;
            rs1 += e02 + e03 + e12 + e13;
            pa[g][0] = pack2h(e00, e01);
            pa[g][1] = pack2h(e02, e03);
            pa[g][2] = pack2h(e10, e11);
            pa[g][3] = pack2h(e12, e13);
        }

        // O += P V  (P single term, V 2-term); b-frags per (j,g)
        #pragma unroll
        for (int j = 0; j < 4; j++) {
            uint32_t br = j * 16 + (lane & 7) + ((lane >> 4) & 1) * 8;
            #pragma unroll
            for (int g = 0; g < 4; g++) {
                uint32_t bh[4], bl[4];
                uint32_t bc = g * 16 + ((lane >> 3) & 1) * 8;
                ldm_x4(bh, bvh + (br * LKV + bc) * 2);
                ldm_x4(bl, bvl + (br * LKV + bc) * 2);
                #pragma unroll
                for (int t2 = 0; t2 < 2; t2++) {
                    mma16816(o[2*j + t2], pa[g], &bh[2 * t2]);
                    mma16816(o[2*j + t2], pa[g], &bl[2 * t2]);
                }
            }
        }
    }

    rs0 += __shfl_xor_sync(~0u, rs0, 1); rs0 += __shfl_xor_sync(~0u, rs0, 2);
    rs1 += __shfl_xor_sync(~0u, rs1, 1); rs1 += __shfl_xor_sync(~0u, rs1, 2);
    float i0 = 1.f / rs0, i1 = 1.f / rs1;

    int row0 = q0 + wid * 16 + (lane >> 2);
    #pragma unroll
    for (int nt = 0; nt < 8; nt++) {
        int col = h * DH + nt * 8 + (lane & 3) * 2;
        size_t o0 = (size_t)(b * NSEQ + row0) * INNER + col;
        size_t o1 = (size_t)(b * NSEQ + row0 + 8) * INNER + col;
        uint32_t lo, hi;
        hi = pack_split_hi(o[nt][0] * i0, o[nt][1] * i0, lo);
        *reinterpret_cast<uint32_t*>(g_aoh + o0) = hi;
        *reinterpret_cast<uint32_t*>(g_aol + o0) = lo;
        hi = pack_split_hi(o[nt][2] * i1, o[nt][3] * i1, lo);
        *reinterpret_cast<uint32_t*>(g_aoh + o1) = hi;
        *reinterpret_cast<uint32_t*>(g_aol + o1) = lo;
    }
}

// -------------------------------- launch -----------------------------------
extern "C" void kernel_launch(void* const* d_in, const int* in_sizes, int n_in,
                              void* d_out, int out_size) {
    const float* x          = (const float*)d_in[0];
    const float* norm_g     = (const float*)d_in[1];
    const float* Wq         = (const float*)d_in[2];
    const float* Wkv        = (const float*)d_in[3];
    const float* Wout       = (const float*)d_in[4];
    const float* out_norm_g = (const float*)d_in[5];
    float* out = (float*)d_out;

    cudaFuncSetAttribute(gemm_mma_kernel<1>, cudaFuncAttributeMaxDynamicSharedMemorySize, 92160);
    cudaFuncSetAttribute(gemm_mma_kernel<0>, cudaFuncAttributeMaxDynamicSharedMemorySize, 81920);
    cudaFuncSetAttribute(attn_kernel,        cudaFuncAttributeMaxDynamicSharedMemorySize, 110592);
    cudaGetLastError();

    ln1_kernel<<<ROWS, 256>>>(x, norm_g);
    tsplit_kernel<0><<<dim3(DIM/32, INNER/32, 1), dim3(32, 8)>>>(Wq);
    tsplit_kernel<1><<<dim3(DIM/32, (2*DH)/32, 1), dim3(32, 8)>>>(Wkv);
    tsplit_kernel<2><<<dim3(INNER/32, DIM/32, 1), dim3(32, 8)>>>(Wout);
    gemm_mma_kernel<1><<<dim3(ROWS/128, 5), 256, 92160>>>();      // q + kv fused
    tsplit_kernel<3><<<dim3(NSEQ/32, DH/32, BATCH), dim3(32, 8)>>>(nullptr);
    attn_kernel<<<dim3(NSEQ/128, BATCH*NH), 256, 110592>>>();
    gemm_mma_kernel<0><<<dim3(ROWS/128, DIM/128), 256, 81920>>>();  // out-proj
    ln2_kernel<<<ROWS, 256>>>(out_norm_g, out);
}

// round 9
// speedup vs baseline: 4.2499x; 1.1380x over previous
#include <cuda_runtime.h>
#include <cuda_fp16.h>
#include <cstdint>
#include <math.h>

#define BATCH 4
#define NSEQ  2048
#define DIM   1024
#define NH    8
#define DH    64
#define INNER 512
#define ROWS  (BATCH*NSEQ)

// ----------------------------- scratch ------------------------------------
__device__ __half g_xn_h[ROWS*DIM];                       // LN(x), single fp16
__device__ __half g_wq_h[INNER*DIM],  g_wq_l[INNER*DIM];  // Wq^T  [512][1024]
__device__ __half g_wkv_h[2*DH*DIM],  g_wkv_l[2*DH*DIM];  // Wkv^T [128][1024]
__device__ __half g_wo_h[DIM*INNER],  g_wo_l[DIM*INNER];  // Wout^T[1024][512]
__device__ float  g_vf[ROWS*DH];
__device__ __half g_qh[ROWS*INNER];                       // q single fp16, head-major
__device__ __half g_kh[ROWS*DH], g_kl[ROWS*DH];           // k 2-term
__device__ __half g_vth[BATCH*DH*NSEQ];                   // V^T [b][dh][n] single fp16
__device__ __half g_aoh[ROWS*INNER], g_aol[ROWS*INNER];   // attn out 2-term
__device__ float  g_proj[ROWS*DIM];

// --------------------------- helpers --------------------------------------
__device__ __forceinline__ uint32_t smem_u32(const void* p) {
    uint32_t a;
    asm("{ .reg .u64 t; cvta.to.shared.u64 t, %1; cvt.u32.u64 %0, t; }" : "=r"(a) : "l"(p));
    return a;
}
__device__ __forceinline__ void ldm_x4(uint32_t* r, uint32_t addr) {
    asm volatile("ldmatrix.sync.aligned.m8n8.x4.shared.b16 {%0,%1,%2,%3}, [%4];"
                 : "=r"(r[0]), "=r"(r[1]), "=r"(r[2]), "=r"(r[3]) : "r"(addr));
}
__device__ __forceinline__ void mma16816(float* c, const uint32_t* a, const uint32_t* b) {
    asm volatile("mma.sync.aligned.m16n8k16.row.col.f32.f16.f16.f32 "
                 "{%0,%1,%2,%3}, {%4,%5,%6,%7}, {%8,%9}, {%0,%1,%2,%3};"
                 : "+f"(c[0]), "+f"(c[1]), "+f"(c[2]), "+f"(c[3])
                 : "r"(a[0]), "r"(a[1]), "r"(a[2]), "r"(a[3]), "r"(b[0]), "r"(b[1]));
}
__device__ __forceinline__ void cp16(uint32_t d, const void* s) {
    asm volatile("cp.async.cg.shared.global [%0], [%1], 16;"
                 :: "r"(d), "l"(__cvta_generic_to_global(s)) : "memory");
}
#define CP_COMMIT() asm volatile("cp.async.commit_group;" ::: "memory")
__device__ __forceinline__ float ex2f(float x) {
    float y;
    asm("ex2.approx.ftz.f32 %0, %1;" : "=f"(y) : "f"(x));
    return y;
}
__device__ __forceinline__ uint32_t pack2h(float a, float b) {
    __half2 h = __floats2half2_rn(a, b);
    return *reinterpret_cast<uint32_t*>(&h);
}
__device__ __forceinline__ uint32_t pack_split_hi(float a, float b, uint32_t& lo) {
    __half2 h = __floats2half2_rn(a, b);
    float2 f = __half22float2(h);
    lo = pack2h(a - f.x, b - f.y);
    return *reinterpret_cast<uint32_t*>(&h);
}

// ------------------------------ LayerNorm ---------------------------------
__device__ __forceinline__ float2 ln_block(float4 v, float* shs, float* shss) {
    int t = threadIdx.x, w = t >> 5, lane = t & 31;
    float s = v.x + v.y + v.z + v.w;
    float ss = v.x*v.x + v.y*v.y + v.z*v.z + v.w*v.w;
    #pragma unroll
    for (int o = 16; o > 0; o >>= 1) { s += __shfl_xor_sync(~0u, s, o); ss += __shfl_xor_sync(~0u, ss, o); }
    if (lane == 0) { shs[w] = s; shss[w] = ss; }
    __syncthreads();
    if (w == 0) {
        s = (lane < 8) ? shs[lane] : 0.f; ss = (lane < 8) ? shss[lane] : 0.f;
        #pragma unroll
        for (int o = 4; o > 0; o >>= 1) { s += __shfl_xor_sync(~0u, s, o); ss += __shfl_xor_sync(~0u, ss, o); }
        if (lane == 0) { shs[0] = s; shss[0] = ss; }
    }
    __syncthreads();
    float mean = shs[0] * (1.f / DIM);
    float inv = rsqrtf(shss[0] * (1.f / DIM) - mean * mean + 1e-5f);
    return make_float2(mean, inv);
}
__global__ void ln1_kernel(const float* __restrict__ x, const float* __restrict__ g) {
    __shared__ float shs[8], shss[8];
    int row = blockIdx.x, t = threadIdx.x;
    float4 v = reinterpret_cast<const float4*>(x + (size_t)row * DIM)[t];
    float2 mi = ln_block(v, shs, shss);
    float4 gv = reinterpret_cast<const float4*>(g)[t];
    uint2 hi;
    hi.x = pack2h((v.x - mi.x) * mi.y * gv.x, (v.y - mi.x) * mi.y * gv.y);
    hi.y = pack2h((v.z - mi.x) * mi.y * gv.z, (v.w - mi.x) * mi.y * gv.w);
    reinterpret_cast<uint2*>(g_xn_h + (size_t)row * DIM)[t] = hi;
}
__global__ void ln2_kernel(const float* __restrict__ g, float* __restrict__ out) {
    __shared__ float shs[8], shss[8];
    int row = blockIdx.x, t = threadIdx.x;
    float4 v = reinterpret_cast<const float4*>(g_proj + (size_t)row * DIM)[t];
    float2 mi = ln_block(v, shs, shss);
    float4 gv = reinterpret_cast<const float4*>(g)[t];
    float4 o4 = make_float4((v.x - mi.x) * mi.y * gv.x, (v.y - mi.x) * mi.y * gv.y,
                            (v.z - mi.x) * mi.y * gv.z, (v.w - mi.x) * mi.y * gv.w);
    reinterpret_cast<float4*>(out + (size_t)row * DIM)[t] = o4;
}

// ------------------ transpose + split: src[R][C] -> dst[C][R] --------------
template<int MODE>
__global__ void tsplit_kernel(const float* __restrict__ srcp) {
    constexpr int R = (MODE == 0 || MODE == 1) ? DIM : (MODE == 2 ? INNER : NSEQ);
    constexpr int C = (MODE == 0) ? INNER : (MODE == 1 ? 2*DH : (MODE == 2 ? DIM : DH));
    __shared__ float t[32][33];
    const float* src; __half *dh, *dl = nullptr;
    if (MODE == 0) { src = srcp; dh = g_wq_h;  dl = g_wq_l;  }
    else if (MODE == 1) { src = srcp; dh = g_wkv_h; dl = g_wkv_l; }
    else if (MODE == 2) { src = srcp; dh = g_wo_h;  dl = g_wo_l;  }
    else { size_t z = (size_t)blockIdx.z * NSEQ * DH; src = g_vf + z; dh = g_vth + z; }
    int r0 = blockIdx.x * 32, c0 = blockIdx.y * 32;
    int tx = threadIdx.x, ty = threadIdx.y;
    #pragma unroll
    for (int i = 0; i < 4; i++)
        t[ty + i*8][tx] = src[(size_t)(r0 + ty + i*8) * C + c0 + tx];
    __syncthreads();
    #pragma unroll
    for (int i = 0; i < 4; i++) {
        float v = t[tx][ty + i*8];
        size_t o = (size_t)(c0 + ty + i*8) * R + r0 + tx;
        __half h = __float2half_rn(v);
        dh[o] = h;
        if (MODE != 3) dl[o] = __float2half_rn(v - __half2float(h));
    }
}

// --------------------- mma.sync projection GEMM ----------------------------
// QKV==1: A=xn single fp16, B 2-term -> 2 mmas; 3-stage pipe; grid (64,5).
// QKV==0: out-proj, A/B 2-term -> 3 mmas; 2-stage pipe (fits 2 CTAs/SM).
template<int QKV>
__global__ void __launch_bounds__(256, 2) gemm_mma_kernel() {
    constexpr int KD  = QKV ? DIM : INNER;
    constexpr int LDT = 40;               // fp16 elems per row (32+8 pad)
    constexpr int AS  = 128 * LDT * 2;    // 10240 B per array
    constexpr int NAR = QKV ? 3 : 4;      // QKV: [Ah,Bh,Bl]; out: [Ah,Al,Bh,Bl]
    constexpr int STG = NAR * AS;
    extern __shared__ __align__(16) char dsm[];

    int tid = threadIdx.x, lane = tid & 31, wid = tid >> 5;
    int by = blockIdx.y;
    int m0 = blockIdx.x * 128, n0;
    const __half *Ah, *Al, *Bh, *Bl;
    if (QKV) {
        Ah = g_xn_h; Al = nullptr;
        if (by < 4) { Bh = g_wq_h;  Bl = g_wq_l;  n0 = by * 128; }
        else        { Bh = g_wkv_h; Bl = g_wkv_l; n0 = 0; }
    } else {
        Ah = g_aoh; Al = g_aol; Bh = g_wo_h; Bl = g_wo_l; n0 = by * 128;
    }
    int wm = wid & 3, wn = wid >> 2;
    uint32_t sb = smem_u32(dsm);

    float c[2][8][4];
    #pragma unroll
    for (int i = 0; i < 2; i++) for (int j = 0; j < 8; j++) for (int q = 0; q < 4; q++) c[i][j][q] = 0.f;

    int lr = tid >> 2, lc = tid & 3;
    auto pf = [&](int kc, int st) {
        size_t ko = (size_t)kc * 32 + lc * 8;
        uint32_t base = sb + st * STG;
        uint32_t d0 = (lr * LDT + lc * 8) * 2, d1 = ((lr + 64) * LDT + lc * 8) * 2;
        cp16(base + d0,  Ah + (size_t)(m0 + lr) * KD + ko);
        cp16(base + d1,  Ah + (size_t)(m0 + lr + 64) * KD + ko);
        if (!QKV) {
            cp16(base + AS + d0, Al + (size_t)(m0 + lr) * KD + ko);
            cp16(base + AS + d1, Al + (size_t)(m0 + lr + 64) * KD + ko);
        }
        uint32_t bo = QKV ? AS : 2*AS;
        cp16(base + bo + d0,      Bh + (size_t)(n0 + lr) * KD + ko);
        cp16(base + bo + d1,      Bh + (size_t)(n0 + lr + 64) * KD + ko);
        cp16(base + bo + AS + d0, Bl + (size_t)(n0 + lr) * KD + ko);
        cp16(base + bo + AS + d1, Bl + (size_t)(n0 + lr + 64) * KD + ko);
        CP_COMMIT();
    };

    const int NC = KD / 32;
    pf(0, 0);
    if (QKV) pf(1, 1);
    for (int kc = 0; kc < NC; kc++) {
        int st;
        if (QKV) {
            st = kc % 3;
            if (kc < NC - 1) asm volatile("cp.async.wait_group 1;" ::: "memory");
            else             asm volatile("cp.async.wait_group 0;" ::: "memory");
            __syncthreads();
            if (kc + 2 < NC) pf(kc + 2, (kc + 2) % 3);
        } else {
            st = kc & 1;
            if (kc + 1 < NC) { pf(kc + 1, (kc + 1) & 1);
                               asm volatile("cp.async.wait_group 1;" ::: "memory"); }
            else             { asm volatile("cp.async.wait_group 0;" ::: "memory"); }
            __syncthreads();
        }
        uint32_t bAh = sb + st * STG;
        uint32_t bAl = bAh + AS;                       // valid only for !QKV
        uint32_t bBh = bAh + (QKV ? AS : 2*AS), bBl = bBh + AS;
        #pragma unroll
        for (int ks = 0; ks < 2; ks++) {
            uint32_t a_h[2][4], a_l[2][4];
            #pragma unroll
            for (int mt = 0; mt < 2; mt++) {
                uint32_t ar = wm * 32 + mt * 16 + (lane & 15);
                uint32_t ac = ks * 16 + (lane >> 4) * 8;
                ldm_x4(a_h[mt], bAh + (ar * LDT + ac) * 2);
                if (!QKV) ldm_x4(a_l[mt], bAl + (ar * LDT + ac) * 2);
            }
            #pragma unroll
            for (int j = 0; j < 4; j++) {
                uint32_t bh[4], bl[4];
                uint32_t br = wn * 64 + j * 16 + (lane & 7) + ((lane >> 4) & 1) * 8;
                uint32_t bc = ks * 16 + ((lane >> 3) & 1) * 8;
                ldm_x4(bh, bBh + (br * LDT + bc) * 2);
                ldm_x4(bl, bBl + (br * LDT + bc) * 2);
                #pragma unroll
                for (int mt = 0; mt < 2; mt++)
                    #pragma unroll
                    for (int t2 = 0; t2 < 2; t2++) {
                        mma16816(c[mt][2*j + t2], a_h[mt], &bh[2 * t2]);
                        mma16816(c[mt][2*j + t2], a_h[mt], &bl[2 * t2]);
                        if (!QKV) mma16816(c[mt][2*j + t2], a_l[mt], &bh[2 * t2]);
                    }
            }
        }
        if (!QKV) __syncthreads();     // WAR barrier for 2-stage pipe
    }

    // ------------------------------ epilogue -------------------------------
    bool qpath = QKV && (by < 4);
    bool kpath = QKV && (by == 4) && (wn == 0);
    bool vpath = QKV && (by == 4) && (wn == 1);
    #pragma unroll
    for (int mt = 0; mt < 2; mt++) {
        int r = m0 + wm * 32 + mt * 16 + (lane >> 2);
        if (qpath || kpath) {
            float ss0 = 0.f, ss1 = 0.f;
            #pragma unroll
            for (int nt = 0; nt < 8; nt++) {
                ss0 += c[mt][nt][0]*c[mt][nt][0] + c[mt][nt][1]*c[mt][nt][1];
                ss1 += c[mt][nt][2]*c[mt][nt][2] + c[mt][nt][3]*c[mt][nt][3];
            }
            ss0 += __shfl_xor_sync(~0u, ss0, 1); ss0 += __shfl_xor_sync(~0u, ss0, 2);
            ss1 += __shfl_xor_sync(~0u, ss1, 1); ss1 += __shfl_xor_sync(~0u, ss1, 2);
            float i0 = 4.f / fmaxf(sqrtf(ss0), 1e-12f);
            float i1 = 4.f / fmaxf(sqrtf(ss1), 1e-12f);
            if (qpath) {
                int b = r >> 11, nn = r & (NSEQ - 1), hd = by * 2 + wn;
                size_t off0 = ((size_t)(b * NH + hd) * NSEQ + nn) * DH;
                #pragma unroll
                for (int nt = 0; nt < 8; nt++) {
                    int di = nt * 8 + (lane & 3) * 2;
                    *reinterpret_cast<uint32_t*>(g_qh + off0 + di) =
                        pack2h(c[mt][nt][0] * i0, c[mt][nt][1] * i0);
                    *reinterpret_cast<uint32_t*>(g_qh + off0 + (size_t)8 * DH + di) =
                        pack2h(c[mt][nt][2] * i1, c[mt][nt][3] * i1);
                }
            } else {
                size_t off0 = (size_t)r * DH;
                #pragma unroll
                for (int nt = 0; nt < 8; nt++) {
                    int di = nt * 8 + (lane & 3) * 2;
                    uint32_t lo, hi;
                    hi = pack_split_hi(c[mt][nt][0] * i0, c[mt][nt][1] * i0, lo);
                    *reinterpret_cast<uint32_t*>(g_kh + off0 + di) = hi;
                    *reinterpret_cast<uint32_t*>(g_kl + off0 + di) = lo;
                    hi = pack_split_hi(c[mt][nt][2] * i1, c[mt][nt][3] * i1, lo);
                    *reinterpret_cast<uint32_t*>(g_kh + off0 + (size_t)8 * DH + di) = hi;
                    *reinterpret_cast<uint32_t*>(g_kl + off0 + (size_t)8 * DH + di) = lo;
                }
            }
        } else if (vpath) {
            #pragma unroll
            for (int nt = 0; nt < 8; nt++) {
                int di = nt * 8 + (lane & 3) * 2;
                float* d0 = g_vf + (size_t)r * DH + di;
                *reinterpret_cast<float2*>(d0) = make_float2(c[mt][nt][0], c[mt][nt][1]);
                *reinterpret_cast<float2*>(d0 + (size_t)8 * DH) = make_float2(c[mt][nt][2], c[mt][nt][3]);
            }
        } else {
            #pragma unroll
            for (int nt = 0; nt < 8; nt++) {
                int col = n0 + wn * 64 + nt * 8 + (lane & 3) * 2;
                float* d0 = g_proj + (size_t)r * DIM + col;
                *reinterpret_cast<float2*>(d0) = make_float2(c[mt][nt][0], c[mt][nt][1]);
                *reinterpret_cast<float2*>(d0 + (size_t)8 * DIM) = make_float2(c[mt][nt][2], c[mt][nt][3]);
            }
        }
    }
}

// ------------------------------ attention ----------------------------------
// block: (b,h,q-tile 128). 8 warps x 16 q-rows; 3-stage cp.async; 2 CTAs/SM.
// S = Qh*(Kh+Kl): 2 mmas. PV = P*Vh: 1 mma (V single fp16).
__global__ void __launch_bounds__(256, 2) attn_kernel() {
    constexpr int LKV = 72;              // 64 + 8 pad
    constexpr int AS  = 64 * LKV * 2;    // 9216 B
    constexpr int STG = 3 * AS;          // 27648 B (kh,kl,vh)
    extern __shared__ __align__(16) char dsm[];
    int tid = threadIdx.x, lane = tid & 31, wid = tid >> 5;
    int b = blockIdx.y >> 3, h = blockIdx.y & 7;
    int q0 = blockIdx.x * 128;
    uint32_t sb = smem_u32(dsm);

    const __half* qhp = g_qh + ((size_t)(b * NH + h) * NSEQ + q0) * DH;
    const __half* khp = g_kh + (size_t)b * NSEQ * DH;
    const __half* klp = g_kl + (size_t)b * NSEQ * DH;
    const __half* vhp = g_vth + (size_t)b * DH * NSEQ;

    int lr = tid >> 2, lc = tid & 3;

    auto pf = [&](int kt, int st) {
        uint32_t base = sb + st * STG;
        uint32_t d = (lr * LKV + lc * 16) * 2;
        const __half* k0 = khp + (size_t)(kt * 64 + lr) * DH + lc * 16;
        const __half* k1 = klp + (size_t)(kt * 64 + lr) * DH + lc * 16;
        const __half* v0 = vhp + (size_t)lr * NSEQ + kt * 64 + lc * 16;
        cp16(base + d,            k0);  cp16(base + d + 16,        k0 + 8);
        cp16(base + AS + d,       k1);  cp16(base + AS + d + 16,   k1 + 8);
        cp16(base + 2*AS + d,     v0);  cp16(base + 2*AS + d + 16, v0 + 8);
        CP_COMMIT();
    };

    pf(0, 0); pf(1, 1);

    // stage Q through stage-2 smem area; fragments in regs
    uint32_t qfh[4][4];
    {
        __half* skh = reinterpret_cast<__half*>(dsm + 2 * STG);
        uint32_t bq = sb + 2 * STG;
        #pragma unroll
        for (int stage = 0; stage < 2; stage++) {
            const uint4* sh = reinterpret_cast<const uint4*>(qhp + (size_t)(stage * 64 + lr) * DH);
            *reinterpret_cast<uint4*>(skh + lr * LKV + lc * 16)     = sh[lc * 2];
            *reinterpret_cast<uint4*>(skh + lr * LKV + lc * 16 + 8) = sh[lc * 2 + 1];
            __syncthreads();
            if ((wid >> 2) == stage) {
                int rb = (wid & 3) * 16 + (lane & 15);
                #pragma unroll
                for (int g = 0; g < 4; g++) {
                    uint32_t ac = g * 16 + (lane >> 4) * 8;
                    ldm_x4(qfh[g], bq + (rb * LKV + ac) * 2);
                }
            }
            __syncthreads();
        }
    }

    float o[8][4];
    #pragma unroll
    for (int i = 0; i < 8; i++) for (int j = 0; j < 4; j++) o[i][j] = 0.f;
    float rs0 = 0.f, rs1 = 0.f;
    const float L2E = 1.44269504f, SH = -7.93482272f;   // -5.5*log2(e)

    const int NT = NSEQ / 64;
    for (int kt = 0; kt < NT; kt++) {
        int st = kt % 3;
        if (kt < NT - 1) asm volatile("cp.async.wait_group 1;" ::: "memory");
        else             asm volatile("cp.async.wait_group 0;" ::: "memory");
        __syncthreads();
        if (kt + 2 < NT) pf(kt + 2, (kt + 2) % 3);
        uint32_t bkh = sb + st * STG, bkl = bkh + AS, bvh = bkh + 2*AS;

        // S = Q K^T  (Q single term, K 2-term)
        float s[8][4];
        #pragma unroll
        for (int i = 0; i < 8; i++) for (int j = 0; j < 4; j++) s[i][j] = 0.f;
        #pragma unroll
        for (int j = 0; j < 4; j++) {
            uint32_t br = j * 16 + (lane & 7) + ((lane >> 4) & 1) * 8;
            #pragma unroll
            for (int g = 0; g < 4; g++) {
                uint32_t bh[4], bl[4];
                uint32_t bc = g * 16 + ((lane >> 3) & 1) * 8;
                ldm_x4(bh, bkh + (br * LKV + bc) * 2);
                ldm_x4(bl, bkl + (br * LKV + bc) * 2);
                #pragma unroll
                for (int t2 = 0; t2 < 2; t2++) {
                    mma16816(s[2*j + t2], qfh[g], &bh[2 * t2]);
                    mma16816(s[2*j + t2], qfh[g], &bl[2 * t2]);
                }
            }
        }

        // P = exp(s - 5.5), packed single fp16 into A-fragments
        uint32_t pa[4][4];
        #pragma unroll
        for (int g = 0; g < 4; g++) {
            float e00 = ex2f(fmaf(s[2*g][0],   L2E, SH)), e01 = ex2f(fmaf(s[2*g][1],   L2E, SH));
            float e02 = ex2f(fmaf(s[2*g][2],   L2E, SH)), e03 = ex2f(fmaf(s[2*g][3],   L2E, SH));
            float e10 = ex2f(fmaf(s[2*g+1][0], L2E, SH)), e11 = ex2f(fmaf(s[2*g+1][1], L2E, SH));
            float e12 = ex2f(fmaf(s[2*g+1][2], L2E, SH)), e13 = ex2f(fmaf(s[2*g+1][3], L2E, SH));
            rs0 += e00 + e01 + e10 + e11;
            rs1 += e02 + e03 + e12 + e13;
            pa[g][0] = pack2h(e00, e01);
            pa[g][1] = pack2h(e02, e03);
            pa[g][2] = pack2h(e10, e11);
            pa[g][3] = pack2h(e12, e13);
        }

        // O += P V  (both single term)
        #pragma unroll
        for (int j = 0; j < 4; j++) {
            uint32_t br = j * 16 + (lane & 7) + ((lane >> 4) & 1) * 8;
            #pragma unroll
            for (int g = 0; g < 4; g++) {
                uint32_t bh[4];
                uint32_t bc = g * 16 + ((lane >> 3) & 1) * 8;
                ldm_x4(bh, bvh + (br * LKV + bc) * 2);
                #pragma unroll
                for (int t2 = 0; t2 < 2; t2++)
                    mma16816(o[2*j + t2], pa[g], &bh[2 * t2]);
            }
        }
    }

    rs0 += __shfl_xor_sync(~0u, rs0, 1); rs0 += __shfl_xor_sync(~0u, rs0, 2);
    rs1 += __shfl_xor_sync(~0u, rs1, 1); rs1 += __shfl_xor_sync(~0u, rs1, 2);
    float i0 = 1.f / rs0, i1 = 1.f / rs1;

    int row0 = q0 + wid * 16 + (lane >> 2);
    #pragma unroll
    for (int nt = 0; nt < 8; nt++) {
        int col = h * DH + nt * 8 + (lane & 3) * 2;
        size_t o0 = (size_t)(b * NSEQ + row0) * INNER + col;
        size_t o1 = (size_t)(b * NSEQ + row0 + 8) * INNER + col;
        uint32_t lo, hi;
        hi = pack_split_hi(o[nt][0] * i0, o[nt][1] * i0, lo);
        *reinterpret_cast<uint32_t*>(g_aoh + o0) = hi;
        *reinterpret_cast<uint32_t*>(g_aol + o0) = lo;
        hi = pack_split_hi(o[nt][2] * i1, o[nt][3] * i1, lo);
        *reinterpret_cast<uint32_t*>(g_aoh + o1) = hi;
        *reinterpret_cast<uint32_t*>(g_aol + o1) = lo;
    }
}

// -------------------------------- launch -----------------------------------
extern "C" void kernel_launch(void* const* d_in, const int* in_sizes, int n_in,
                              void* d_out, int out_size) {
    const float* x          = (const float*)d_in[0];
    const float* norm_g     = (const float*)d_in[1];
    const float* Wq         = (const float*)d_in[2];
    const float* Wkv        = (const float*)d_in[3];
    const float* Wout       = (const float*)d_in[4];
    const float* out_norm_g = (const float*)d_in[5];
    float* out = (float*)d_out;

    cudaFuncSetAttribute(gemm_mma_kernel<1>, cudaFuncAttributeMaxDynamicSharedMemorySize, 92160);
    cudaFuncSetAttribute(gemm_mma_kernel<0>, cudaFuncAttributeMaxDynamicSharedMemorySize, 81920);
    cudaFuncSetAttribute(attn_kernel,        cudaFuncAttributeMaxDynamicSharedMemorySize, 82944);
    cudaGetLastError();

    ln1_kernel<<<ROWS, 256>>>(x, norm_g);
    tsplit_kernel<0><<<dim3(DIM/32, INNER/32, 1), dim3(32, 8)>>>(Wq);
    tsplit_kernel<1><<<dim3(DIM/32, (2*DH)/32, 1), dim3(32, 8)>>>(Wkv);
    tsplit_kernel<2><<<dim3(INNER/32, DIM/32, 1), dim3(32, 8)>>>(Wout);
    gemm_mma_kernel<1><<<dim3(ROWS/128, 5), 256, 92160>>>();      // q + kv fused
    tsplit_kernel<3><<<dim3(NSEQ/32, DH/32, BATCH), dim3(32, 8)>>>(nullptr);
    attn_kernel<<<dim3(NSEQ/128, BATCH*NH), 256, 82944>>>();
    gemm_mma_kernel<0><<<dim3(ROWS/128, DIM/128), 256, 81920>>>();  // out-proj
    ln2_kernel<<<ROWS, 256>>>(out_norm_g, out);
}

// round 10
// speedup vs baseline: 4.3744x; 1.0293x over previous
#include <cuda_runtime.h>
#include <cuda_fp16.h>
#include <cstdint>
#include <math.h>

#define BATCH 4
#define NSEQ  2048
#define DIM   1024
#define NH    8
#define DH    64
#define INNER 512
#define ROWS  (BATCH*NSEQ)

// ----------------------------- scratch ------------------------------------
__device__ __half g_xn_h[ROWS*DIM];                       // LN(x), single fp16
__device__ __half g_wq_h[INNER*DIM],  g_wq_l[INNER*DIM];  // Wq^T  [512][1024]
__device__ __half g_wkv_h[2*DH*DIM],  g_wkv_l[2*DH*DIM];  // Wkv^T [128][1024]
__device__ __half g_wo_h[DIM*INNER],  g_wo_l[DIM*INNER];  // Wout^T[1024][512]
__device__ float  g_vf[ROWS*DH];
__device__ __half g_qh[ROWS*INNER];                       // q single fp16, head-major
__device__ __half g_kh[ROWS*DH], g_kl[ROWS*DH];           // k 2-term
__device__ __half g_vth[BATCH*DH*NSEQ];                   // V^T [b][dh][n] single fp16
__device__ __half g_aoh[ROWS*INNER];                      // attn out single fp16
__device__ float  g_proj[ROWS*DIM];

// --------------------------- helpers --------------------------------------
__device__ __forceinline__ uint32_t smem_u32(const void* p) {
    uint32_t a;
    asm("{ .reg .u64 t; cvta.to.shared.u64 t, %1; cvt.u32.u64 %0, t; }" : "=r"(a) : "l"(p));
    return a;
}
__device__ __forceinline__ void ldm_x4(uint32_t* r, uint32_t addr) {
    asm volatile("ldmatrix.sync.aligned.m8n8.x4.shared.b16 {%0,%1,%2,%3}, [%4];"
                 : "=r"(r[0]), "=r"(r[1]), "=r"(r[2]), "=r"(r[3]) : "r"(addr));
}
__device__ __forceinline__ void mma16816(float* c, const uint32_t* a, const uint32_t* b) {
    asm volatile("mma.sync.aligned.m16n8k16.row.col.f32.f16.f16.f32 "
                 "{%0,%1,%2,%3}, {%4,%5,%6,%7}, {%8,%9}, {%0,%1,%2,%3};"
                 : "+f"(c[0]), "+f"(c[1]), "+f"(c[2]), "+f"(c[3])
                 : "r"(a[0]), "r"(a[1]), "r"(a[2]), "r"(a[3]), "r"(b[0]), "r"(b[1]));
}
__device__ __forceinline__ void cp16(uint32_t d, const void* s) {
    asm volatile("cp.async.cg.shared.global [%0], [%1], 16;"
                 :: "r"(d), "l"(__cvta_generic_to_global(s)) : "memory");
}
#define CP_COMMIT() asm volatile("cp.async.commit_group;" ::: "memory")
__device__ __forceinline__ float ex2f(float x) {
    float y;
    asm("ex2.approx.ftz.f32 %0, %1;" : "=f"(y) : "f"(x));
    return y;
}
__device__ __forceinline__ uint32_t pack2h(float a, float b) {
    __half2 h = __floats2half2_rn(a, b);
    return *reinterpret_cast<uint32_t*>(&h);
}
__device__ __forceinline__ uint32_t pack_split_hi(float a, float b, uint32_t& lo) {
    __half2 h = __floats2half2_rn(a, b);
    float2 f = __half22float2(h);
    lo = pack2h(a - f.x, b - f.y);
    return *reinterpret_cast<uint32_t*>(&h);
}

// ------------------------------ LayerNorm ---------------------------------
__device__ __forceinline__ float2 ln_block(float4 v, float* shs, float* shss) {
    int t = threadIdx.x, w = t >> 5, lane = t & 31;
    float s = v.x + v.y + v.z + v.w;
    float ss = v.x*v.x + v.y*v.y + v.z*v.z + v.w*v.w;
    #pragma unroll
    for (int o = 16; o > 0; o >>= 1) { s += __shfl_xor_sync(~0u, s, o); ss += __shfl_xor_sync(~0u, ss, o); }
    if (lane == 0) { shs[w] = s; shss[w] = ss; }
    __syncthreads();
    if (w == 0) {
        s = (lane < 8) ? shs[lane] : 0.f; ss = (lane < 8) ? shss[lane] : 0.f;
        #pragma unroll
        for (int o = 4; o > 0; o >>= 1) { s += __shfl_xor_sync(~0u, s, o); ss += __shfl_xor_sync(~0u, ss, o); }
        if (lane == 0) { shs[0] = s; shss[0] = ss; }
    }
    __syncthreads();
    float mean = shs[0] * (1.f / DIM);
    float inv = rsqrtf(shss[0] * (1.f / DIM) - mean * mean + 1e-5f);
    return make_float2(mean, inv);
}
__global__ void ln1_kernel(const float* __restrict__ x, const float* __restrict__ g) {
    __shared__ float shs[8], shss[8];
    int row = blockIdx.x, t = threadIdx.x;
    float4 v = reinterpret_cast<const float4*>(x + (size_t)row * DIM)[t];
    float2 mi = ln_block(v, shs, shss);
    float4 gv = reinterpret_cast<const float4*>(g)[t];
    uint2 hi;
    hi.x = pack2h((v.x - mi.x) * mi.y * gv.x, (v.y - mi.x) * mi.y * gv.y);
    hi.y = pack2h((v.z - mi.x) * mi.y * gv.z, (v.w - mi.x) * mi.y * gv.w);
    reinterpret_cast<uint2*>(g_xn_h + (size_t)row * DIM)[t] = hi;
}
__global__ void ln2_kernel(const float* __restrict__ g, float* __restrict__ out) {
    __shared__ float shs[8], shss[8];
    int row = blockIdx.x, t = threadIdx.x;
    float4 v = reinterpret_cast<const float4*>(g_proj + (size_t)row * DIM)[t];
    float2 mi = ln_block(v, shs, shss);
    float4 gv = reinterpret_cast<const float4*>(g)[t];
    float4 o4 = make_float4((v.x - mi.x) * mi.y * gv.x, (v.y - mi.x) * mi.y * gv.y,
                            (v.z - mi.x) * mi.y * gv.z, (v.w - mi.x) * mi.y * gv.w);
    reinterpret_cast<float4*>(out + (size_t)row * DIM)[t] = o4;
}

// ------------------ transpose + split: src[R][C] -> dst[C][R] --------------
template<int MODE>
__global__ void tsplit_kernel(const float* __restrict__ srcp) {
    constexpr int R = (MODE == 0 || MODE == 1) ? DIM : (MODE == 2 ? INNER : NSEQ);
    constexpr int C = (MODE == 0) ? INNER : (MODE == 1 ? 2*DH : (MODE == 2 ? DIM : DH));
    __shared__ float t[32][33];
    const float* src; __half *dh, *dl = nullptr;
    if (MODE == 0) { src = srcp; dh = g_wq_h;  dl = g_wq_l;  }
    else if (MODE == 1) { src = srcp; dh = g_wkv_h; dl = g_wkv_l; }
    else if (MODE == 2) { src = srcp; dh = g_wo_h;  dl = g_wo_l;  }
    else { size_t z = (size_t)blockIdx.z * NSEQ * DH; src = g_vf + z; dh = g_vth + z; }
    int r0 = blockIdx.x * 32, c0 = blockIdx.y * 32;
    int tx = threadIdx.x, ty = threadIdx.y;
    #pragma unroll
    for (int i = 0; i < 4; i++)
        t[ty + i*8][tx] = src[(size_t)(r0 + ty + i*8) * C + c0 + tx];
    __syncthreads();
    #pragma unroll
    for (int i = 0; i < 4; i++) {
        float v = t[tx][ty + i*8];
        size_t o = (size_t)(c0 + ty + i*8) * R + r0 + tx;
        __half h = __float2half_rn(v);
        dh[o] = h;
        if (MODE != 3) dl[o] = __float2half_rn(v - __half2float(h));
    }
}

// --------------------- mma.sync projection GEMM (MT=64) --------------------
// A single fp16, B 2-term -> 2 mmas. 3-stage cp.async, 2 CTAs/SM.
// MODE 0 (qkv): A=xn, KD=1024, grid (128,5): by<4 q (fused l2norm), by==4 kv.
// MODE 1 (out): A=aoh, B=Wout, KD=512, grid (128,8) -> g_proj fp32.
// Warps: wm = wid&3 (4 x 16 rows), wn = wid>>2 (2 x 64 cols).
template<int MODE>
__global__ void __launch_bounds__(256, 2) gemm_mma_kernel() {
    constexpr int KD  = MODE ? INNER : DIM;
    constexpr int LDT = 40;                 // fp16 elems per row (32+8 pad)
    constexpr int ASZ = 64  * LDT * 2;      // 5120 B  (A tile)
    constexpr int BSZ = 128 * LDT * 2;      // 10240 B (per B array)
    constexpr int STG = ASZ + 2 * BSZ;      // 25600 B per stage
    extern __shared__ __align__(16) char dsm[];

    int tid = threadIdx.x, lane = tid & 31, wid = tid >> 5;
    int by = blockIdx.y;
    int m0 = blockIdx.x * 64, n0;
    const __half *Ah, *Bh, *Bl;
    if (MODE == 0) {
        Ah = g_xn_h;
        if (by < 4) { Bh = g_wq_h;  Bl = g_wq_l;  n0 = by * 128; }
        else        { Bh = g_wkv_h; Bl = g_wkv_l; n0 = 0; }
    } else {
        Ah = g_aoh; Bh = g_wo_h; Bl = g_wo_l; n0 = by * 128;
    }
    int wm = wid & 3, wn = wid >> 2;
    uint32_t sb = smem_u32(dsm);

    float c[8][4];
    #pragma unroll
    for (int j = 0; j < 8; j++) for (int q = 0; q < 4; q++) c[j][q] = 0.f;

    int lr = tid >> 2, lc = tid & 3;
    auto pf = [&](int kc, int st) {
        size_t ko = (size_t)kc * 32 + lc * 8;
        uint32_t base = sb + st * STG;
        uint32_t dr = (lr * LDT + lc * 8) * 2;
        cp16(base + dr, Ah + (size_t)(m0 + lr) * KD + ko);
        uint32_t d1 = ((lr + 64) * LDT + lc * 8) * 2;
        cp16(base + ASZ + dr,       Bh + (size_t)(n0 + lr) * KD + ko);
        cp16(base + ASZ + d1,       Bh + (size_t)(n0 + lr + 64) * KD + ko);
        cp16(base + ASZ + BSZ + dr, Bl + (size_t)(n0 + lr) * KD + ko);
        cp16(base + ASZ + BSZ + d1, Bl + (size_t)(n0 + lr + 64) * KD + ko);
        CP_COMMIT();
    };

    const int NC = KD / 32;
    pf(0, 0); pf(1, 1);
    for (int kc = 0; kc < NC; kc++) {
        int st = kc % 3;
        if (kc < NC - 1) asm volatile("cp.async.wait_group 1;" ::: "memory");
        else             asm volatile("cp.async.wait_group 0;" ::: "memory");
        __syncthreads();
        if (kc + 2 < NC) pf(kc + 2, (kc + 2) % 3);
        uint32_t bA = sb + st * STG, bB = bA + ASZ, bBl = bB + BSZ;
        #pragma unroll
        for (int ks = 0; ks < 2; ks++) {
            uint32_t a[4];
            uint32_t ar = wm * 16 + (lane & 15);
            uint32_t ac = ks * 16 + (lane >> 4) * 8;
            ldm_x4(a, bA + (ar * LDT + ac) * 2);
            #pragma unroll
            for (int j = 0; j < 4; j++) {
                uint32_t bh[4], bl[4];
                uint32_t br = wn * 64 + j * 16 + (lane & 7) + ((lane >> 4) & 1) * 8;
                uint32_t bc = ks * 16 + ((lane >> 3) & 1) * 8;
                ldm_x4(bh, bB  + (br * LDT + bc) * 2);
                ldm_x4(bl, bBl + (br * LDT + bc) * 2);
                #pragma unroll
                for (int t2 = 0; t2 < 2; t2++) {
                    mma16816(c[2*j + t2], a, &bh[2 * t2]);
                    mma16816(c[2*j + t2], a, &bl[2 * t2]);
                }
            }
        }
    }

    // ------------------------------ epilogue -------------------------------
    int r = m0 + wm * 16 + (lane >> 2);         // rows r and r+8
    if (MODE == 0 && (by < 4 || wn == 0)) {
        // q (by<4) or k (by==4, wn==0): fused l2norm * 4 over the warp's 64 cols
        float ss0 = 0.f, ss1 = 0.f;
        #pragma unroll
        for (int nt = 0; nt < 8; nt++) {
            ss0 += c[nt][0]*c[nt][0] + c[nt][1]*c[nt][1];
            ss1 += c[nt][2]*c[nt][2] + c[nt][3]*c[nt][3];
        }
        ss0 += __shfl_xor_sync(~0u, ss0, 1); ss0 += __shfl_xor_sync(~0u, ss0, 2);
        ss1 += __shfl_xor_sync(~0u, ss1, 1); ss1 += __shfl_xor_sync(~0u, ss1, 2);
        float i0 = 4.f / fmaxf(sqrtf(ss0), 1e-12f);
        float i1 = 4.f / fmaxf(sqrtf(ss1), 1e-12f);
        if (by < 4) {
            int b = r >> 11, nn = r & (NSEQ - 1), hd = by * 2 + wn;
            size_t off0 = ((size_t)(b * NH + hd) * NSEQ + nn) * DH;
            #pragma unroll
            for (int nt = 0; nt < 8; nt++) {
                int di = nt * 8 + (lane & 3) * 2;
                *reinterpret_cast<uint32_t*>(g_qh + off0 + di) =
                    pack2h(c[nt][0] * i0, c[nt][1] * i0);
                *reinterpret_cast<uint32_t*>(g_qh + off0 + (size_t)8 * DH + di) =
                    pack2h(c[nt][2] * i1, c[nt][3] * i1);
            }
        } else {
            size_t off0 = (size_t)r * DH;
            #pragma unroll
            for (int nt = 0; nt < 8; nt++) {
                int di = nt * 8 + (lane & 3) * 2;
                uint32_t lo, hi;
                hi = pack_split_hi(c[nt][0] * i0, c[nt][1] * i0, lo);
                *reinterpret_cast<uint32_t*>(g_kh + off0 + di) = hi;
                *reinterpret_cast<uint32_t*>(g_kl + off0 + di) = lo;
                hi = pack_split_hi(c[nt][2] * i1, c[nt][3] * i1, lo);
                *reinterpret_cast<uint32_t*>(g_kh + off0 + (size_t)8 * DH + di) = hi;
                *reinterpret_cast<uint32_t*>(g_kl + off0 + (size_t)8 * DH + di) = lo;
            }
        }
    } else if (MODE == 0) {                     // by==4, wn==1: v fp32
        #pragma unroll
        for (int nt = 0; nt < 8; nt++) {
            int di = nt * 8 + (lane & 3) * 2;
            float* d0 = g_vf + (size_t)r * DH + di;
            *reinterpret_cast<float2*>(d0) = make_float2(c[nt][0], c[nt][1]);
            *reinterpret_cast<float2*>(d0 + (size_t)8 * DH) = make_float2(c[nt][2], c[nt][3]);
        }
    } else {                                    // MODE 1: out-proj fp32
        #pragma unroll
        for (int nt = 0; nt < 8; nt++) {
            int col = n0 + wn * 64 + nt * 8 + (lane & 3) * 2;
            float* d0 = g_proj + (size_t)r * DIM + col;
            *reinterpret_cast<float2*>(d0) = make_float2(c[nt][0], c[nt][1]);
            *reinterpret_cast<float2*>(d0 + (size_t)8 * DIM) = make_float2(c[nt][2], c[nt][3]);
        }
    }
}

// ------------------------------ attention ----------------------------------
// block: (b,h,q-tile 128). 8 warps x 16 q-rows; 3-stage cp.async; 2 CTAs/SM.
// S = Qh*(Kh+Kl): 2 mmas. PV = P*Vh: 1 mma. Output single fp16.
__global__ void __launch_bounds__(256, 2) attn_kernel() {
    constexpr int LKV = 72;              // 64 + 8 pad
    constexpr int AS  = 64 * LKV * 2;    // 9216 B
    constexpr int STG = 3 * AS;          // 27648 B (kh,kl,vh)
    extern __shared__ __align__(16) char dsm[];
    int tid = threadIdx.x, lane = tid & 31, wid = tid >> 5;
    int b = blockIdx.y >> 3, h = blockIdx.y & 7;
    int q0 = blockIdx.x * 128;
    uint32_t sb = smem_u32(dsm);

    const __half* qhp = g_qh + ((size_t)(b * NH + h) * NSEQ + q0) * DH;
    const __half* khp = g_kh + (size_t)b * NSEQ * DH;
    const __half* klp = g_kl + (size_t)b * NSEQ * DH;
    const __half* vhp = g_vth + (size_t)b * DH * NSEQ;

    int lr = tid >> 2, lc = tid & 3;

    auto pf = [&](int kt, int st) {
        uint32_t base = sb + st * STG;
        uint32_t d = (lr * LKV + lc * 16) * 2;
        const __half* k0 = khp + (size_t)(kt * 64 + lr) * DH + lc * 16;
        const __half* k1 = klp + (size_t)(kt * 64 + lr) * DH + lc * 16;
        const __half* v0 = vhp + (size_t)lr * NSEQ + kt * 64 + lc * 16;
        cp16(base + d,            k0);  cp16(base + d + 16,        k0 + 8);
        cp16(base + AS + d,       k1);  cp16(base + AS + d + 16,   k1 + 8);
        cp16(base + 2*AS + d,     v0);  cp16(base + 2*AS + d + 16, v0 + 8);
        CP_COMMIT();
    };

    pf(0, 0); pf(1, 1);

    // stage Q through stage-2 smem area; fragments in regs
    uint32_t qfh[4][4];
    {
        __half* skh = reinterpret_cast<__half*>(dsm + 2 * STG);
        uint32_t bq = sb + 2 * STG;
        #pragma unroll
        for (int stage = 0; stage < 2; stage++) {
            const uint4* sh = reinterpret_cast<const uint4*>(qhp + (size_t)(stage * 64 + lr) * DH);
            *reinterpret_cast<uint4*>(skh + lr * LKV + lc * 16)     = sh[lc * 2];
            *reinterpret_cast<uint4*>(skh + lr * LKV + lc * 16 + 8) = sh[lc * 2 + 1];
            __syncthreads();
            if ((wid >> 2) == stage) {
                int rb = (wid & 3) * 16 + (lane & 15);
                #pragma unroll
                for (int g = 0; g < 4; g++) {
                    uint32_t ac = g * 16 + (lane >> 4) * 8;
                    ldm_x4(qfh[g], bq + (rb * LKV + ac) * 2);
                }
            }
            __syncthreads();
        }
    }

    float o[8][4];
    #pragma unroll
    for (int i = 0; i < 8; i++) for (int j = 0; j < 4; j++) o[i][j] = 0.f;
    float rs0 = 0.f, rs1 = 0.f;
    const float L2E = 1.44269504f, SH = -7.93482272f;   // -5.5*log2(e)

    const int NT = NSEQ / 64;
    for (int kt = 0; kt < NT; kt++) {
        int st = kt % 3;
        if (kt < NT - 1) asm volatile("cp.async.wait_group 1;" ::: "memory");
        else             asm volatile("cp.async.wait_group 0;" ::: "memory");
        __syncthreads();
        if (kt + 2 < NT) pf(kt + 2, (kt + 2) % 3);
        uint32_t bkh = sb + st * STG, bkl = bkh + AS, bvh = bkh + 2*AS;

        // S = Q K^T  (Q single term, K 2-term)
        float s[8][4];
        #pragma unroll
        for (int i = 0; i < 8; i++) for (int j = 0; j < 4; j++) s[i][j] = 0.f;
        #pragma unroll
        for (int j = 0; j < 4; j++) {
            uint32_t br = j * 16 + (lane & 7) + ((lane >> 4) & 1) * 8;
            #pragma unroll
            for (int g = 0; g < 4; g++) {
                uint32_t bh[4], bl[4];
                uint32_t bc = g * 16 + ((lane >> 3) & 1) * 8;
                ldm_x4(bh, bkh + (br * LKV + bc) * 2);
                ldm_x4(bl, bkl + (br * LKV + bc) * 2);
                #pragma unroll
                for (int t2 = 0; t2 < 2; t2++) {
                    mma16816(s[2*j + t2], qfh[g], &bh[2 * t2]);
                    mma16816(s[2*j + t2], qfh[g], &bl[2 * t2]);
                }
            }
        }

        // P = exp(s - 5.5), packed single fp16 into A-fragments
        uint32_t pa[4][4];
        #pragma unroll
        for (int g = 0; g < 4; g++) {
            float e00 = ex2f(fmaf(s[2*g][0],   L2E, SH)), e01 = ex2f(fmaf(s[2*g][1],   L2E, SH));
            float e02 = ex2f(fmaf(s[2*g][2],   L2E, SH)), e03 = ex2f(fmaf(s[2*g][3],   L2E, SH));
            float e10 = ex2f(fmaf(s[2*g+1][0], L2E, SH)), e11 = ex2f(fmaf(s[2*g+1][1], L2E, SH));
            float e12 = ex2f(fmaf(s[2*g+1][2], L2E, SH)), e13 = ex2f(fmaf(s[2*g+1][3], L2E, SH));
            rs0 += e00 + e01 + e10 + e11;
            rs1 += e02 + e03 + e12 + e13;
            pa[g][0] = pack2h(e00, e01);
            pa[g][1] = pack2h(e02, e03);
            pa[g][2] = pack2h(e10, e11);
            pa[g][3] = pack2h(e12, e13);
        }

        // O += P V  (both single term)
        #pragma unroll
        for (int j = 0; j < 4; j++) {
            uint32_t br = j * 16 + (lane & 7) + ((lane >> 4) & 1) * 8;
            #pragma unroll
            for (int g = 0; g < 4; g++) {
                uint32_t bh[4];
                uint32_t bc = g * 16 + ((lane >> 3) & 1) * 8;
                ldm_x4(bh, bvh + (br * LKV + bc) * 2);
                #pragma unroll
                for (int t2 = 0; t2 < 2; t2++)
                    mma16816(o[2*j + t2], pa[g], &bh[2 * t2]);
            }
        }
    }

    rs0 += __shfl_xor_sync(~0u, rs0, 1); rs0 += __shfl_xor_sync(~0u, rs0, 2);
    rs1 += __shfl_xor_sync(~0u, rs1, 1); rs1 += __shfl_xor_sync(~0u, rs1, 2);
    float i0 = 1.f / rs0, i1 = 1.f / rs1;

    int row0 = q0 + wid * 16 + (lane >> 2);
    #pragma unroll
    for (int nt = 0; nt < 8; nt++) {
        int col = h * DH + nt * 8 + (lane & 3) * 2;
        size_t o0 = (size_t)(b * NSEQ + row0) * INNER + col;
        size_t o1 = (size_t)(b * NSEQ + row0 + 8) * INNER + col;
        *reinterpret_cast<uint32_t*>(g_aoh + o0) = pack2h(o[nt][0] * i0, o[nt][1] * i0);
        *reinterpret_cast<uint32_t*>(g_aoh + o1) = pack2h(o[nt][2] * i1, o[nt][3] * i1);
    }
}

// -------------------------------- launch -----------------------------------
extern "C" void kernel_launch(void* const* d_in, const int* in_sizes, int n_in,
                              void* d_out, int out_size) {
    const float* x          = (const float*)d_in[0];
    const float* norm_g     = (const float*)d_in[1];
    const float* Wq         = (const float*)d_in[2];
    const float* Wkv        = (const float*)d_in[3];
    const float* Wout       = (const float*)d_in[4];
    const float* out_norm_g = (const float*)d_in[5];
    float* out = (float*)d_out;

    cudaFuncSetAttribute(gemm_mma_kernel<0>, cudaFuncAttributeMaxDynamicSharedMemorySize, 76800);
    cudaFuncSetAttribute(gemm_mma_kernel<1>, cudaFuncAttributeMaxDynamicSharedMemorySize, 76800);
    cudaFuncSetAttribute(attn_kernel,        cudaFuncAttributeMaxDynamicSharedMemorySize, 82944);
    cudaGetLastError();

    ln1_kernel<<<ROWS, 256>>>(x, norm_g);
    tsplit_kernel<0><<<dim3(DIM/32, INNER/32, 1), dim3(32, 8)>>>(Wq);
    tsplit_kernel<1><<<dim3(DIM/32, (2*DH)/32, 1), dim3(32, 8)>>>(Wkv);
    tsplit_kernel<2><<<dim3(INNER/32, DIM/32, 1), dim3(32, 8)>>>(Wout);
    gemm_mma_kernel<0><<<dim3(ROWS/64, 5), 256, 76800>>>();       // q + kv fused
    tsplit_kernel<3><<<dim3(NSEQ/32, DH/32, BATCH), dim3(32, 8)>>>(nullptr);
    attn_kernel<<<dim3(NSEQ/128, BATCH*NH), 256, 82944>>>();
    gemm_mma_kernel<1><<<dim3(ROWS/64, DIM/128), 256, 76800>>>(); // out-proj
    ln2_kernel<<<ROWS, 256>>>(out_norm_g, out);
}

// round 11
// speedup vs baseline: 5.5719x; 1.2738x over previous
#include <cuda_runtime.h>
#include <cuda_fp16.h>
#include <cstdint>
#include <math.h>

#define BATCH 4
#define NSEQ  2048
#define DIM   1024
#define NH    8
#define DH    64
#define INNER 512
#define ROWS  (BATCH*NSEQ)

// ----------------------------- scratch ------------------------------------
__device__ __half g_xn_h[ROWS*DIM];                       // LN(x), single fp16
__device__ __half g_wq_h[INNER*DIM],  g_wq_l[INNER*DIM];  // Wq^T  [512][1024] 2-term
__device__ __half g_wkv_h[2*DH*DIM],  g_wkv_l[2*DH*DIM];  // Wkv^T [128][1024] 2-term
__device__ __half g_wo_h[DIM*INNER];                      // Wout^T[1024][512] single
__device__ float  g_vf[ROWS*DH];
__device__ __half g_qh[ROWS*INNER];                       // q single fp16, head-major
__device__ __half g_kh[ROWS*DH];                          // k single fp16
__device__ __half g_vth[BATCH*DH*NSEQ];                   // V^T [b][dh][n] single fp16
__device__ __half g_aoh[ROWS*INNER];                      // attn out single fp16
__device__ float  g_proj[ROWS*DIM];

// --------------------------- helpers --------------------------------------
__device__ __forceinline__ uint32_t smem_u32(const void* p) {
    uint32_t a;
    asm("{ .reg .u64 t; cvta.to.shared.u64 t, %1; cvt.u32.u64 %0, t; }" : "=r"(a) : "l"(p));
    return a;
}
__device__ __forceinline__ void ldm_x4(uint32_t* r, uint32_t addr) {
    asm volatile("ldmatrix.sync.aligned.m8n8.x4.shared.b16 {%0,%1,%2,%3}, [%4];"
                 : "=r"(r[0]), "=r"(r[1]), "=r"(r[2]), "=r"(r[3]) : "r"(addr));
}
__device__ __forceinline__ void mma16816(float* c, const uint32_t* a, const uint32_t* b) {
    asm volatile("mma.sync.aligned.m16n8k16.row.col.f32.f16.f16.f32 "
                 "{%0,%1,%2,%3}, {%4,%5,%6,%7}, {%8,%9}, {%0,%1,%2,%3};"
                 : "+f"(c[0]), "+f"(c[1]), "+f"(c[2]), "+f"(c[3])
                 : "r"(a[0]), "r"(a[1]), "r"(a[2]), "r"(a[3]), "r"(b[0]), "r"(b[1]));
}
__device__ __forceinline__ void cp16(uint32_t d, const void* s) {
    asm volatile("cp.async.cg.shared.global [%0], [%1], 16;"
                 :: "r"(d), "l"(__cvta_generic_to_global(s)) : "memory");
}
#define CP_COMMIT() asm volatile("cp.async.commit_group;" ::: "memory")
__device__ __forceinline__ float ex2f(float x) {
    float y;
    asm("ex2.approx.ftz.f32 %0, %1;" : "=f"(y) : "f"(x));
    return y;
}
__device__ __forceinline__ uint32_t pack2h(float a, float b) {
    __half2 h = __floats2half2_rn(a, b);
    return *reinterpret_cast<uint32_t*>(&h);
}

// ------------------------------ LayerNorm ---------------------------------
__device__ __forceinline__ float2 ln_block(float4 v, float* shs, float* shss) {
    int t = threadIdx.x, w = t >> 5, lane = t & 31;
    float s = v.x + v.y + v.z + v.w;
    float ss = v.x*v.x + v.y*v.y + v.z*v.z + v.w*v.w;
    #pragma unroll
    for (int o = 16; o > 0; o >>= 1) { s += __shfl_xor_sync(~0u, s, o); ss += __shfl_xor_sync(~0u, ss, o); }
    if (lane == 0) { shs[w] = s; shss[w] = ss; }
    __syncthreads();
    if (w == 0) {
        s = (lane < 8) ? shs[lane] : 0.f; ss = (lane < 8) ? shss[lane] : 0.f;
        #pragma unroll
        for (int o = 4; o > 0; o >>= 1) { s += __shfl_xor_sync(~0u, s, o); ss += __shfl_xor_sync(~0u, ss, o); }
        if (lane == 0) { shs[0] = s; shss[0] = ss; }
    }
    __syncthreads();
    float mean = shs[0] * (1.f / DIM);
    float inv = rsqrtf(shss[0] * (1.f / DIM) - mean * mean + 1e-5f);
    return make_float2(mean, inv);
}
__global__ void ln1_kernel(const float* __restrict__ x, const float* __restrict__ g) {
    __shared__ float shs[8], shss[8];
    int row = blockIdx.x, t = threadIdx.x;
    float4 v = reinterpret_cast<const float4*>(x + (size_t)row * DIM)[t];
    float2 mi = ln_block(v, shs, shss);
    float4 gv = reinterpret_cast<const float4*>(g)[t];
    uint2 hi;
    hi.x = pack2h((v.x - mi.x) * mi.y * gv.x, (v.y - mi.x) * mi.y * gv.y);
    hi.y = pack2h((v.z - mi.x) * mi.y * gv.z, (v.w - mi.x) * mi.y * gv.w);
    reinterpret_cast<uint2*>(g_xn_h + (size_t)row * DIM)[t] = hi;
}
__global__ void ln2_kernel(const float* __restrict__ g, float* __restrict__ out) {
    __shared__ float shs[8], shss[8];
    int row = blockIdx.x, t = threadIdx.x;
    float4 v = reinterpret_cast<const float4*>(g_proj + (size_t)row * DIM)[t];
    float2 mi = ln_block(v, shs, shss);
    float4 gv = reinterpret_cast<const float4*>(g)[t];
    float4 o4 = make_float4((v.x - mi.x) * mi.y * gv.x, (v.y - mi.x) * mi.y * gv.y,
                            (v.z - mi.x) * mi.y * gv.z, (v.w - mi.x) * mi.y * gv.w);
    reinterpret_cast<float4*>(out + (size_t)row * DIM)[t] = o4;
}

// ------------------ transpose + split: src[R][C] -> dst[C][R] --------------
// MODE 0: Wq 2-term, 1: Wkv 2-term, 2: Wout single, 3: V^T single
template<int MODE>
__global__ void tsplit_kernel(const float* __restrict__ srcp) {
    constexpr int R = (MODE == 0 || MODE == 1) ? DIM : (MODE == 2 ? INNER : NSEQ);
    constexpr int C = (MODE == 0) ? INNER : (MODE == 1 ? 2*DH : (MODE == 2 ? DIM : DH));
    __shared__ float t[32][33];
    const float* src; __half *dh, *dl = nullptr;
    if (MODE == 0) { src = srcp; dh = g_wq_h;  dl = g_wq_l;  }
    else if (MODE == 1) { src = srcp; dh = g_wkv_h; dl = g_wkv_l; }
    else if (MODE == 2) { src = srcp; dh = g_wo_h; }
    else { size_t z = (size_t)blockIdx.z * NSEQ * DH; src = g_vf + z; dh = g_vth + z; }
    int r0 = blockIdx.x * 32, c0 = blockIdx.y * 32;
    int tx = threadIdx.x, ty = threadIdx.y;
    #pragma unroll
    for (int i = 0; i < 4; i++)
        t[ty + i*8][tx] = src[(size_t)(r0 + ty + i*8) * C + c0 + tx];
    __syncthreads();
    #pragma unroll
    for (int i = 0; i < 4; i++) {
        float v = t[tx][ty + i*8];
        size_t o = (size_t)(c0 + ty + i*8) * R + r0 + tx;
        __half h = __float2half_rn(v);
        dh[o] = h;
        if (MODE == 0 || MODE == 1) dl[o] = __float2half_rn(v - __half2float(h));
    }
}

// --------------------- mma.sync projection GEMM (MT=64) --------------------
// MODE 0 (qkv): A=xn single, B 2-term -> 2 mmas; grid (128,5): by<4 q, by==4 kv.
// MODE 1 (out): A=aoh single, B=Wout single -> 1 mma; grid (128,8) -> g_proj.
// 3-stage cp.async, 2 CTAs/SM. Warps: wm = wid&3 (16 rows), wn = wid>>2 (64 cols).
template<int MODE>
__global__ void __launch_bounds__(256, 2) gemm_mma_kernel() {
    constexpr int KD  = MODE ? INNER : DIM;
    constexpr int LDT = 40;                 // fp16 elems per row (32+8 pad)
    constexpr int ASZ = 64  * LDT * 2;      // 5120 B  (A tile)
    constexpr int BSZ = 128 * LDT * 2;      // 10240 B (per B array)
    constexpr int NB  = MODE ? 1 : 2;       // B term count
    constexpr int STG = ASZ + NB * BSZ;
    extern __shared__ __align__(16) char dsm[];

    int tid = threadIdx.x, lane = tid & 31, wid = tid >> 5;
    int by = blockIdx.y;
    int m0 = blockIdx.x * 64, n0;
    const __half *Ah, *Bh, *Bl = nullptr;
    if (MODE == 0) {
        Ah = g_xn_h;
        if (by < 4) { Bh = g_wq_h;  Bl = g_wq_l;  n0 = by * 128; }
        else        { Bh = g_wkv_h; Bl = g_wkv_l; n0 = 0; }
    } else {
        Ah = g_aoh; Bh = g_wo_h; n0 = by * 128;
    }
    int wm = wid & 3, wn = wid >> 2;
    uint32_t sb = smem_u32(dsm);

    float c[8][4];
    #pragma unroll
    for (int j = 0; j < 8; j++) for (int q = 0; q < 4; q++) c[j][q] = 0.f;

    int lr = tid >> 2, lc = tid & 3;
    auto pf = [&](int kc, int st) {
        size_t ko = (size_t)kc * 32 + lc * 8;
        uint32_t base = sb + st * STG;
        uint32_t dr = (lr * LDT + lc * 8) * 2;
        uint32_t d1 = ((lr + 64) * LDT + lc * 8) * 2;
        cp16(base + dr, Ah + (size_t)(m0 + lr) * KD + ko);
        cp16(base + ASZ + dr, Bh + (size_t)(n0 + lr) * KD + ko);
        cp16(base + ASZ + d1, Bh + (size_t)(n0 + lr + 64) * KD + ko);
        if (NB == 2) {
            cp16(base + ASZ + BSZ + dr, Bl + (size_t)(n0 + lr) * KD + ko);
            cp16(base + ASZ + BSZ + d1, Bl + (size_t)(n0 + lr + 64) * KD + ko);
        }
        CP_COMMIT();
    };

    const int NC = KD / 32;
    pf(0, 0); pf(1, 1);
    for (int kc = 0; kc < NC; kc++) {
        int st = kc % 3;
        if (kc < NC - 1) asm volatile("cp.async.wait_group 1;" ::: "memory");
        else             asm volatile("cp.async.wait_group 0;" ::: "memory");
        __syncthreads();
        if (kc + 2 < NC) pf(kc + 2, (kc + 2) % 3);
        uint32_t bA = sb + st * STG, bB = bA + ASZ, bBl = bB + BSZ;
        #pragma unroll
        for (int ks = 0; ks < 2; ks++) {
            uint32_t a[4];
            uint32_t ar = wm * 16 + (lane & 15);
            uint32_t ac = ks * 16 + (lane >> 4) * 8;
            ldm_x4(a, bA + (ar * LDT + ac) * 2);
            #pragma unroll
            for (int j = 0; j < 4; j++) {
                uint32_t bh[4], bl[4];
                uint32_t br = wn * 64 + j * 16 + (lane & 7) + ((lane >> 4) & 1) * 8;
                uint32_t bc = ks * 16 + ((lane >> 3) & 1) * 8;
                ldm_x4(bh, bB + (br * LDT + bc) * 2);
                if (NB == 2) ldm_x4(bl, bBl + (br * LDT + bc) * 2);
                #pragma unroll
                for (int t2 = 0; t2 < 2; t2++) {
                    mma16816(c[2*j + t2], a, &bh[2 * t2]);
                    if (NB == 2) mma16816(c[2*j + t2], a, &bl[2 * t2]);
                }
            }
        }
    }

    // ------------------------------ epilogue -------------------------------
    int r = m0 + wm * 16 + (lane >> 2);         // rows r and r+8
    if (MODE == 0 && (by < 4 || wn == 0)) {
        // q (by<4) or k (by==4, wn==0): fused l2norm * 4 over the warp's 64 cols
        float ss0 = 0.f, ss1 = 0.f;
        #pragma unroll
        for (int nt = 0; nt < 8; nt++) {
            ss0 += c[nt][0]*c[nt][0] + c[nt][1]*c[nt][1];
            ss1 += c[nt][2]*c[nt][2] + c[nt][3]*c[nt][3];
        }
        ss0 += __shfl_xor_sync(~0u, ss0, 1); ss0 += __shfl_xor_sync(~0u, ss0, 2);
        ss1 += __shfl_xor_sync(~0u, ss1, 1); ss1 += __shfl_xor_sync(~0u, ss1, 2);
        float i0 = 4.f / fmaxf(sqrtf(ss0), 1e-12f);
        float i1 = 4.f / fmaxf(sqrtf(ss1), 1e-12f);
        __half* dst; size_t off0;
        if (by < 4) {
            int b = r >> 11, nn = r & (NSEQ - 1), hd = by * 2 + wn;
            off0 = ((size_t)(b * NH + hd) * NSEQ + nn) * DH;
            dst = g_qh;
        } else {
            off0 = (size_t)r * DH;
            dst = g_kh;
        }
        #pragma unroll
        for (int nt = 0; nt < 8; nt++) {
            int di = nt * 8 + (lane & 3) * 2;
            *reinterpret_cast<uint32_t*>(dst + off0 + di) =
                pack2h(c[nt][0] * i0, c[nt][1] * i0);
            *reinterpret_cast<uint32_t*>(dst + off0 + (size_t)8 * DH + di) =
                pack2h(c[nt][2] * i1, c[nt][3] * i1);
        }
    } else if (MODE == 0) {                     // by==4, wn==1: v fp32
        #pragma unroll
        for (int nt = 0; nt < 8; nt++) {
            int di = nt * 8 + (lane & 3) * 2;
            float* d0 = g_vf + (size_t)r * DH + di;
            *reinterpret_cast<float2*>(d0) = make_float2(c[nt][0], c[nt][1]);
            *reinterpret_cast<float2*>(d0 + (size_t)8 * DH) = make_float2(c[nt][2], c[nt][3]);
        }
    } else {                                    // MODE 1: out-proj fp32
        #pragma unroll
        for (int nt = 0; nt < 8; nt++) {
            int col = n0 + wn * 64 + nt * 8 + (lane & 3) * 2;
            float* d0 = g_proj + (size_t)r * DIM + col;
            *reinterpret_cast<float2*>(d0) = make_float2(c[nt][0], c[nt][1]);
            *reinterpret_cast<float2*>(d0 + (size_t)8 * DIM) = make_float2(c[nt][2], c[nt][3]);
        }
    }
}

// ------------------------------ attention ----------------------------------
// block: (b,h,q-tile 128). 8 warps x 16 q-rows; 3-stage cp.async; 2 CTAs/SM.
// S = Qh*Kh: 1 mma. PV = P*Vh: 1 mma. All single fp16 operands.
__global__ void __launch_bounds__(256, 2) attn_kernel() {
    constexpr int LKV = 72;              // 64 + 8 pad
    constexpr int AS  = 64 * LKV * 2;    // 9216 B
    constexpr int STG = 2 * AS;          // 18432 B (kh, vh)
    extern __shared__ __align__(16) char dsm[];
    int tid = threadIdx.x, lane = tid & 31, wid = tid >> 5;
    int b = blockIdx.y >> 3, h = blockIdx.y & 7;
    int q0 = blockIdx.x * 128;
    uint32_t sb = smem_u32(dsm);

    const __half* qhp = g_qh + ((size_t)(b * NH + h) * NSEQ + q0) * DH;
    const __half* khp = g_kh + (size_t)b * NSEQ * DH;
    const __half* vhp = g_vth + (size_t)b * DH * NSEQ;

    int lr = tid >> 2, lc = tid & 3;

    auto pf = [&](int kt, int st) {
        uint32_t base = sb + st * STG;
        uint32_t d = (lr * LKV + lc * 16) * 2;
        const __half* k0 = khp + (size_t)(kt * 64 + lr) * DH + lc * 16;
        const __half* v0 = vhp + (size_t)lr * NSEQ + kt * 64 + lc * 16;
        cp16(base + d,        k0);  cp16(base + d + 16,        k0 + 8);
        cp16(base + AS + d,   v0);  cp16(base + AS + d + 16,   v0 + 8);
        CP_COMMIT();
    };

    pf(0, 0); pf(1, 1);

    // stage Q through stage-2 smem area (untouched until kt=0 prefetches kt+2)
    uint32_t qfh[4][4];
    {
        __half* skh = reinterpret_cast<__half*>(dsm + 2 * STG);
        uint32_t bq = sb + 2 * STG;
        #pragma unroll
        for (int stage = 0; stage < 2; stage++) {
            const uint4* sh = reinterpret_cast<const uint4*>(qhp + (size_t)(stage * 64 + lr) * DH);
            *reinterpret_cast<uint4*>(skh + lr * LKV + lc * 16)     = sh[lc * 2];
            *reinterpret_cast<uint4*>(skh + lr * LKV + lc * 16 + 8) = sh[lc * 2 + 1];
            __syncthreads();
            if ((wid >> 2) == stage) {
                int rb = (wid & 3) * 16 + (lane & 15);
                #pragma unroll
                for (int g = 0; g < 4; g++) {
                    uint32_t ac = g * 16 + (lane >> 4) * 8;
                    ldm_x4(qfh[g], bq + (rb * LKV + ac) * 2);
                }
            }
            __syncthreads();
        }
    }

    float o[8][4];
    #pragma unroll
    for (int i = 0; i < 8; i++) for (int j = 0; j < 4; j++) o[i][j] = 0.f;
    float rs0 = 0.f, rs1 = 0.f;
    const float L2E = 1.44269504f, SH = -7.93482272f;   // -5.5*log2(e)

    const int NT = NSEQ / 64;
    for (int kt = 0; kt < NT; kt++) {
        int st = kt % 3;
        if (kt < NT - 1) asm volatile("cp.async.wait_group 1;" ::: "memory");
        else             asm volatile("cp.async.wait_group 0;" ::: "memory");
        __syncthreads();
        if (kt + 2 < NT) pf(kt + 2, (kt + 2) % 3);
        uint32_t bkh = sb + st * STG, bvh = bkh + AS;

        // S = Q K^T  (both single term)
        float s[8][4];
        #pragma unroll
        for (int i = 0; i < 8; i++) for (int j = 0; j < 4; j++) s[i][j] = 0.f;
        #pragma unroll
        for (int j = 0; j < 4; j++) {
            uint32_t br = j * 16 + (lane & 7) + ((lane >> 4) & 1) * 8;
            #pragma unroll
            for (int g = 0; g < 4; g++) {
                uint32_t bh[4];
                uint32_t bc = g * 16 + ((lane >> 3) & 1) * 8;
                ldm_x4(bh, bkh + (br * LKV + bc) * 2);
                #pragma unroll
                for (int t2 = 0; t2 < 2; t2++)
                    mma16816(s[2*j + t2], qfh[g], &bh[2 * t2]);
            }
        }

        // P = exp(s - 5.5), packed single fp16 into A-fragments
        uint32_t pa[4][4];
        #pragma unroll
        for (int g = 0; g < 4; g++) {
            float e00 = ex2f(fmaf(s[2*g][0],   L2E, SH)), e01 = ex2f(fmaf(s[2*g][1],   L2E, SH));
            float e02 = ex2f(fmaf(s[2*g][2],   L2E, SH)), e03 = ex2f(fmaf(s[2*g][3],   L2E, SH));
            float e10 = ex2f(fmaf(s[2*g+1][0], L2E, SH)), e11 = ex2f(fmaf(s[2*g+1][1], L2E, SH));
            float e12 = ex2f(fmaf(s[2*g+1][2], L2E, SH)), e13 = ex2f(fmaf(s[2*g+1][3], L2E, SH));
            rs0 += e00 + e01 + e10 + e11;
            rs1 += e02 + e03 + e12 + e13;
            pa[g][0] = pack2h(e00, e01);
            pa[g][1] = pack2h(e02, e03);
            pa[g][2] = pack2h(e10, e11);
            pa[g][3] = pack2h(e12, e13);
        }

        // O += P V  (both single term)
        #pragma unroll
        for (int j = 0; j < 4; j++) {
            uint32_t br = j * 16 + (lane & 7) + ((lane >> 4) & 1) * 8;
            #pragma unroll
            for (int g = 0; g < 4; g++) {
                uint32_t bh[4];
                uint32_t bc = g * 16 + ((lane >> 3) & 1) * 8;
                ldm_x4(bh, bvh + (br * LKV + bc) * 2);
                #pragma unroll
                for (int t2 = 0; t2 < 2; t2++)
                    mma16816(o[2*j + t2], pa[g], &bh[2 * t2]);
            }
        }
    }

    rs0 += __shfl_xor_sync(~0u, rs0, 1); rs0 += __shfl_xor_sync(~0u, rs0, 2);
    rs1 += __shfl_xor_sync(~0u, rs1, 1); rs1 += __shfl_xor_sync(~0u, rs1, 2);
    float i0 = 1.f / rs0, i1 = 1.f / rs1;

    int row0 = q0 + wid * 16 + (lane >> 2);
    #pragma unroll
    for (int nt = 0; nt < 8; nt++) {
        int col = h * DH + nt * 8 + (lane & 3) * 2;
        size_t o0 = (size_t)(b * NSEQ + row0) * INNER + col;
        size_t o1 = (size_t)(b * NSEQ + row0 + 8) * INNER + col;
        *reinterpret_cast<uint32_t*>(g_aoh + o0) = pack2h(o[nt][0] * i0, o[nt][1] * i0);
        *reinterpret_cast<uint32_t*>(g_aoh + o1) = pack2h(o[nt][2] * i1, o[nt][3] * i1);
    }
}

// -------------------------------- launch -----------------------------------
extern "C" void kernel_launch(void* const* d_in, const int* in_sizes, int n_in,
                              void* d_out, int out_size) {
    const float* x          = (const float*)d_in[0];
    const float* norm_g     = (const float*)d_in[1];
    const float* Wq         = (const float*)d_in[2];
    const float* Wkv        = (const float*)d_in[3];
    const float* Wout       = (const float*)d_in[4];
    const float* out_norm_g = (const float*)d_in[5];
    float* out = (float*)d_out;

    cudaFuncSetAttribute(gemm_mma_kernel<0>, cudaFuncAttributeMaxDynamicSharedMemorySize, 76800);
    cudaFuncSetAttribute(gemm_mma_kernel<1>, cudaFuncAttributeMaxDynamicSharedMemorySize, 46080);
    cudaFuncSetAttribute(attn_kernel,        cudaFuncAttributeMaxDynamicSharedMemorySize, 55296);
    cudaGetLastError();

    ln1_kernel<<<ROWS, 256>>>(x, norm_g);
    tsplit_kernel<0><<<dim3(DIM/32, INNER/32, 1), dim3(32, 8)>>>(Wq);
    tsplit_kernel<1><<<dim3(DIM/32, (2*DH)/32, 1), dim3(32, 8)>>>(Wkv);
    tsplit_kernel<2><<<dim3(INNER/32, DIM/32, 1), dim3(32, 8)>>>(Wout);
    gemm_mma_kernel<0><<<dim3(ROWS/64, 5), 256, 76800>>>();       // q + kv fused
    tsplit_kernel<3><<<dim3(NSEQ/32, DH/32, BATCH), dim3(32, 8)>>>(nullptr);
    attn_kernel<<<dim3(NSEQ/128, BATCH*NH), 256, 55296>>>();
    gemm_mma_kernel<1><<<dim3(ROWS/64, DIM/128), 256, 46080>>>(); // out-proj
    ln2_kernel<<<ROWS, 256>>>(out_norm_g, out);
}